// round 3
// baseline (speedup 1.0000x reference)
#include <cuda_runtime.h>
#include <cfloat>
#include <cstdint>

// ---------------- scratch (__device__ globals; no allocations) ----------------
__device__ float g_qkv[1024 * 3072];              // 12 MB  (T, 3C)
__device__ float g_att[16 * 1024 * 1024];         // 64 MB  (H, T, T)
__device__ float g_ksnorm[16 * 8192];             // (H, M)
__device__ float g_psc[16 * 1024 * 16];           // partial top4 scores (row,4z,4)
__device__ int   g_pix[16 * 1024 * 16];           // partial top4 idx
__device__ int   g_idx[16 * 1024 * 4];            // (H, T, 4)
__device__ int   g_sel[16 * 1024];                // (H, T)
__device__ float g_vnew[16 * 1024 * 64];          // (H, T, d)
__device__ float g_y[1024 * 1024];                // (T, C)

// ---------- double-buffered 128x128x16 SGEMM: C = epilogue(A * B^T) ----------
// A: (M,K) rm stride lda, B: (N,K) rm stride ldb.
// MODE 0: + bias(aux[col]);  MODE 1: * 0.125, skip blocks above causal diag.
template <int MODE>
__global__ __launch_bounds__(256, 2) void gemm128db(
    const float* __restrict__ A, int lda, long long aZ,
    const float* __restrict__ B, int ldb, long long bZ,
    float* __restrict__ C, int ldc, long long cZ,
    int K, const float* __restrict__ aux, long long auxZ) {
    int bx = blockIdx.x, by = blockIdx.y, z = blockIdx.z;
    if (MODE == 1 && bx > by) return;
    A += (size_t)z * aZ + (size_t)by * 128 * lda;
    B += (size_t)z * bZ + (size_t)bx * 128 * ldb;
    C += (size_t)z * cZ;
    if (MODE == 0) aux += (size_t)z * auxZ;

    __shared__ float As[2][16][128];
    __shared__ float Bs[2][16][128];

    int tid = threadIdx.x;
    int tx = tid & 15, ty = tid >> 4;
    int lr = tid >> 1, lk = (tid & 1) * 8;
    const float* Ap = A + (size_t)lr * lda + lk;
    const float* Bp = B + (size_t)lr * ldb + lk;

    float4 ra0, ra1, rb0, rb1;
    ra0 = *(const float4*)(Ap);     ra1 = *(const float4*)(Ap + 4);
    rb0 = *(const float4*)(Bp);     rb1 = *(const float4*)(Bp + 4);

    float acc[8][8];
#pragma unroll
    for (int i = 0; i < 8; i++)
#pragma unroll
        for (int j = 0; j < 8; j++) acc[i][j] = 0.f;

    int nt = K >> 4;
    int buf = 0;
    As[0][lk + 0][lr] = ra0.x; As[0][lk + 1][lr] = ra0.y;
    As[0][lk + 2][lr] = ra0.z; As[0][lk + 3][lr] = ra0.w;
    As[0][lk + 4][lr] = ra1.x; As[0][lk + 5][lr] = ra1.y;
    As[0][lk + 6][lr] = ra1.z; As[0][lk + 7][lr] = ra1.w;
    Bs[0][lk + 0][lr] = rb0.x; Bs[0][lk + 1][lr] = rb0.y;
    Bs[0][lk + 2][lr] = rb0.z; Bs[0][lk + 3][lr] = rb0.w;
    Bs[0][lk + 4][lr] = rb1.x; Bs[0][lk + 5][lr] = rb1.y;
    Bs[0][lk + 6][lr] = rb1.z; Bs[0][lk + 7][lr] = rb1.w;
    __syncthreads();

    for (int t = 0; t < nt; t++) {
        if (t + 1 < nt) {
            const float* Apn = Ap + (t + 1) * 16;
            const float* Bpn = Bp + (t + 1) * 16;
            ra0 = *(const float4*)(Apn);     ra1 = *(const float4*)(Apn + 4);
            rb0 = *(const float4*)(Bpn);     rb1 = *(const float4*)(Bpn + 4);
        }
#pragma unroll
        for (int kk = 0; kk < 16; kk++) {
            float a[8], b[8];
#pragma unroll
            for (int i = 0; i < 8; i++) a[i] = As[buf][kk][ty * 8 + i];
#pragma unroll
            for (int j = 0; j < 8; j++) b[j] = Bs[buf][kk][tx * 8 + j];
#pragma unroll
            for (int i = 0; i < 8; i++)
#pragma unroll
                for (int j = 0; j < 8; j++) acc[i][j] = fmaf(a[i], b[j], acc[i][j]);
        }
        if (t + 1 < nt) {
            int nb = buf ^ 1;
            As[nb][lk + 0][lr] = ra0.x; As[nb][lk + 1][lr] = ra0.y;
            As[nb][lk + 2][lr] = ra0.z; As[nb][lk + 3][lr] = ra0.w;
            As[nb][lk + 4][lr] = ra1.x; As[nb][lk + 5][lr] = ra1.y;
            As[nb][lk + 6][lr] = ra1.z; As[nb][lk + 7][lr] = ra1.w;
            Bs[nb][lk + 0][lr] = rb0.x; Bs[nb][lk + 1][lr] = rb0.y;
            Bs[nb][lk + 2][lr] = rb0.z; Bs[nb][lk + 3][lr] = rb0.w;
            Bs[nb][lk + 4][lr] = rb1.x; Bs[nb][lk + 5][lr] = rb1.y;
            Bs[nb][lk + 6][lr] = rb1.z; Bs[nb][lk + 7][lr] = rb1.w;
            __syncthreads();
            buf = nb;
        }
    }

#pragma unroll
    for (int i = 0; i < 8; i++) {
        int row = by * 128 + ty * 8 + i;
#pragma unroll
        for (int j = 0; j < 8; j++) {
            int col = bx * 128 + tx * 8 + j;
            float v = acc[i][j];
            if (MODE == 0) v += aux[col];
            if (MODE == 1) v *= 0.125f;
            C[(size_t)row * ldc + col] = v;
        }
    }
}

// ---------------- ||key_store[h,m]||^2 ----------------
__global__ void ksnorm_kernel(const float* __restrict__ ks, float* __restrict__ nrm) {
    int r = blockIdx.x * blockDim.x + threadIdx.x;
    if (r >= 16 * 8192) return;
    const float4* p = (const float4*)(ks + (size_t)r * 64);
    float s = 0.f;
#pragma unroll
    for (int i = 0; i < 16; i++) {
        float4 f = p[i];
        s += f.x * f.x + f.y * f.y + f.z * f.z + f.w * f.w;
    }
    nrm[r] = s;
}

// ------- causal row softmax (in place), single read, register-cached -------
__global__ void softmax_kernel(float* __restrict__ att) {
    int t = blockIdx.x, h = blockIdx.y;
    float* row = att + ((size_t)h * 1024 + t) * 1024;
    int tid = threadIdx.x;
    int lane = tid & 31, warp = tid >> 5;
    int n = t + 1;

    __shared__ float red[8];
    __shared__ float bcast;

    float v[4];
#pragma unroll
    for (int u = 0; u < 4; u++) {
        int k = tid + u * 256;
        v[u] = (k < n) ? row[k] : -FLT_MAX;
    }
    float m = fmaxf(fmaxf(v[0], v[1]), fmaxf(v[2], v[3]));
#pragma unroll
    for (int o = 16; o > 0; o >>= 1) m = fmaxf(m, __shfl_xor_sync(0xffffffffu, m, o));
    if (lane == 0) red[warp] = m;
    __syncthreads();
    if (tid == 0) {
        float x = red[0];
#pragma unroll
        for (int w = 1; w < 8; w++) x = fmaxf(x, red[w]);
        bcast = x;
    }
    __syncthreads();
    m = bcast;

    float e[4], s = 0.f;
#pragma unroll
    for (int u = 0; u < 4; u++) {
        int k = tid + u * 256;
        e[u] = (k < n) ? __expf(v[u] - m) : 0.f;
        s += e[u];
    }
#pragma unroll
    for (int o = 16; o > 0; o >>= 1) s += __shfl_xor_sync(0xffffffffu, s, o);
    if (lane == 0) red[warp] = s;
    __syncthreads();
    if (tid == 0) {
        float x = 0.f;
#pragma unroll
        for (int w = 0; w < 8; w++) x += red[w];
        bcast = x;
    }
    __syncthreads();
    float inv = 1.f / bcast;

#pragma unroll
    for (int u = 0; u < 4; u++) {
        int k = tid + u * 256;
        row[k] = (k < n) ? e[u] * inv : 0.f;
    }
}

// ---------------- sel[h,t] = att[h, T-1, t] >= 1/(MEM_FRAC*T) ----------------
__global__ void sel_kernel(const float* __restrict__ att, int* __restrict__ sel) {
    int i = blockIdx.x * 256 + threadIdx.x;
    int h = i >> 10, t = i & 1023;
    float a = att[((size_t)h * 1024 + 1023) * 1024 + t];
    sel[i] = (a >= (1.0f / 8192.0f)) ? 1 : 0;
}

// ------------- lexicographic (score, idx) compare: stable top-k --------------
__device__ __forceinline__ bool lex_lt(float sa, int ia, float sb, int ib) {
    return sa < sb || (sa == sb && ia < ib);
}

#define TOP4_INSERT(v, m, s0, x0, s1, x1, s2, x2, s3, x3)              \
    if (lex_lt(v, m, s3, x3)) {                                        \
        if (lex_lt(v, m, s2, x2)) {                                    \
            s3 = s2; x3 = x2;                                          \
            if (lex_lt(v, m, s1, x1)) {                                \
                s2 = s1; x2 = x1;                                      \
                if (lex_lt(v, m, s0, x0)) {                            \
                    s1 = s0; x1 = x0; s0 = v; x0 = m;                  \
                } else { s1 = v; x1 = m; }                             \
            } else { s2 = v; x2 = m; }                                 \
        } else { s3 = v; x3 = m; }                                     \
    }

// ---- fused kNN scores + per-split top-4; M split 4-ways; reg-staged prefetch ----
// Block: 256 thr, 64 t-rows x one head x 2048 memory slots (16 chunks of 128).
#define KNN_AS_STRIDE 68
#define KNN_BS_STRIDE 132
#define KNN_SMEM_FLOATS (64 * KNN_AS_STRIDE + 64 * KNN_BS_STRIDE + 128)

__global__ __launch_bounds__(256, 2) void knn_topk_kernel(
    const float* __restrict__ qkv, const float* __restrict__ kstore,
    const float* __restrict__ ksn, float* __restrict__ psc, int* __restrict__ pix) {
    extern __shared__ float sm[];
    float* As = sm;                                   // [64][68]  k-major
    float* Bs = sm + 64 * KNN_AS_STRIDE;              // [64][132] k-major
    float* Ns = Bs + 64 * KNN_BS_STRIDE;              // [128]

    const int tid = threadIdx.x;
    const int t0 = blockIdx.x * 64;
    const int h = blockIdx.y;
    const int mz = blockIdx.z;                        // M quarter
    const int tx = tid & 15;
    const int ty = tid >> 4;

    // A tile: k-vectors of 64 t-rows, transposed to [k][t]
    const float* Abase = qkv + (size_t)t0 * 3072 + 1024 + h * 64;
    for (int i = tid; i < 64 * 16; i += 256) {
        int r = i & 63, c4 = (i >> 6) << 2;
        float4 v = *(const float4*)(Abase + (size_t)r * 3072 + c4);
        As[(c4 + 0) * KNN_AS_STRIDE + r] = v.x;
        As[(c4 + 1) * KNN_AS_STRIDE + r] = v.y;
        As[(c4 + 2) * KNN_AS_STRIDE + r] = v.z;
        As[(c4 + 3) * KNN_AS_STRIDE + r] = v.w;
    }

    float s0[4], s1[4], s2[4], s3[4];
    int x0[4], x1[4], x2[4], x3[4];
#pragma unroll
    for (int i = 0; i < 4; i++) {
        s0[i] = s1[i] = s2[i] = s3[i] = FLT_MAX;
        x0[i] = x1[i] = x2[i] = x3[i] = 0x7fffffff;
    }

    const float* Bbase = kstore + ((size_t)h * 8192 + mz * 2048) * 64;
    const float* Nbase = ksn + h * 8192 + mz * 2048;

    const int r = tid & 127, bsel = tid >> 7;
    float4 stg[8];
    float nstg = 0.f;

    // stage chunk 0
    {
        const float* p = Bbase + (size_t)r * 64 + bsel * 4;
#pragma unroll
        for (int s = 0; s < 8; s++) stg[s] = *(const float4*)(p + 8 * s);
        if (tid < 128) nstg = Nbase[tid];
    }

    for (int c = 0; c < 16; c++) {
        __syncthreads();  // prior compute (and initial As loads) done
#pragma unroll
        for (int s = 0; s < 8; s++) {
            int c4 = bsel * 4 + 8 * s;
            Bs[(c4 + 0) * KNN_BS_STRIDE + r] = stg[s].x;
            Bs[(c4 + 1) * KNN_BS_STRIDE + r] = stg[s].y;
            Bs[(c4 + 2) * KNN_BS_STRIDE + r] = stg[s].z;
            Bs[(c4 + 3) * KNN_BS_STRIDE + r] = stg[s].w;
        }
        if (tid < 128) Ns[tid] = nstg;
        __syncthreads();

        if (c + 1 < 16) {  // prefetch next chunk; latency hidden under compute
            const float* p = Bbase + (size_t)((c + 1) * 128 + r) * 64 + bsel * 4;
#pragma unroll
            for (int s = 0; s < 8; s++) stg[s] = *(const float4*)(p + 8 * s);
            if (tid < 128) nstg = Nbase[(c + 1) * 128 + tid];
        }

        float acc[4][8];
#pragma unroll
        for (int i = 0; i < 4; i++)
#pragma unroll
            for (int j = 0; j < 8; j++) acc[i][j] = 0.f;

#pragma unroll 8
        for (int kk = 0; kk < 64; kk++) {
            float a[4], b[8];
#pragma unroll
            for (int i = 0; i < 4; i++) a[i] = As[kk * KNN_AS_STRIDE + ty * 4 + i];
#pragma unroll
            for (int j = 0; j < 8; j++) b[j] = Bs[kk * KNN_BS_STRIDE + tx * 8 + j];
#pragma unroll
            for (int i = 0; i < 4; i++)
#pragma unroll
                for (int j = 0; j < 8; j++) acc[i][j] = fmaf(a[i], b[j], acc[i][j]);
        }

        const int m0 = mz * 2048 + c * 128;
#pragma unroll
        for (int i = 0; i < 4; i++) {
#pragma unroll
            for (int j = 0; j < 8; j++) {
                int m = m0 + tx * 8 + j;
                float v = Ns[tx * 8 + j] - 2.0f * acc[i][j];
                TOP4_INSERT(v, m, s0[i], x0[i], s1[i], x1[i], s2[i], x2[i], s3[i], x3[i]);
            }
        }
    }

    // merge 16 per-thread lists per row -> top-4 of this M quarter
    __syncthreads();
    float* msc = As;
    int* mix = (int*)Bs;
#pragma unroll
    for (int i = 0; i < 4; i++) {
        int rr = ty * 4 + i;
        msc[(rr * 16 + tx) * 4 + 0] = s0[i]; mix[(rr * 16 + tx) * 4 + 0] = x0[i];
        msc[(rr * 16 + tx) * 4 + 1] = s1[i]; mix[(rr * 16 + tx) * 4 + 1] = x1[i];
        msc[(rr * 16 + tx) * 4 + 2] = s2[i]; mix[(rr * 16 + tx) * 4 + 2] = x2[i];
        msc[(rr * 16 + tx) * 4 + 3] = s3[i]; mix[(rr * 16 + tx) * 4 + 3] = x3[i];
    }
    __syncthreads();
    if (tid < 64) {
        float f0 = FLT_MAX, f1 = FLT_MAX, f2 = FLT_MAX, f3 = FLT_MAX;
        int g0 = 0x7fffffff, g1 = 0x7fffffff, g2 = 0x7fffffff, g3 = 0x7fffffff;
        for (int c = 0; c < 64; c++) {
            float v = msc[tid * 64 + c];
            int m = mix[tid * 64 + c];
            TOP4_INSERT(v, m, f0, g0, f1, g1, f2, g2, f3, g3);
        }
        size_t row = (size_t)h * 1024 + t0 + tid;
        size_t o = row * 16 + mz * 4;
        psc[o + 0] = f0; pix[o + 0] = g0;
        psc[o + 1] = f1; pix[o + 1] = g1;
        psc[o + 2] = f2; pix[o + 2] = g2;
        psc[o + 3] = f3; pix[o + 3] = g3;
    }
}

// ---------------- merge 4 partial top-4 lists -> exact global top-4 ----------------
__global__ void knn_merge_kernel(const float* __restrict__ psc, const int* __restrict__ pix,
                                 int* __restrict__ idx_out) {
    int r = blockIdx.x * 256 + threadIdx.x;  // < 16384
    float s0 = FLT_MAX, s1 = FLT_MAX, s2 = FLT_MAX, s3 = FLT_MAX;
    int x0 = 0x7fffffff, x1 = 0x7fffffff, x2 = 0x7fffffff, x3 = 0x7fffffff;
#pragma unroll
    for (int c = 0; c < 16; c++) {
        float v = psc[(size_t)r * 16 + c];
        int m = pix[(size_t)r * 16 + c];
        TOP4_INSERT(v, m, s0, x0, s1, x1, s2, x2, s3, x3);
    }
    idx_out[(size_t)r * 4 + 0] = x0;
    idx_out[(size_t)r * 4 + 1] = x1;
    idx_out[(size_t)r * 4 + 2] = x2;
    idx_out[(size_t)r * 4 + 3] = x3;
}

// ---------------- per-token 5-way memory softmax & blend -> v_new ----------------
__device__ __forceinline__ float warp_sum(float v) {
#pragma unroll
    for (int o = 16; o > 0; o >>= 1) v += __shfl_xor_sync(0xffffffffu, v, o);
    return v;
}

__global__ void vnew_kernel(const float* __restrict__ qkv, const float* __restrict__ kstore,
                            const float* __restrict__ vstore, const int* __restrict__ idx,
                            const int* __restrict__ sel, float* __restrict__ vnew) {
    int gw = (blockIdx.x * blockDim.x + threadIdx.x) >> 5;
    int lane = threadIdx.x & 31;
    if (gw >= 16 * 1024) return;
    int h = gw >> 10, t = gw & 1023;

    const float* base = qkv + (size_t)t * 3072 + h * 64;
    int d0 = lane * 2;
    float q0 = base[d0],        q1 = base[d0 + 1];
    float k0 = base[1024 + d0], k1 = base[1024 + d0 + 1];
    float v0 = base[2048 + d0], v1 = base[2048 + d0 + 1];
    const float scale = 0.125f;

    float attf[5];
    attf[0] = warp_sum(q0 * k0 + q1 * k1) * scale;

    int ids[4];
#pragma unroll
    for (int s2 = 0; s2 < 4; s2++) ids[s2] = idx[(size_t)gw * 4 + s2];

    float fv0[4], fv1[4];
#pragma unroll
    for (int s2 = 0; s2 < 4; s2++) {
        const float* kp = kstore + ((size_t)h * 8192 + ids[s2]) * 64;
        attf[s2 + 1] = warp_sum(q0 * kp[d0] + q1 * kp[d0 + 1]) * scale;
        const float* vp = vstore + ((size_t)h * 8192 + ids[s2]) * 64;
        fv0[s2] = vp[d0]; fv1[s2] = vp[d0 + 1];
    }

    float mx = attf[0];
#pragma unroll
    for (int s2 = 1; s2 < 5; s2++) mx = fmaxf(mx, attf[s2]);
    float e[5], sum = 0.f;
#pragma unroll
    for (int s2 = 0; s2 < 5; s2++) { e[s2] = expf(attf[s2] - mx); sum += e[s2]; }
    float inv = 1.f / sum;

    float o0 = e[0] * v0, o1 = e[0] * v1;
#pragma unroll
    for (int s2 = 0; s2 < 4; s2++) { o0 += e[s2 + 1] * fv0[s2]; o1 += e[s2 + 1] * fv1[s2]; }
    o0 = o0 * inv * 0.5f + v0 * 0.5f;
    o1 = o1 * inv * 0.5f + v1 * 0.5f;

    bool sl = sel[gw] != 0;
    vnew[(size_t)gw * 64 + d0]     = sl ? o0 : v0;
    vnew[(size_t)gw * 64 + d0 + 1] = sl ? o1 : v1;
}

// ---------------- y = att @ v_new  (per head, N=64), writes (T,C) layout ----------------
__global__ void ygemm_kernel(const float* __restrict__ att, const float* __restrict__ vnew,
                             float* __restrict__ y) {
    int h = blockIdx.y, t0 = blockIdx.x * 128;
    __shared__ float As[16][132];
    __shared__ float Bs[16][64];
    int tid = threadIdx.x;
    int tx = tid & 7, ty = tid >> 3;

    float acc[4][8];
#pragma unroll
    for (int i = 0; i < 4; i++)
#pragma unroll
        for (int j = 0; j < 8; j++) acc[i][j] = 0.f;

    const float* Ab = att + ((size_t)h * 1024 + t0) * 1024;
    const float* Bb = vnew + (size_t)h * 1024 * 64;

    int r = tid >> 2, c = (tid & 3) * 4;
    int rb = tid >> 4, cb = (tid & 15) * 4;

    for (int k0 = 0; k0 < 1024; k0 += 16) {
        float4 fa0 = *(const float4*)(Ab + (size_t)r * 1024 + k0 + c);
        float4 fa1 = *(const float4*)(Ab + (size_t)(r + 64) * 1024 + k0 + c);
        float4 fb  = *(const float4*)(Bb + (size_t)(k0 + rb) * 64 + cb);
        __syncthreads();
        As[c + 0][r] = fa0.x; As[c + 1][r] = fa0.y; As[c + 2][r] = fa0.z; As[c + 3][r] = fa0.w;
        As[c + 0][r + 64] = fa1.x; As[c + 1][r + 64] = fa1.y;
        As[c + 2][r + 64] = fa1.z; As[c + 3][r + 64] = fa1.w;
        *(float4*)&Bs[rb][cb] = fb;
        __syncthreads();
#pragma unroll
        for (int kk = 0; kk < 16; kk++) {
            float a[4], b[8];
#pragma unroll
            for (int i = 0; i < 4; i++) a[i] = As[kk][ty * 4 + i];
#pragma unroll
            for (int j = 0; j < 8; j++) b[j] = Bs[kk][tx * 8 + j];
#pragma unroll
            for (int i = 0; i < 4; i++)
#pragma unroll
                for (int j = 0; j < 8; j++) acc[i][j] = fmaf(a[i], b[j], acc[i][j]);
        }
    }

#pragma unroll
    for (int i = 0; i < 4; i++)
#pragma unroll
        for (int j = 0; j < 8; j++)
            y[(size_t)(t0 + ty * 4 + i) * 1024 + h * 64 + tx * 8 + j] = acc[i][j];
}

// ---------------- launch ----------------
extern "C" void kernel_launch(void* const* d_in, const int* in_sizes, int n_in,
                              void* d_out, int out_size) {
    const float* x  = (const float*)d_in[0];
    const float* aw = (const float*)d_in[1];
    const float* ab = (const float*)d_in[2];
    const float* pw = (const float*)d_in[3];
    const float* pb = (const float*)d_in[4];
    const float* ks = (const float*)d_in[5];
    const float* vs = (const float*)d_in[6];
    float* out = (float*)d_out;

    float *qkv, *att, *ksn, *psc, *vnw, *y;
    int *pix, *idx, *sel;
    cudaGetSymbolAddress((void**)&qkv, g_qkv);
    cudaGetSymbolAddress((void**)&att, g_att);
    cudaGetSymbolAddress((void**)&ksn, g_ksnorm);
    cudaGetSymbolAddress((void**)&psc, g_psc);
    cudaGetSymbolAddress((void**)&pix, g_pix);
    cudaGetSymbolAddress((void**)&idx, g_idx);
    cudaGetSymbolAddress((void**)&sel, g_sel);
    cudaGetSymbolAddress((void**)&vnw, g_vnew);
    cudaGetSymbolAddress((void**)&y,   g_y);

    cudaFuncSetAttribute(knn_topk_kernel,
                         cudaFuncAttributeMaxDynamicSharedMemorySize,
                         KNN_SMEM_FLOATS * (int)sizeof(float));

    // 1) qkv = x @ c_attn_w^T + b
    gemm128db<0><<<dim3(24, 8, 1), 256>>>(x, 1024, 0, aw, 1024, 0,
                                          qkv, 3072, 0, 1024, ab, 0);
    // 2) ||key_store||^2
    ksnorm_kernel<<<512, 256>>>(ks, ksn);
    // 3) logits = q k^T / 8 (causal tiles only)
    gemm128db<1><<<dim3(8, 8, 16), 256>>>(qkv, 3072, 64, qkv + 1024, 3072, 64,
                                          att, 1024, 1024LL * 1024, 64, nullptr, 0);
    // 4) causal softmax in place
    softmax_kernel<<<dim3(1024, 16), 256>>>(att);
    // 5) sel from last row
    sel_kernel<<<64, 256>>>(att, sel);
    // 6) fused kNN scores + per-quarter top-4
    knn_topk_kernel<<<dim3(16, 16, 4), 256, KNN_SMEM_FLOATS * sizeof(float)>>>(
        qkv, ks, ksn, psc, pix);
    // 7) exact merge of quarters
    knn_merge_kernel<<<64, 256>>>(psc, pix, idx);
    // 8) 5-way softmax blend -> v_new
    vnew_kernel<<<2048, 256>>>(qkv, ks, vs, idx, sel, vnw);
    // 9) y = att @ v_new
    ygemm_kernel<<<dim3(8, 16), 256>>>(att, vnw, y);
    // 10) out = y @ c_proj_w^T + b
    gemm128db<0><<<dim3(8, 8, 1), 256>>>(y, 1024, 0, pw, 1024, 0,
                                         out, 1024, 0, 1024, pb, 0);
}

// round 5
// speedup vs baseline: 1.0759x; 1.0759x over previous
#include <cuda_runtime.h>
#include <cfloat>
#include <cstdint>

// ---------------- scratch (__device__ globals; no allocations) ----------------
__device__ float g_qkv[1024 * 3072];              // 12 MB  (T, 3C)
__device__ float g_ksnorm[16 * 8192];             // (H, M)
__device__ int   g_idx[16 * 1024 * 4];            // (H, T, 4)
__device__ int   g_sel[16 * 1024];                // (H, T)
__device__ float g_vnew[16 * 1024 * 64];          // (H, T, d)
__device__ float g_y[1024 * 1024];                // (T, C)

// ---------------- generic 128x128x16 SGEMM: C = A * B^T + bias ----------------
// (round-2 known-good single-buffer version)
__global__ void gemm128(const float* __restrict__ A, int lda,
                        const float* __restrict__ B, int ldb,
                        float* __restrict__ C, int ldc,
                        int K, const float* __restrict__ aux) {
    int bx = blockIdx.x, by = blockIdx.y;
    A += (size_t)by * 128 * lda;
    B += (size_t)bx * 128 * ldb;

    __shared__ float As[16][128];
    __shared__ float Bs[16][128];

    int tid = threadIdx.x;
    int tx = tid & 15, ty = tid >> 4;
    int lr = tid >> 1, lc = (tid & 1) * 4;

    float acc[8][8];
#pragma unroll
    for (int i = 0; i < 8; i++)
#pragma unroll
        for (int j = 0; j < 8; j++) acc[i][j] = 0.f;

    const float* Ap = A + (size_t)lr * lda + lc;
    const float* Bp = B + (size_t)lr * ldb + lc;

    for (int k0 = 0; k0 < K; k0 += 16) {
        float4 a0 = *(const float4*)(Ap + k0);
        float4 a1 = *(const float4*)(Ap + k0 + 8);
        float4 b0 = *(const float4*)(Bp + k0);
        float4 b1 = *(const float4*)(Bp + k0 + 8);
        __syncthreads();
        As[lc + 0][lr] = a0.x; As[lc + 1][lr] = a0.y;
        As[lc + 2][lr] = a0.z; As[lc + 3][lr] = a0.w;
        As[lc + 8][lr] = a1.x; As[lc + 9][lr] = a1.y;
        As[lc + 10][lr] = a1.z; As[lc + 11][lr] = a1.w;
        Bs[lc + 0][lr] = b0.x; Bs[lc + 1][lr] = b0.y;
        Bs[lc + 2][lr] = b0.z; Bs[lc + 3][lr] = b0.w;
        Bs[lc + 8][lr] = b1.x; Bs[lc + 9][lr] = b1.y;
        Bs[lc + 10][lr] = b1.z; Bs[lc + 11][lr] = b1.w;
        __syncthreads();
#pragma unroll
        for (int kk = 0; kk < 16; kk++) {
            float a[8], b[8];
#pragma unroll
            for (int i = 0; i < 8; i++) a[i] = As[kk][ty * 8 + i];
#pragma unroll
            for (int j = 0; j < 8; j++) b[j] = Bs[kk][tx * 8 + j];
#pragma unroll
            for (int i = 0; i < 8; i++)
#pragma unroll
                for (int j = 0; j < 8; j++) acc[i][j] = fmaf(a[i], b[j], acc[i][j]);
        }
    }

#pragma unroll
    for (int i = 0; i < 8; i++) {
        int row = by * 128 + ty * 8 + i;
#pragma unroll
        for (int j = 0; j < 8; j++) {
            int col = bx * 128 + tx * 8 + j;
            C[(size_t)row * ldc + col] = acc[i][j] + aux[col];
        }
    }
}

// ---------------- ||key_store[h,m]||^2 ----------------
__global__ void ksnorm_kernel(const float* __restrict__ ks, float* __restrict__ nrm) {
    int r = blockIdx.x * blockDim.x + threadIdx.x;
    if (r >= 16 * 8192) return;
    const float4* p = (const float4*)(ks + (size_t)r * 64);
    float s = 0.f;
#pragma unroll
    for (int i = 0; i < 16; i++) {
        float4 f = p[i];
        s += f.x * f.x + f.y * f.y + f.z * f.z + f.w * f.w;
    }
    nrm[r] = s;
}

// -------- sel from softmax of the LAST causal row only (full row, t=1023) --------
__global__ void sel_kernel(const float* __restrict__ qkv, int* __restrict__ sel) {
    int h = blockIdx.x;
    int tid = threadIdx.x;
    int lane = tid & 31, warp = tid >> 5;
    __shared__ float qrow[64];
    __shared__ float red[8];
    __shared__ float bcast;
    if (tid < 64) qrow[tid] = qkv[(size_t)1023 * 3072 + h * 64 + tid];
    __syncthreads();

    float lg[4];
#pragma unroll
    for (int u = 0; u < 4; u++) {
        int t = tid + u * 256;
        const float* kp = qkv + (size_t)t * 3072 + 1024 + h * 64;
        float s = 0.f;
#pragma unroll
        for (int k = 0; k < 64; k++) s = fmaf(qrow[k], kp[k], s);
        lg[u] = s * 0.125f;
    }
    float m = fmaxf(fmaxf(lg[0], lg[1]), fmaxf(lg[2], lg[3]));
#pragma unroll
    for (int o = 16; o > 0; o >>= 1) m = fmaxf(m, __shfl_xor_sync(0xffffffffu, m, o));
    if (lane == 0) red[warp] = m;
    __syncthreads();
    if (tid == 0) {
        float x = red[0];
#pragma unroll
        for (int w = 1; w < 8; w++) x = fmaxf(x, red[w]);
        bcast = x;
    }
    __syncthreads();
    m = bcast;
    float e[4], s = 0.f;
#pragma unroll
    for (int u = 0; u < 4; u++) { e[u] = __expf(lg[u] - m); s += e[u]; }
#pragma unroll
    for (int o = 16; o > 0; o >>= 1) s += __shfl_xor_sync(0xffffffffu, s, o);
    if (lane == 0) red[warp] = s;
    __syncthreads();
    if (tid == 0) {
        float x = 0.f;
#pragma unroll
        for (int w = 0; w < 8; w++) x += red[w];
        bcast = x;
    }
    __syncthreads();
    float inv = 1.f / bcast;
#pragma unroll
    for (int u = 0; u < 4; u++) {
        int t = tid + u * 256;
        sel[h * 1024 + t] = (e[u] * inv >= (1.0f / 8192.0f)) ? 1 : 0;
    }
}

// ------------- lexicographic (score, idx) compare: stable top-k --------------
__device__ __forceinline__ bool lex_lt(float sa, int ia, float sb, int ib) {
    return sa < sb || (sa == sb && ia < ib);
}

#define TOP4_INSERT(v, m, s0, x0, s1, x1, s2, x2, s3, x3)              \
    if (lex_lt(v, m, s3, x3)) {                                        \
        if (lex_lt(v, m, s2, x2)) {                                    \
            s3 = s2; x3 = x2;                                          \
            if (lex_lt(v, m, s1, x1)) {                                \
                s2 = s1; x2 = x1;                                      \
                if (lex_lt(v, m, s0, x0)) {                            \
                    s1 = s0; x1 = x0; s0 = v; x0 = m;                  \
                } else { s1 = v; x1 = m; }                             \
            } else { s2 = v; x2 = m; }                                 \
        } else { s3 = v; x3 = m; }                                     \
    }

// ---------------- fused kNN scores + top-4 (round-2 known-good) --------
#define KNN_AS_STRIDE 68
#define KNN_BS_STRIDE 132
#define KNN_SMEM_FLOATS (64 * KNN_AS_STRIDE + 64 * KNN_BS_STRIDE + 128)

__global__ __launch_bounds__(256) void knn_topk_kernel(
    const float* __restrict__ qkv, const float* __restrict__ kstore,
    const float* __restrict__ ksn, int* __restrict__ idx_out) {
    extern __shared__ float sm[];
    float* As = sm;                                   // [64][68]  k-major
    float* Bs = sm + 64 * KNN_AS_STRIDE;              // [64][132] k-major
    float* Ns = Bs + 64 * KNN_BS_STRIDE;              // [128]

    const int tid = threadIdx.x;
    const int t0 = blockIdx.x * 64;
    const int h = blockIdx.y;
    const int tx = tid & 15;
    const int ty = tid >> 4;

    const float* Abase = qkv + (size_t)t0 * 3072 + 1024 + h * 64;
    for (int i = tid; i < 64 * 16; i += 256) {
        int r = i & 63, c4 = (i >> 6) << 2;
        float4 v = *(const float4*)(Abase + (size_t)r * 3072 + c4);
        As[(c4 + 0) * KNN_AS_STRIDE + r] = v.x;
        As[(c4 + 1) * KNN_AS_STRIDE + r] = v.y;
        As[(c4 + 2) * KNN_AS_STRIDE + r] = v.z;
        As[(c4 + 3) * KNN_AS_STRIDE + r] = v.w;
    }

    float s0[4], s1[4], s2[4], s3[4];
    int x0[4], x1[4], x2[4], x3[4];
#pragma unroll
    for (int i = 0; i < 4; i++) {
        s0[i] = s1[i] = s2[i] = s3[i] = FLT_MAX;
        x0[i] = x1[i] = x2[i] = x3[i] = 0x7fffffff;
    }

    const float* Bbase = kstore + (size_t)h * 8192 * 64;
    const float* Nbase = ksn + h * 8192;

    for (int chunk = 0; chunk < 64; chunk++) {
        const int m0 = chunk << 7;
        __syncthreads();
        if (tid < 128) Ns[tid] = Nbase[m0 + tid];
        for (int i = tid; i < 128 * 16; i += 256) {
            int r = i & 127, c4 = (i >> 7) << 2;
            float4 v = *(const float4*)(Bbase + (size_t)(m0 + r) * 64 + c4);
            Bs[(c4 + 0) * KNN_BS_STRIDE + r] = v.x;
            Bs[(c4 + 1) * KNN_BS_STRIDE + r] = v.y;
            Bs[(c4 + 2) * KNN_BS_STRIDE + r] = v.z;
            Bs[(c4 + 3) * KNN_BS_STRIDE + r] = v.w;
        }
        __syncthreads();

        float acc[4][8];
#pragma unroll
        for (int i = 0; i < 4; i++)
#pragma unroll
            for (int j = 0; j < 8; j++) acc[i][j] = 0.f;

#pragma unroll 8
        for (int kk = 0; kk < 64; kk++) {
            float a[4], b[8];
#pragma unroll
            for (int i = 0; i < 4; i++) a[i] = As[kk * KNN_AS_STRIDE + ty * 4 + i];
#pragma unroll
            for (int j = 0; j < 8; j++) b[j] = Bs[kk * KNN_BS_STRIDE + tx * 8 + j];
#pragma unroll
            for (int i = 0; i < 4; i++)
#pragma unroll
                for (int j = 0; j < 8; j++) acc[i][j] = fmaf(a[i], b[j], acc[i][j]);
        }

#pragma unroll
        for (int i = 0; i < 4; i++) {
#pragma unroll
            for (int j = 0; j < 8; j++) {
                int m = m0 + tx * 8 + j;
                float v = Ns[tx * 8 + j] - 2.0f * acc[i][j];
                TOP4_INSERT(v, m, s0[i], x0[i], s1[i], x1[i], s2[i], x2[i], s3[i], x3[i]);
            }
        }
    }

    __syncthreads();
    float* msc = As;
    int* mix = (int*)Bs;
#pragma unroll
    for (int i = 0; i < 4; i++) {
        int r = ty * 4 + i;
        msc[(r * 16 + tx) * 4 + 0] = s0[i]; mix[(r * 16 + tx) * 4 + 0] = x0[i];
        msc[(r * 16 + tx) * 4 + 1] = s1[i]; mix[(r * 16 + tx) * 4 + 1] = x1[i];
        msc[(r * 16 + tx) * 4 + 2] = s2[i]; mix[(r * 16 + tx) * 4 + 2] = x2[i];
        msc[(r * 16 + tx) * 4 + 3] = s3[i]; mix[(r * 16 + tx) * 4 + 3] = x3[i];
    }
    __syncthreads();
    if (tid < 64) {
        float f0 = FLT_MAX, f1 = FLT_MAX, f2 = FLT_MAX, f3 = FLT_MAX;
        int g0 = 0x7fffffff, g1 = 0x7fffffff, g2 = 0x7fffffff, g3 = 0x7fffffff;
        for (int c = 0; c < 64; c++) {
            float v = msc[tid * 64 + c];
            int m = mix[tid * 64 + c];
            TOP4_INSERT(v, m, f0, g0, f1, g1, f2, g2, f3, g3);
        }
        size_t row = (size_t)h * 1024 + t0 + tid;
        idx_out[row * 4 + 0] = g0;
        idx_out[row * 4 + 1] = g1;
        idx_out[row * 4 + 2] = g2;
        idx_out[row * 4 + 3] = g3;
    }
}

// ---------------- per-token 5-way memory softmax & blend -> v_new ----------------
__device__ __forceinline__ float warp_sum(float v) {
#pragma unroll
    for (int o = 16; o > 0; o >>= 1) v += __shfl_xor_sync(0xffffffffu, v, o);
    return v;
}

__global__ void vnew_kernel(const float* __restrict__ qkv, const float* __restrict__ kstore,
                            const float* __restrict__ vstore, const int* __restrict__ idx,
                            const int* __restrict__ sel, float* __restrict__ vnew) {
    int gw = (blockIdx.x * blockDim.x + threadIdx.x) >> 5;
    int lane = threadIdx.x & 31;
    if (gw >= 16 * 1024) return;
    int h = gw >> 10, t = gw & 1023;

    const float* base = qkv + (size_t)t * 3072 + h * 64;
    int d0 = lane * 2;
    float q0 = base[d0],        q1 = base[d0 + 1];
    float k0 = base[1024 + d0], k1 = base[1024 + d0 + 1];
    float v0 = base[2048 + d0], v1 = base[2048 + d0 + 1];
    const float scale = 0.125f;

    float attf[5];
    attf[0] = warp_sum(q0 * k0 + q1 * k1) * scale;

    int ids[4];
#pragma unroll
    for (int s2 = 0; s2 < 4; s2++) ids[s2] = idx[(size_t)gw * 4 + s2];

    float fv0[4], fv1[4];
#pragma unroll
    for (int s2 = 0; s2 < 4; s2++) {
        const float* kp = kstore + ((size_t)h * 8192 + ids[s2]) * 64;
        attf[s2 + 1] = warp_sum(q0 * kp[d0] + q1 * kp[d0 + 1]) * scale;
        const float* vp = vstore + ((size_t)h * 8192 + ids[s2]) * 64;
        fv0[s2] = vp[d0]; fv1[s2] = vp[d0 + 1];
    }

    float mx = attf[0];
#pragma unroll
    for (int s2 = 1; s2 < 5; s2++) mx = fmaxf(mx, attf[s2]);
    float e[5], sum = 0.f;
#pragma unroll
    for (int s2 = 0; s2 < 5; s2++) { e[s2] = expf(attf[s2] - mx); sum += e[s2]; }
    float inv = 1.f / sum;

    float o0 = e[0] * v0, o1 = e[0] * v1;
#pragma unroll
    for (int s2 = 0; s2 < 4; s2++) { o0 += e[s2 + 1] * fv0[s2]; o1 += e[s2 + 1] * fv1[s2]; }
    o0 = o0 * inv * 0.5f + v0 * 0.5f;
    o1 = o1 * inv * 0.5f + v1 * 0.5f;

    bool sl = sel[gw] != 0;
    vnew[(size_t)gw * 64 + d0]     = sl ? o0 : v0;
    vnew[(size_t)gw * 64 + d0 + 1] = sl ? o1 : v1;
}

// ------- fused flash attention: y = softmax_causal(q k^T / 8) @ v_new -------
// Block: 256 threads, 128 q-rows x one head. Streams 64-wide k-blocks.
// smem: Qs[64][132] (k-major, q pre-scaled), Ks[64][68], Vs[64][68], Ps[128][68]
#define FL_QS 132
#define FL_KS 68
#define FL_VS 68
#define FL_PS 68
#define FL_SMEM_FLOATS (64 * FL_QS + 64 * FL_KS + 64 * FL_VS + 128 * FL_PS)

__global__ __launch_bounds__(256) void flash_kernel(
    const float* __restrict__ qkv, const float* __restrict__ vnew,
    float* __restrict__ y) {
    extern __shared__ float sm[];
    float* Qs = sm;
    float* Ks = Qs + 64 * FL_QS;
    float* Vs = Ks + 64 * FL_KS;
    float* Ps = Vs + 64 * FL_VS;

    const int tid = threadIdx.x;
    const int qb = blockIdx.x, h = blockIdx.y;
    const int tx = tid & 15, ty = tid >> 4;
    const int t0 = qb * 128;

    // Q tile (scaled by 0.125 — exact power of two, bit-neutral), k-major [k][t]
    const float* Qbase = qkv + (size_t)t0 * 3072 + h * 64;
    for (int i = tid; i < 128 * 16; i += 256) {
        int r = i & 127, c4 = (i >> 7) << 2;
        float4 v = *(const float4*)(Qbase + (size_t)r * 3072 + c4);
        Qs[(c4 + 0) * FL_QS + r] = v.x * 0.125f;
        Qs[(c4 + 1) * FL_QS + r] = v.y * 0.125f;
        Qs[(c4 + 2) * FL_QS + r] = v.z * 0.125f;
        Qs[(c4 + 3) * FL_QS + r] = v.w * 0.125f;
    }

    float m[8], l[8], O[8][4];
#pragma unroll
    for (int i = 0; i < 8; i++) {
        m[i] = -FLT_MAX; l[i] = 0.f;
#pragma unroll
        for (int j = 0; j < 4; j++) O[i][j] = 0.f;
    }

    const int nj = 2 * qb + 2;
    for (int j = 0; j < nj; j++) {
        const int s0 = j * 64;
        __syncthreads();  // prev PV done (and Qs loads on first iter)
        // K block, k-major [k][s]
        const float* Kbase = qkv + (size_t)s0 * 3072 + 1024 + h * 64;
        for (int i = tid; i < 64 * 16; i += 256) {
            int r = i & 63, c4 = (i >> 6) << 2;
            float4 v = *(const float4*)(Kbase + (size_t)r * 3072 + c4);
            Ks[(c4 + 0) * FL_KS + r] = v.x;
            Ks[(c4 + 1) * FL_KS + r] = v.y;
            Ks[(c4 + 2) * FL_KS + r] = v.z;
            Ks[(c4 + 3) * FL_KS + r] = v.w;
        }
        // V block, row-major [s][d]
        const float* Vbase = vnew + ((size_t)h * 1024 + s0) * 64;
        for (int i = tid; i < 64 * 16; i += 256) {
            int r = i >> 4, c4 = (i & 15) << 2;
            *(float4*)&Vs[r * FL_VS + c4] = *(const float4*)(Vbase + (size_t)r * 64 + c4);
        }
        __syncthreads();

        // S = Qs^T Ks : 8t x 4s per thread
        float acc[8][4];
#pragma unroll
        for (int i = 0; i < 8; i++)
#pragma unroll
            for (int jj = 0; jj < 4; jj++) acc[i][jj] = 0.f;
#pragma unroll 8
        for (int kk = 0; kk < 64; kk++) {
            float4 a0 = *(const float4*)&Qs[kk * FL_QS + ty * 8];
            float4 a1 = *(const float4*)&Qs[kk * FL_QS + ty * 8 + 4];
            float4 b  = *(const float4*)&Ks[kk * FL_KS + tx * 4];
            float av[8] = {a0.x, a0.y, a0.z, a0.w, a1.x, a1.y, a1.z, a1.w};
            float bv[4] = {b.x, b.y, b.z, b.w};
#pragma unroll
            for (int i = 0; i < 8; i++)
#pragma unroll
                for (int jj = 0; jj < 4; jj++)
                    acc[i][jj] = fmaf(av[i], bv[jj], acc[i][jj]);
        }

        const bool diag = (j >= 2 * qb);  // masking can only trigger here
#pragma unroll
        for (int i = 0; i < 8; i++) {
            int tg = t0 + ty * 8 + i;
            float v0 = acc[i][0], v1 = acc[i][1], v2 = acc[i][2], v3 = acc[i][3];
            if (diag) {
                int sg = s0 + tx * 4;
                if (sg + 0 > tg) v0 = -FLT_MAX;
                if (sg + 1 > tg) v1 = -FLT_MAX;
                if (sg + 2 > tg) v2 = -FLT_MAX;
                if (sg + 3 > tg) v3 = -FLT_MAX;
            }
            float rm = fmaxf(fmaxf(v0, v1), fmaxf(v2, v3));
#pragma unroll
            for (int o = 8; o > 0; o >>= 1) rm = fmaxf(rm, __shfl_xor_sync(0xffffffffu, rm, o));
            float mn = fmaxf(m[i], rm);
            float alpha = __expf(m[i] - mn);
            float p0 = __expf(v0 - mn), p1 = __expf(v1 - mn);
            float p2 = __expf(v2 - mn), p3 = __expf(v3 - mn);
            float ps = p0 + p1 + p2 + p3;
#pragma unroll
            for (int o = 8; o > 0; o >>= 1) ps += __shfl_xor_sync(0xffffffffu, ps, o);
            l[i] = l[i] * alpha + ps;
            m[i] = mn;
#pragma unroll
            for (int jj = 0; jj < 4; jj++) O[i][jj] *= alpha;
            float4 pv = {p0, p1, p2, p3};
            *(float4*)&Ps[(ty * 8 + i) * FL_PS + tx * 4] = pv;
        }
        __syncthreads();  // Ps fully written

        // O += P @ V : 8t x 4d per thread (d = tx*4..)
#pragma unroll 4
        for (int s4 = 0; s4 < 16; s4++) {
            float4 vv0 = *(const float4*)&Vs[(s4 * 4 + 0) * FL_VS + tx * 4];
            float4 vv1 = *(const float4*)&Vs[(s4 * 4 + 1) * FL_VS + tx * 4];
            float4 vv2 = *(const float4*)&Vs[(s4 * 4 + 2) * FL_VS + tx * 4];
            float4 vv3 = *(const float4*)&Vs[(s4 * 4 + 3) * FL_VS + tx * 4];
#pragma unroll
            for (int i = 0; i < 8; i++) {
                float4 pp = *(const float4*)&Ps[(ty * 8 + i) * FL_PS + s4 * 4];
                O[i][0] = fmaf(pp.x, vv0.x, O[i][0]); O[i][1] = fmaf(pp.x, vv0.y, O[i][1]);
                O[i][2] = fmaf(pp.x, vv0.z, O[i][2]); O[i][3] = fmaf(pp.x, vv0.w, O[i][3]);
                O[i][0] = fmaf(pp.y, vv1.x, O[i][0]); O[i][1] = fmaf(pp.y, vv1.y, O[i][1]);
                O[i][2] = fmaf(pp.y, vv1.z, O[i][2]); O[i][3] = fmaf(pp.y, vv1.w, O[i][3]);
                O[i][0] = fmaf(pp.z, vv2.x, O[i][0]); O[i][1] = fmaf(pp.z, vv2.y, O[i][1]);
                O[i][2] = fmaf(pp.z, vv2.z, O[i][2]); O[i][3] = fmaf(pp.z, vv2.w, O[i][3]);
                O[i][0] = fmaf(pp.w, vv3.x, O[i][0]); O[i][1] = fmaf(pp.w, vv3.y, O[i][1]);
                O[i][2] = fmaf(pp.w, vv3.z, O[i][2]); O[i][3] = fmaf(pp.w, vv3.w, O[i][3]);
            }
        }
    }

    // epilogue: y[t][h*64 + d] = O / l
#pragma unroll
    for (int i = 0; i < 8; i++) {
        float inv = 1.f / l[i];
        float4 o = {O[i][0] * inv, O[i][1] * inv, O[i][2] * inv, O[i][3] * inv};
        *(float4*)&y[(size_t)(t0 + ty * 8 + i) * 1024 + h * 64 + tx * 4] = o;
    }
}

// ---------------- launch ----------------
extern "C" void kernel_launch(void* const* d_in, const int* in_sizes, int n_in,
                              void* d_out, int out_size) {
    const float* x  = (const float*)d_in[0];
    const float* aw = (const float*)d_in[1];
    const float* ab = (const float*)d_in[2];
    const float* pw = (const float*)d_in[3];
    const float* pb = (const float*)d_in[4];
    const float* ks = (const float*)d_in[5];
    const float* vs = (const float*)d_in[6];
    float* out = (float*)d_out;

    float *qkv, *ksn, *vnw, *y;
    int *idx, *sel;
    cudaGetSymbolAddress((void**)&qkv, g_qkv);
    cudaGetSymbolAddress((void**)&ksn, g_ksnorm);
    cudaGetSymbolAddress((void**)&idx, g_idx);
    cudaGetSymbolAddress((void**)&sel, g_sel);
    cudaGetSymbolAddress((void**)&vnw, g_vnew);
    cudaGetSymbolAddress((void**)&y,   g_y);

    cudaFuncSetAttribute(knn_topk_kernel,
                         cudaFuncAttributeMaxDynamicSharedMemorySize,
                         KNN_SMEM_FLOATS * (int)sizeof(float));
    cudaFuncSetAttribute(flash_kernel,
                         cudaFuncAttributeMaxDynamicSharedMemorySize,
                         FL_SMEM_FLOATS * (int)sizeof(float));

    // 1) qkv = x @ c_attn_w^T + b
    gemm128<<<dim3(24, 8), 256>>>(x, 1024, aw, 1024, qkv, 3072, 1024, ab);
    // 2) ||key_store||^2
    ksnorm_kernel<<<512, 256>>>(ks, ksn);
    // 3) fused kNN scores + top-4
    knn_topk_kernel<<<dim3(16, 16), 256, KNN_SMEM_FLOATS * sizeof(float)>>>(
        qkv, ks, ksn, idx);
    // 4) sel from last-row softmax
    sel_kernel<<<16, 256>>>(qkv, sel);
    // 5) 5-way softmax blend -> v_new
    vnew_kernel<<<2048, 256>>>(qkv, ks, vs, idx, sel, vnw);
    // 6) fused flash attention -> y (T,C)
    flash_kernel<<<dim3(8, 16), 256, FL_SMEM_FLOATS * sizeof(float)>>>(qkv, vnw, y);
    // 7) out = y @ c_proj_w^T + b
    gemm128<<<dim3(8, 8), 256>>>(y, 1024, pw, 1024, out, 1024, 1024, pb);
}

// round 6
// speedup vs baseline: 1.4896x; 1.3845x over previous
#include <cuda_runtime.h>
#include <cfloat>
#include <cstdint>

// ---------------- scratch (__device__ globals; no allocations) ----------------
__device__ float g_qkv[1024 * 3072];              // 12 MB  (T, 3C)
__device__ float g_ksnorm[16 * 8192];             // (H, M)
__device__ float g_kh[16 * 1024 * 64];            // tf32-hi of k, [h][t][d]
__device__ float g_kl[16 * 1024 * 64];            // tf32-lo of k
__device__ float g_mh[16 * 8192 * 64];            // tf32-hi of key_store
__device__ float g_ml[16 * 8192 * 64];            // tf32-lo of key_store
__device__ float g_lg[16 * 1024];                 // last-row logits
__device__ int   g_idx[16 * 1024 * 4];            // (H, T, 4)
__device__ int   g_sel[16 * 1024];                // (H, T)
__device__ float g_vnew[16 * 1024 * 64];          // (H, T, d)
__device__ float g_y[1024 * 1024];                // (T, C)

// ---------------- helpers ----------------
__device__ __forceinline__ float tf32_rna(float x) {
    uint32_t r;
    asm("cvt.rna.tf32.f32 %0, %1;" : "=r"(r) : "f"(x));
    return __uint_as_float(r);
}

__device__ __forceinline__ void mma_tf32(float& c0, float& c1, float& c2, float& c3,
                                         uint32_t a0, uint32_t a1, uint32_t a2, uint32_t a3,
                                         uint32_t b0, uint32_t b1) {
    asm volatile(
        "mma.sync.aligned.m16n8k8.row.col.f32.tf32.tf32.f32 "
        "{%0,%1,%2,%3}, {%4,%5,%6,%7}, {%8,%9}, {%0,%1,%2,%3};"
        : "+f"(c0), "+f"(c1), "+f"(c2), "+f"(c3)
        : "r"(a0), "r"(a1), "r"(a2), "r"(a3), "r"(b0), "r"(b1));
}

// ---------------- generic 128x128x16 SGEMM: C = A * B^T + bias ----------------
__global__ void gemm128(const float* __restrict__ A, int lda,
                        const float* __restrict__ B, int ldb,
                        float* __restrict__ C, int ldc,
                        int K, const float* __restrict__ aux) {
    int bx = blockIdx.x, by = blockIdx.y;
    A += (size_t)by * 128 * lda;
    B += (size_t)bx * 128 * ldb;

    __shared__ float As[16][128];
    __shared__ float Bs[16][128];

    int tid = threadIdx.x;
    int tx = tid & 15, ty = tid >> 4;
    int lr = tid >> 1, lc = (tid & 1) * 4;

    float acc[8][8];
#pragma unroll
    for (int i = 0; i < 8; i++)
#pragma unroll
        for (int j = 0; j < 8; j++) acc[i][j] = 0.f;

    const float* Ap = A + (size_t)lr * lda + lc;
    const float* Bp = B + (size_t)lr * ldb + lc;

    for (int k0 = 0; k0 < K; k0 += 16) {
        float4 a0 = *(const float4*)(Ap + k0);
        float4 a1 = *(const float4*)(Ap + k0 + 8);
        float4 b0 = *(const float4*)(Bp + k0);
        float4 b1 = *(const float4*)(Bp + k0 + 8);
        __syncthreads();
        As[lc + 0][lr] = a0.x; As[lc + 1][lr] = a0.y;
        As[lc + 2][lr] = a0.z; As[lc + 3][lr] = a0.w;
        As[lc + 8][lr] = a1.x; As[lc + 9][lr] = a1.y;
        As[lc + 10][lr] = a1.z; As[lc + 11][lr] = a1.w;
        Bs[lc + 0][lr] = b0.x; Bs[lc + 1][lr] = b0.y;
        Bs[lc + 2][lr] = b0.z; Bs[lc + 3][lr] = b0.w;
        Bs[lc + 8][lr] = b1.x; Bs[lc + 9][lr] = b1.y;
        Bs[lc + 10][lr] = b1.z; Bs[lc + 11][lr] = b1.w;
        __syncthreads();
#pragma unroll
        for (int kk = 0; kk < 16; kk++) {
            float a[8], b[8];
#pragma unroll
            for (int i = 0; i < 8; i++) a[i] = As[kk][ty * 8 + i];
#pragma unroll
            for (int j = 0; j < 8; j++) b[j] = Bs[kk][tx * 8 + j];
#pragma unroll
            for (int i = 0; i < 8; i++)
#pragma unroll
                for (int j = 0; j < 8; j++) acc[i][j] = fmaf(a[i], b[j], acc[i][j]);
        }
    }

#pragma unroll
    for (int i = 0; i < 8; i++) {
        int row = by * 128 + ty * 8 + i;
#pragma unroll
        for (int j = 0; j < 8; j++) {
            int col = bx * 128 + tx * 8 + j;
            C[(size_t)row * ldc + col] = acc[i][j] + aux[col];
        }
    }
}

// ---------------- ||key_store[h,m]||^2 (exact fp32) ----------------
__global__ void ksnorm_kernel(const float* __restrict__ ks, float* __restrict__ nrm) {
    int r = blockIdx.x * blockDim.x + threadIdx.x;
    if (r >= 16 * 8192) return;
    const float4* p = (const float4*)(ks + (size_t)r * 64);
    float s = 0.f;
#pragma unroll
    for (int i = 0; i < 16; i++) {
        float4 f = p[i];
        s += f.x * f.x + f.y * f.y + f.z * f.z + f.w * f.w;
    }
    nrm[r] = s;
}

// ---------------- tf32 hi/lo split of key_store ----------------
__global__ void split_ks_kernel(const float* __restrict__ ks,
                                float* __restrict__ hi, float* __restrict__ lo) {
    size_t i = (size_t)blockIdx.x * 1024 + threadIdx.x;  // 8.4M
    float x = ks[i];
    float h = tf32_rna(x);
    hi[i] = h;
    lo[i] = tf32_rna(x - h);
}

// ---------------- tf32 hi/lo split of k (from qkv), relayout to [h][t][d] ----------
__global__ void split_qk_kernel(const float* __restrict__ qkv,
                                float* __restrict__ hi, float* __restrict__ lo) {
    int i = blockIdx.x * 1024 + threadIdx.x;  // 1M
    int d = i & 63, t = (i >> 6) & 1023, h = i >> 16;
    float x = qkv[(size_t)t * 3072 + 1024 + h * 64 + d];
    float hf = tf32_rna(x);
    hi[i] = hf;
    lo[i] = tf32_rna(x - hf);
}

// ------------- lexicographic (score, idx) compare: stable top-k --------------
__device__ __forceinline__ bool lex_lt(float sa, int ia, float sb, int ib) {
    return sa < sb || (sa == sb && ia < ib);
}

#define TOP4_INSERT(v, m, s0, x0, s1, x1, s2, x2, s3, x3)              \
    if (lex_lt(v, m, s3, x3)) {                                        \
        if (lex_lt(v, m, s2, x2)) {                                    \
            s3 = s2; x3 = x2;                                          \
            if (lex_lt(v, m, s1, x1)) {                                \
                s2 = s1; x2 = x1;                                      \
                if (lex_lt(v, m, s0, x0)) {                            \
                    s1 = s0; x1 = x0; s0 = v; x0 = m;                  \
                } else { s1 = v; x1 = m; }                             \
            } else { s2 = v; x2 = m; }                                 \
        } else { s3 = v; x3 = m; }                                     \
    }

// ---- fused kNN scores + top-4 via tensor cores (3xTF32 compensated) ----
// Block: 256 thr (8 warps), 64 t-rows x one head; streams M=8192 in 128-col chunks.
// Warp w: row tile (w&3)*16, col half (w>>2)*64; mma m16n8k8.
#define KA 68
#define KNN_SMEM_FLOATS (64 * KA * 2 + 128 * KA * 2 + 128)

__global__ __launch_bounds__(256) void knn_mma_kernel(
    const float* __restrict__ kh, const float* __restrict__ kl,
    const float* __restrict__ mh, const float* __restrict__ ml,
    const float* __restrict__ ksn, int* __restrict__ idx_out) {
    extern __shared__ float sm[];
    float* Ah = sm;                   // [64][68]  t-major (row=t, col=k)
    float* Al = Ah + 64 * KA;
    float* Bh = Al + 64 * KA;         // [128][68] m-major (row=m, col=k)
    float* Bl = Bh + 128 * KA;
    float* Ns = Bl + 128 * KA;        // [128]

    const int tid = threadIdx.x;
    const int t0 = blockIdx.x * 64;
    const int h = blockIdx.y;
    const int w = tid >> 5, lane = tid & 31;
    const int gid = lane >> 2, qid = lane & 3;
    const int rt = (w & 3) * 16;        // row tile base
    const int ch = (w >> 2) * 64;       // col half base

    // A tiles: copy hi/lo (already tf32-valued)
    const float* Ahg = kh + ((size_t)h * 1024 + t0) * 64;
    const float* Alg = kl + ((size_t)h * 1024 + t0) * 64;
    for (int i = tid; i < 64 * 16; i += 256) {
        int r = i >> 4, c4 = (i & 15) << 2;
        *(float4*)&Ah[r * KA + c4] = *(const float4*)(Ahg + (size_t)r * 64 + c4);
        *(float4*)&Al[r * KA + c4] = *(const float4*)(Alg + (size_t)r * 64 + c4);
    }

    // per-thread running top4 for 2 rows (gid, gid+8 within the row tile)
    float S[2][4];
    int I[2][4];
#pragma unroll
    for (int r = 0; r < 2; r++)
#pragma unroll
        for (int k = 0; k < 4; k++) { S[r][k] = FLT_MAX; I[r][k] = 0x7fffffff; }

    const float* Bhg = mh + (size_t)h * 8192 * 64;
    const float* Blg = ml + (size_t)h * 8192 * 64;
    const float* Nbase = ksn + h * 8192;

    for (int chunk = 0; chunk < 64; chunk++) {
        const int m0 = chunk << 7;
        __syncthreads();  // prior compute done (covers initial A loads too)
        if (tid < 128) Ns[tid] = Nbase[m0 + tid];
        for (int i = tid; i < 128 * 16; i += 256) {
            int r = i >> 4, c4 = (i & 15) << 2;
            *(float4*)&Bh[r * KA + c4] = *(const float4*)(Bhg + (size_t)(m0 + r) * 64 + c4);
            *(float4*)&Bl[r * KA + c4] = *(const float4*)(Blg + (size_t)(m0 + r) * 64 + c4);
        }
        __syncthreads();

        float c[8][4];
#pragma unroll
        for (int nb = 0; nb < 8; nb++)
#pragma unroll
            for (int k = 0; k < 4; k++) c[nb][k] = 0.f;

#pragma unroll
        for (int ks8 = 0; ks8 < 8; ks8++) {
            const int k0 = ks8 * 8;
            uint32_t ah0 = __float_as_uint(Ah[(rt + gid) * KA + k0 + qid]);
            uint32_t ah1 = __float_as_uint(Ah[(rt + gid + 8) * KA + k0 + qid]);
            uint32_t ah2 = __float_as_uint(Ah[(rt + gid) * KA + k0 + qid + 4]);
            uint32_t ah3 = __float_as_uint(Ah[(rt + gid + 8) * KA + k0 + qid + 4]);
            uint32_t al0 = __float_as_uint(Al[(rt + gid) * KA + k0 + qid]);
            uint32_t al1 = __float_as_uint(Al[(rt + gid + 8) * KA + k0 + qid]);
            uint32_t al2 = __float_as_uint(Al[(rt + gid) * KA + k0 + qid + 4]);
            uint32_t al3 = __float_as_uint(Al[(rt + gid + 8) * KA + k0 + qid + 4]);
#pragma unroll
            for (int nb = 0; nb < 8; nb++) {
                int mrow = ch + nb * 8 + gid;
                uint32_t bh0 = __float_as_uint(Bh[mrow * KA + k0 + qid]);
                uint32_t bh1 = __float_as_uint(Bh[mrow * KA + k0 + qid + 4]);
                uint32_t bl0 = __float_as_uint(Bl[mrow * KA + k0 + qid]);
                uint32_t bl1 = __float_as_uint(Bl[mrow * KA + k0 + qid + 4]);
                mma_tf32(c[nb][0], c[nb][1], c[nb][2], c[nb][3],
                         ah0, ah1, ah2, ah3, bh0, bh1);
                mma_tf32(c[nb][0], c[nb][1], c[nb][2], c[nb][3],
                         ah0, ah1, ah2, ah3, bl0, bl1);
                mma_tf32(c[nb][0], c[nb][1], c[nb][2], c[nb][3],
                         al0, al1, al2, al3, bh0, bh1);
            }
        }

        // fold candidates: c[nb][k]: row = gid + (k>=2 ? 8 : 0), col = ch+nb*8+2*qid+(k&1)
#pragma unroll
        for (int nb = 0; nb < 8; nb++) {
#pragma unroll
            for (int k = 0; k < 4; k++) {
                int cl = ch + nb * 8 + 2 * qid + (k & 1);
                int r = k >> 1;
                float v = Ns[cl] - 2.0f * c[nb][k];
                int mg = m0 + cl;
                TOP4_INSERT(v, mg, S[r][0], I[r][0], S[r][1], I[r][1],
                            S[r][2], I[r][2], S[r][3], I[r][3]);
            }
        }
    }

    // merge: each local row has 8 contributor threads (2 warps x 4 qid)
    __syncthreads();
    float* msc = Ah;          // [64][8][4] = 2048 floats
    int* mix = (int*)Al;
    const int slot = (w >> 2) * 4 + qid;
#pragma unroll
    for (int r = 0; r < 2; r++) {
        int row = rt + gid + r * 8;
#pragma unroll
        for (int k = 0; k < 4; k++) {
            msc[(row * 8 + slot) * 4 + k] = S[r][k];
            mix[(row * 8 + slot) * 4 + k] = I[r][k];
        }
    }
    __syncthreads();
    if (tid < 64) {
        float f0 = FLT_MAX, f1 = FLT_MAX, f2 = FLT_MAX, f3 = FLT_MAX;
        int g0 = 0x7fffffff, g1 = 0x7fffffff, g2 = 0x7fffffff, g3 = 0x7fffffff;
        for (int c2 = 0; c2 < 32; c2++) {
            float v = msc[tid * 32 + c2];
            int m = mix[tid * 32 + c2];
            TOP4_INSERT(v, m, f0, g0, f1, g1, f2, g2, f3, g3);
        }
        size_t row = (size_t)h * 1024 + t0 + tid;
        idx_out[row * 4 + 0] = g0;
        idx_out[row * 4 + 1] = g1;
        idx_out[row * 4 + 2] = g2;
        idx_out[row * 4 + 3] = g3;
    }
}

// ---------------- warp-per-token last-row logits ----------------
__global__ void selA_kernel(const float* __restrict__ qkv, float* __restrict__ lg) {
    int h = blockIdx.y;
    int t = blockIdx.x * 8 + (threadIdx.x >> 5);
    int lane = threadIdx.x & 31;
    int d0 = lane * 2;
    const float* q = qkv + (size_t)1023 * 3072 + h * 64;
    const float* k = qkv + (size_t)t * 3072 + 1024 + h * 64;
    float s = q[d0] * k[d0] + q[d0 + 1] * k[d0 + 1];
#pragma unroll
    for (int o = 16; o > 0; o >>= 1) s += __shfl_xor_sync(0xffffffffu, s, o);
    if (lane == 0) lg[h * 1024 + t] = s * 0.125f;
}

// ---------------- per-head softmax of logits row -> sel ----------------
__global__ void selB_kernel(const float* __restrict__ lg, int* __restrict__ sel) {
    int h = blockIdx.x;
    int tid = threadIdx.x;
    int lane = tid & 31, warp = tid >> 5;
    __shared__ float red[8];
    __shared__ float bcast;

    float v[4];
#pragma unroll
    for (int u = 0; u < 4; u++) v[u] = lg[h * 1024 + tid + u * 256];
    float m = fmaxf(fmaxf(v[0], v[1]), fmaxf(v[2], v[3]));
#pragma unroll
    for (int o = 16; o > 0; o >>= 1) m = fmaxf(m, __shfl_xor_sync(0xffffffffu, m, o));
    if (lane == 0) red[warp] = m;
    __syncthreads();
    if (tid == 0) {
        float x = red[0];
#pragma unroll
        for (int w = 1; w < 8; w++) x = fmaxf(x, red[w]);
        bcast = x;
    }
    __syncthreads();
    m = bcast;
    float e[4], s = 0.f;
#pragma unroll
    for (int u = 0; u < 4; u++) { e[u] = __expf(v[u] - m); s += e[u]; }
#pragma unroll
    for (int o = 16; o > 0; o >>= 1) s += __shfl_xor_sync(0xffffffffu, s, o);
    if (lane == 0) red[warp] = s;
    __syncthreads();
    if (tid == 0) {
        float x = 0.f;
#pragma unroll
        for (int w = 0; w < 8; w++) x += red[w];
        bcast = x;
    }
    __syncthreads();
    float inv = 1.f / bcast;
#pragma unroll
    for (int u = 0; u < 4; u++)
        sel[h * 1024 + tid + u * 256] = (e[u] * inv >= (1.0f / 8192.0f)) ? 1 : 0;
}

// ---------------- per-token 5-way memory softmax & blend -> v_new ----------------
__device__ __forceinline__ float warp_sum(float v) {
#pragma unroll
    for (int o = 16; o > 0; o >>= 1) v += __shfl_xor_sync(0xffffffffu, v, o);
    return v;
}

__global__ void vnew_kernel(const float* __restrict__ qkv, const float* __restrict__ kstore,
                            const float* __restrict__ vstore, const int* __restrict__ idx,
                            const int* __restrict__ sel, float* __restrict__ vnew) {
    int gw = (blockIdx.x * blockDim.x + threadIdx.x) >> 5;
    int lane = threadIdx.x & 31;
    if (gw >= 16 * 1024) return;
    int h = gw >> 10, t = gw & 1023;

    const float* base = qkv + (size_t)t * 3072 + h * 64;
    int d0 = lane * 2;
    float q0 = base[d0],        q1 = base[d0 + 1];
    float k0 = base[1024 + d0], k1 = base[1024 + d0 + 1];
    float v0 = base[2048 + d0], v1 = base[2048 + d0 + 1];
    const float scale = 0.125f;

    float attf[5];
    attf[0] = warp_sum(q0 * k0 + q1 * k1) * scale;

    int ids[4];
#pragma unroll
    for (int s2 = 0; s2 < 4; s2++) ids[s2] = idx[(size_t)gw * 4 + s2];

    float fv0[4], fv1[4];
#pragma unroll
    for (int s2 = 0; s2 < 4; s2++) {
        const float* kp = kstore + ((size_t)h * 8192 + ids[s2]) * 64;
        attf[s2 + 1] = warp_sum(q0 * kp[d0] + q1 * kp[d0 + 1]) * scale;
        const float* vp = vstore + ((size_t)h * 8192 + ids[s2]) * 64;
        fv0[s2] = vp[d0]; fv1[s2] = vp[d0 + 1];
    }

    float mx = attf[0];
#pragma unroll
    for (int s2 = 1; s2 < 5; s2++) mx = fmaxf(mx, attf[s2]);
    float e[5], sum = 0.f;
#pragma unroll
    for (int s2 = 0; s2 < 5; s2++) { e[s2] = expf(attf[s2] - mx); sum += e[s2]; }
    float inv = 1.f / sum;

    float o0 = e[0] * v0, o1 = e[0] * v1;
#pragma unroll
    for (int s2 = 0; s2 < 4; s2++) { o0 += e[s2 + 1] * fv0[s2]; o1 += e[s2 + 1] * fv1[s2]; }
    o0 = o0 * inv * 0.5f + v0 * 0.5f;
    o1 = o1 * inv * 0.5f + v1 * 0.5f;

    bool sl = sel[gw] != 0;
    vnew[(size_t)gw * 64 + d0]     = sl ? o0 : v0;
    vnew[(size_t)gw * 64 + d0 + 1] = sl ? o1 : v1;
}

// ------- fused flash attention: y = softmax_causal(q k^T / 8) @ v_new -------
#define FL_QS 132
#define FL_KS 68
#define FL_VS 68
#define FL_PS 68
#define FL_SMEM_FLOATS (64 * FL_QS + 64 * FL_KS + 64 * FL_VS + 128 * FL_PS)

__global__ __launch_bounds__(256) void flash_kernel(
    const float* __restrict__ qkv, const float* __restrict__ vnew,
    float* __restrict__ y) {
    extern __shared__ float sm[];
    float* Qs = sm;
    float* Ks = Qs + 64 * FL_QS;
    float* Vs = Ks + 64 * FL_KS;
    float* Ps = Vs + 64 * FL_VS;

    const int tid = threadIdx.x;
    const int qb = blockIdx.x, h = blockIdx.y;
    const int tx = tid & 15, ty = tid >> 4;
    const int t0 = qb * 128;

    const float* Qbase = qkv + (size_t)t0 * 3072 + h * 64;
    for (int i = tid; i < 128 * 16; i += 256) {
        int r = i & 127, c4 = (i >> 7) << 2;
        float4 v = *(const float4*)(Qbase + (size_t)r * 3072 + c4);
        Qs[(c4 + 0) * FL_QS + r] = v.x * 0.125f;
        Qs[(c4 + 1) * FL_QS + r] = v.y * 0.125f;
        Qs[(c4 + 2) * FL_QS + r] = v.z * 0.125f;
        Qs[(c4 + 3) * FL_QS + r] = v.w * 0.125f;
    }

    float m[8], l[8], O[8][4];
#pragma unroll
    for (int i = 0; i < 8; i++) {
        m[i] = -FLT_MAX; l[i] = 0.f;
#pragma unroll
        for (int j = 0; j < 4; j++) O[i][j] = 0.f;
    }

    const int nj = 2 * qb + 2;
    for (int j = 0; j < nj; j++) {
        const int s0 = j * 64;
        __syncthreads();
        const float* Kbase = qkv + (size_t)s0 * 3072 + 1024 + h * 64;
        for (int i = tid; i < 64 * 16; i += 256) {
            int r = i & 63, c4 = (i >> 6) << 2;
            float4 v = *(const float4*)(Kbase + (size_t)r * 3072 + c4);
            Ks[(c4 + 0) * FL_KS + r] = v.x;
            Ks[(c4 + 1) * FL_KS + r] = v.y;
            Ks[(c4 + 2) * FL_KS + r] = v.z;
            Ks[(c4 + 3) * FL_KS + r] = v.w;
        }
        const float* Vbase = vnew + ((size_t)h * 1024 + s0) * 64;
        for (int i = tid; i < 64 * 16; i += 256) {
            int r = i >> 4, c4 = (i & 15) << 2;
            *(float4*)&Vs[r * FL_VS + c4] = *(const float4*)(Vbase + (size_t)r * 64 + c4);
        }
        __syncthreads();

        float acc[8][4];
#pragma unroll
        for (int i = 0; i < 8; i++)
#pragma unroll
            for (int jj = 0; jj < 4; jj++) acc[i][jj] = 0.f;
#pragma unroll 8
        for (int kk = 0; kk < 64; kk++) {
            float4 a0 = *(const float4*)&Qs[kk * FL_QS + ty * 8];
            float4 a1 = *(const float4*)&Qs[kk * FL_QS + ty * 8 + 4];
            float4 b  = *(const float4*)&Ks[kk * FL_KS + tx * 4];
            float av[8] = {a0.x, a0.y, a0.z, a0.w, a1.x, a1.y, a1.z, a1.w};
            float bv[4] = {b.x, b.y, b.z, b.w};
#pragma unroll
            for (int i = 0; i < 8; i++)
#pragma unroll
                for (int jj = 0; jj < 4; jj++)
                    acc[i][jj] = fmaf(av[i], bv[jj], acc[i][jj]);
        }

        const bool diag = (j >= 2 * qb);
#pragma unroll
        for (int i = 0; i < 8; i++) {
            int tg = t0 + ty * 8 + i;
            float v0 = acc[i][0], v1 = acc[i][1], v2 = acc[i][2], v3 = acc[i][3];
            if (diag) {
                int sg = s0 + tx * 4;
                if (sg + 0 > tg) v0 = -FLT_MAX;
                if (sg + 1 > tg) v1 = -FLT_MAX;
                if (sg + 2 > tg) v2 = -FLT_MAX;
                if (sg + 3 > tg) v3 = -FLT_MAX;
            }
            float rm = fmaxf(fmaxf(v0, v1), fmaxf(v2, v3));
#pragma unroll
            for (int o = 8; o > 0; o >>= 1) rm = fmaxf(rm, __shfl_xor_sync(0xffffffffu, rm, o));
            float mn = fmaxf(m[i], rm);
            float alpha = __expf(m[i] - mn);
            float p0 = __expf(v0 - mn), p1 = __expf(v1 - mn);
            float p2 = __expf(v2 - mn), p3 = __expf(v3 - mn);
            float ps = p0 + p1 + p2 + p3;
#pragma unroll
            for (int o = 8; o > 0; o >>= 1) ps += __shfl_xor_sync(0xffffffffu, ps, o);
            l[i] = l[i] * alpha + ps;
            m[i] = mn;
#pragma unroll
            for (int jj = 0; jj < 4; jj++) O[i][jj] *= alpha;
            float4 pv = {p0, p1, p2, p3};
            *(float4*)&Ps[(ty * 8 + i) * FL_PS + tx * 4] = pv;
        }
        __syncthreads();

#pragma unroll 4
        for (int s4 = 0; s4 < 16; s4++) {
            float4 vv0 = *(const float4*)&Vs[(s4 * 4 + 0) * FL_VS + tx * 4];
            float4 vv1 = *(const float4*)&Vs[(s4 * 4 + 1) * FL_VS + tx * 4];
            float4 vv2 = *(const float4*)&Vs[(s4 * 4 + 2) * FL_VS + tx * 4];
            float4 vv3 = *(const float4*)&Vs[(s4 * 4 + 3) * FL_VS + tx * 4];
#pragma unroll
            for (int i = 0; i < 8; i++) {
                float4 pp = *(const float4*)&Ps[(ty * 8 + i) * FL_PS + s4 * 4];
                O[i][0] = fmaf(pp.x, vv0.x, O[i][0]); O[i][1] = fmaf(pp.x, vv0.y, O[i][1]);
                O[i][2] = fmaf(pp.x, vv0.z, O[i][2]); O[i][3] = fmaf(pp.x, vv0.w, O[i][3]);
                O[i][0] = fmaf(pp.y, vv1.x, O[i][0]); O[i][1] = fmaf(pp.y, vv1.y, O[i][1]);
                O[i][2] = fmaf(pp.y, vv1.z, O[i][2]); O[i][3] = fmaf(pp.y, vv1.w, O[i][3]);
                O[i][0] = fmaf(pp.z, vv2.x, O[i][0]); O[i][1] = fmaf(pp.z, vv2.y, O[i][1]);
                O[i][2] = fmaf(pp.z, vv2.z, O[i][2]); O[i][3] = fmaf(pp.z, vv2.w, O[i][3]);
                O[i][0] = fmaf(pp.w, vv3.x, O[i][0]); O[i][1] = fmaf(pp.w, vv3.y, O[i][1]);
                O[i][2] = fmaf(pp.w, vv3.z, O[i][2]); O[i][3] = fmaf(pp.w, vv3.w, O[i][3]);
            }
        }
    }

#pragma unroll
    for (int i = 0; i < 8; i++) {
        float inv = 1.f / l[i];
        float4 o = {O[i][0] * inv, O[i][1] * inv, O[i][2] * inv, O[i][3] * inv};
        *(float4*)&y[(size_t)(t0 + ty * 8 + i) * 1024 + h * 64 + tx * 4] = o;
    }
}

// ---------------- launch ----------------
extern "C" void kernel_launch(void* const* d_in, const int* in_sizes, int n_in,
                              void* d_out, int out_size) {
    const float* x  = (const float*)d_in[0];
    const float* aw = (const float*)d_in[1];
    const float* ab = (const float*)d_in[2];
    const float* pw = (const float*)d_in[3];
    const float* pb = (const float*)d_in[4];
    const float* ks = (const float*)d_in[5];
    const float* vs = (const float*)d_in[6];
    float* out = (float*)d_out;

    float *qkv, *ksn, *kh, *kl, *mh, *ml, *lg, *vnw, *y;
    int *idx, *sel;
    cudaGetSymbolAddress((void**)&qkv, g_qkv);
    cudaGetSymbolAddress((void**)&ksn, g_ksnorm);
    cudaGetSymbolAddress((void**)&kh,  g_kh);
    cudaGetSymbolAddress((void**)&kl,  g_kl);
    cudaGetSymbolAddress((void**)&mh,  g_mh);
    cudaGetSymbolAddress((void**)&ml,  g_ml);
    cudaGetSymbolAddress((void**)&lg,  g_lg);
    cudaGetSymbolAddress((void**)&idx, g_idx);
    cudaGetSymbolAddress((void**)&sel, g_sel);
    cudaGetSymbolAddress((void**)&vnw, g_vnew);
    cudaGetSymbolAddress((void**)&y,   g_y);

    cudaFuncSetAttribute(knn_mma_kernel,
                         cudaFuncAttributeMaxDynamicSharedMemorySize,
                         KNN_SMEM_FLOATS * (int)sizeof(float));
    cudaFuncSetAttribute(flash_kernel,
                         cudaFuncAttributeMaxDynamicSharedMemorySize,
                         FL_SMEM_FLOATS * (int)sizeof(float));

    // 1) qkv = x @ c_attn_w^T + b  (exact fp32)
    gemm128<<<dim3(24, 8), 256>>>(x, 1024, aw, 1024, qkv, 3072, 1024, ab);
    // 2) key_store norms + tf32 hi/lo splits
    ksnorm_kernel<<<512, 256>>>(ks, ksn);
    split_ks_kernel<<<8192, 1024>>>(ks, mh, ml);
    split_qk_kernel<<<1024, 1024>>>(qkv, kh, kl);
    // 3) fused kNN scores + top-4 on tensor cores (3xTF32)
    knn_mma_kernel<<<dim3(16, 16), 256, KNN_SMEM_FLOATS * sizeof(float)>>>(
        kh, kl, mh, ml, ksn, idx);
    // 4) sel from last-row softmax (exact fp32 logits)
    selA_kernel<<<dim3(128, 16), 256>>>(qkv, lg);
    selB_kernel<<<16, 1024>>>(lg, sel);
    // 5) 5-way softmax blend -> v_new
    vnew_kernel<<<2048, 256>>>(qkv, ks, vs, idx, sel, vnw);
    // 6) fused flash attention -> y (T,C)
    flash_kernel<<<dim3(8, 16), 256, FL_SMEM_FLOATS * sizeof(float)>>>(qkv, vnw, y);
    // 7) out = y @ c_proj_w^T + b
    gemm128<<<dim3(8, 8), 256>>>(y, 1024, pw, 1024, out, 1024, 1024, pb);
}

// round 7
// speedup vs baseline: 1.5564x; 1.0449x over previous
#include <cuda_runtime.h>
#include <cfloat>
#include <cstdint>

// ---------------- scratch (__device__ globals; no allocations) ----------------
__device__ float g_qkv[1024 * 3072];              // 12 MB  (T, 3C)
__device__ float g_ksnorm[16 * 8192];             // (H, M)
__device__ float g_kh[16 * 1024 * 64];            // tf32-hi of k, [h][t][d]
__device__ float g_kl[16 * 1024 * 64];            // tf32-lo of k
__device__ float g_mh[16 * 8192 * 64];            // tf32-hi of key_store
__device__ float g_ml[16 * 8192 * 64];            // tf32-lo of key_store
__device__ float g_xh[1024 * 1024];               // tf32-hi of x
__device__ float g_xl[1024 * 1024];
__device__ float g_awh[3072 * 1024];              // tf32-hi of c_attn_w
__device__ float g_awl[3072 * 1024];
__device__ float g_pwh[1024 * 1024];              // tf32-hi of c_proj_w
__device__ float g_pwl[1024 * 1024];
__device__ float g_yh[1024 * 1024];               // tf32-hi of y
__device__ float g_yl[1024 * 1024];
__device__ float g_lg[16 * 1024];                 // last-row logits
__device__ int   g_idx[16 * 1024 * 4];            // (H, T, 4)
__device__ int   g_sel[16 * 1024];                // (H, T)
__device__ float g_vnew[16 * 1024 * 64];          // (H, T, d)
__device__ float g_y[1024 * 1024];                // (T, C)

// ---------------- helpers ----------------
__device__ __forceinline__ float tf32_rna(float x) {
    uint32_t r;
    asm("cvt.rna.tf32.f32 %0, %1;" : "=r"(r) : "f"(x));
    return __uint_as_float(r);
}

__device__ __forceinline__ void mma_tf32(float& c0, float& c1, float& c2, float& c3,
                                         uint32_t a0, uint32_t a1, uint32_t a2, uint32_t a3,
                                         uint32_t b0, uint32_t b1) {
    asm volatile(
        "mma.sync.aligned.m16n8k8.row.col.f32.tf32.tf32.f32 "
        "{%0,%1,%2,%3}, {%4,%5,%6,%7}, {%8,%9}, {%0,%1,%2,%3};"
        : "+f"(c0), "+f"(c1), "+f"(c2), "+f"(c3)
        : "r"(a0), "r"(a1), "r"(a2), "r"(a3), "r"(b0), "r"(b1));
}

// ---------------- generic contiguous tf32 hi/lo split ----------------
__global__ void split_kernel(const float* __restrict__ src,
                             float* __restrict__ hi, float* __restrict__ lo) {
    size_t i = (size_t)blockIdx.x * 1024 + threadIdx.x;
    float x = src[i];
    float h = tf32_rna(x);
    hi[i] = h;
    lo[i] = tf32_rna(x - h);
}

// ---------------- tf32 hi/lo split of k (from qkv), relayout to [h][t][d] ----------
__global__ void split_qk_kernel(const float* __restrict__ qkv,
                                float* __restrict__ hi, float* __restrict__ lo) {
    int i = blockIdx.x * 1024 + threadIdx.x;  // 1M
    int d = i & 63, t = (i >> 6) & 1023, h = i >> 16;
    float x = qkv[(size_t)t * 3072 + 1024 + h * 64 + d];
    float hf = tf32_rna(x);
    hi[i] = hf;
    lo[i] = tf32_rna(x - hf);
}

// ---- generic 3xTF32 mma GEMM: C = A * B^T + bias ----
// A: (M,K) rm (hi/lo), B: (N,K) rm (hi/lo). Block: 64 rows x 128 cols, 256 thr.
// grid = (N/128, M/64). Same fragment mapping as knn_mma_kernel (validated).
#define KA 68
#define GM_SMEM_FLOATS (64 * KA * 2 + 128 * KA * 2)

__global__ __launch_bounds__(256) void mma_gemm_kernel(
    const float* __restrict__ Ahg, const float* __restrict__ Alg,
    const float* __restrict__ Bhg, const float* __restrict__ Blg,
    float* __restrict__ C, int ldc, int K, const float* __restrict__ bias) {
    extern __shared__ float sm[];
    float* Ah = sm;                   // [64][68]
    float* Al = Ah + 64 * KA;
    float* Bh = Al + 64 * KA;         // [128][68]
    float* Bl = Bh + 128 * KA;

    const int tid = threadIdx.x;
    const int bx = blockIdx.x, by = blockIdx.y;
    const int w = tid >> 5, lane = tid & 31;
    const int gid = lane >> 2, qid = lane & 3;
    const int rt = (w & 3) * 16;
    const int ch = (w >> 2) * 64;

    const float* Ahb = Ahg + (size_t)(by * 64) * K;
    const float* Alb = Alg + (size_t)(by * 64) * K;
    const float* Bhb = Bhg + (size_t)(bx * 128) * K;
    const float* Blb = Blg + (size_t)(bx * 128) * K;

    float c[8][4];
#pragma unroll
    for (int nb = 0; nb < 8; nb++)
#pragma unroll
        for (int k = 0; k < 4; k++) c[nb][k] = 0.f;

    for (int k0 = 0; k0 < K; k0 += 64) {
        __syncthreads();
        for (int i = tid; i < 64 * 16; i += 256) {
            int r = i >> 4, c4 = (i & 15) << 2;
            *(float4*)&Ah[r * KA + c4] = *(const float4*)(Ahb + (size_t)r * K + k0 + c4);
            *(float4*)&Al[r * KA + c4] = *(const float4*)(Alb + (size_t)r * K + k0 + c4);
        }
        for (int i = tid; i < 128 * 16; i += 256) {
            int r = i >> 4, c4 = (i & 15) << 2;
            *(float4*)&Bh[r * KA + c4] = *(const float4*)(Bhb + (size_t)r * K + k0 + c4);
            *(float4*)&Bl[r * KA + c4] = *(const float4*)(Blb + (size_t)r * K + k0 + c4);
        }
        __syncthreads();

#pragma unroll
        for (int ks8 = 0; ks8 < 8; ks8++) {
            const int kk = ks8 * 8;
            uint32_t ah0 = __float_as_uint(Ah[(rt + gid) * KA + kk + qid]);
            uint32_t ah1 = __float_as_uint(Ah[(rt + gid + 8) * KA + kk + qid]);
            uint32_t ah2 = __float_as_uint(Ah[(rt + gid) * KA + kk + qid + 4]);
            uint32_t ah3 = __float_as_uint(Ah[(rt + gid + 8) * KA + kk + qid + 4]);
            uint32_t al0 = __float_as_uint(Al[(rt + gid) * KA + kk + qid]);
            uint32_t al1 = __float_as_uint(Al[(rt + gid + 8) * KA + kk + qid]);
            uint32_t al2 = __float_as_uint(Al[(rt + gid) * KA + kk + qid + 4]);
            uint32_t al3 = __float_as_uint(Al[(rt + gid + 8) * KA + kk + qid + 4]);
#pragma unroll
            for (int nb = 0; nb < 8; nb++) {
                int mrow = ch + nb * 8 + gid;
                uint32_t bh0 = __float_as_uint(Bh[mrow * KA + kk + qid]);
                uint32_t bh1 = __float_as_uint(Bh[mrow * KA + kk + qid + 4]);
                uint32_t bl0 = __float_as_uint(Bl[mrow * KA + kk + qid]);
                uint32_t bl1 = __float_as_uint(Bl[mrow * KA + kk + qid + 4]);
                mma_tf32(c[nb][0], c[nb][1], c[nb][2], c[nb][3],
                         ah0, ah1, ah2, ah3, bh0, bh1);
                mma_tf32(c[nb][0], c[nb][1], c[nb][2], c[nb][3],
                         ah0, ah1, ah2, ah3, bl0, bl1);
                mma_tf32(c[nb][0], c[nb][1], c[nb][2], c[nb][3],
                         al0, al1, al2, al3, bh0, bh1);
            }
        }
    }

#pragma unroll
    for (int nb = 0; nb < 8; nb++) {
#pragma unroll
        for (int k = 0; k < 4; k++) {
            int row = by * 64 + rt + gid + (k >> 1) * 8;
            int col = bx * 128 + ch + nb * 8 + 2 * qid + (k & 1);
            C[(size_t)row * ldc + col] = c[nb][k] + bias[col];
        }
    }
}

// ---------------- ||key_store[h,m]||^2 (exact fp32) ----------------
__global__ void ksnorm_kernel(const float* __restrict__ ks, float* __restrict__ nrm) {
    int r = blockIdx.x * blockDim.x + threadIdx.x;
    if (r >= 16 * 8192) return;
    const float4* p = (const float4*)(ks + (size_t)r * 64);
    float s = 0.f;
#pragma unroll
    for (int i = 0; i < 16; i++) {
        float4 f = p[i];
        s += f.x * f.x + f.y * f.y + f.z * f.z + f.w * f.w;
    }
    nrm[r] = s;
}

// ------------- lexicographic (score, idx) compare: stable top-k --------------
__device__ __forceinline__ bool lex_lt(float sa, int ia, float sb, int ib) {
    return sa < sb || (sa == sb && ia < ib);
}

#define TOP4_INSERT(v, m, s0, x0, s1, x1, s2, x2, s3, x3)              \
    if (lex_lt(v, m, s3, x3)) {                                        \
        if (lex_lt(v, m, s2, x2)) {                                    \
            s3 = s2; x3 = x2;                                          \
            if (lex_lt(v, m, s1, x1)) {                                \
                s2 = s1; x2 = x1;                                      \
                if (lex_lt(v, m, s0, x0)) {                            \
                    s1 = s0; x1 = x0; s0 = v; x0 = m;                  \
                } else { s1 = v; x1 = m; }                             \
            } else { s2 = v; x2 = m; }                                 \
        } else { s3 = v; x3 = m; }                                     \
    }

// ---- fused kNN scores + top-4 via tensor cores (3xTF32 compensated) ----
#define KNN_SMEM_FLOATS (64 * KA * 2 + 128 * KA * 2 + 128)

__global__ __launch_bounds__(256) void knn_mma_kernel(
    const float* __restrict__ kh, const float* __restrict__ kl,
    const float* __restrict__ mh, const float* __restrict__ ml,
    const float* __restrict__ ksn, int* __restrict__ idx_out) {
    extern __shared__ float sm[];
    float* Ah = sm;                   // [64][68]  t-major
    float* Al = Ah + 64 * KA;
    float* Bh = Al + 64 * KA;         // [128][68] m-major
    float* Bl = Bh + 128 * KA;
    float* Ns = Bl + 128 * KA;        // [128]

    const int tid = threadIdx.x;
    const int t0 = blockIdx.x * 64;
    const int h = blockIdx.y;
    const int w = tid >> 5, lane = tid & 31;
    const int gid = lane >> 2, qid = lane & 3;
    const int rt = (w & 3) * 16;
    const int ch = (w >> 2) * 64;

    const float* Ahg = kh + ((size_t)h * 1024 + t0) * 64;
    const float* Alg = kl + ((size_t)h * 1024 + t0) * 64;
    for (int i = tid; i < 64 * 16; i += 256) {
        int r = i >> 4, c4 = (i & 15) << 2;
        *(float4*)&Ah[r * KA + c4] = *(const float4*)(Ahg + (size_t)r * 64 + c4);
        *(float4*)&Al[r * KA + c4] = *(const float4*)(Alg + (size_t)r * 64 + c4);
    }

    float S[2][4];
    int I[2][4];
#pragma unroll
    for (int r = 0; r < 2; r++)
#pragma unroll
        for (int k = 0; k < 4; k++) { S[r][k] = FLT_MAX; I[r][k] = 0x7fffffff; }

    const float* Bhg = mh + (size_t)h * 8192 * 64;
    const float* Blg = ml + (size_t)h * 8192 * 64;
    const float* Nbase = ksn + h * 8192;

    for (int chunk = 0; chunk < 64; chunk++) {
        const int m0 = chunk << 7;
        __syncthreads();
        if (tid < 128) Ns[tid] = Nbase[m0 + tid];
        for (int i = tid; i < 128 * 16; i += 256) {
            int r = i >> 4, c4 = (i & 15) << 2;
            *(float4*)&Bh[r * KA + c4] = *(const float4*)(Bhg + (size_t)(m0 + r) * 64 + c4);
            *(float4*)&Bl[r * KA + c4] = *(const float4*)(Blg + (size_t)(m0 + r) * 64 + c4);
        }
        __syncthreads();

        float c[8][4];
#pragma unroll
        for (int nb = 0; nb < 8; nb++)
#pragma unroll
            for (int k = 0; k < 4; k++) c[nb][k] = 0.f;

#pragma unroll
        for (int ks8 = 0; ks8 < 8; ks8++) {
            const int k0 = ks8 * 8;
            uint32_t ah0 = __float_as_uint(Ah[(rt + gid) * KA + k0 + qid]);
            uint32_t ah1 = __float_as_uint(Ah[(rt + gid + 8) * KA + k0 + qid]);
            uint32_t ah2 = __float_as_uint(Ah[(rt + gid) * KA + k0 + qid + 4]);
            uint32_t ah3 = __float_as_uint(Ah[(rt + gid + 8) * KA + k0 + qid + 4]);
            uint32_t al0 = __float_as_uint(Al[(rt + gid) * KA + k0 + qid]);
            uint32_t al1 = __float_as_uint(Al[(rt + gid + 8) * KA + k0 + qid]);
            uint32_t al2 = __float_as_uint(Al[(rt + gid) * KA + k0 + qid + 4]);
            uint32_t al3 = __float_as_uint(Al[(rt + gid + 8) * KA + k0 + qid + 4]);
#pragma unroll
            for (int nb = 0; nb < 8; nb++) {
                int mrow = ch + nb * 8 + gid;
                uint32_t bh0 = __float_as_uint(Bh[mrow * KA + k0 + qid]);
                uint32_t bh1 = __float_as_uint(Bh[mrow * KA + k0 + qid + 4]);
                uint32_t bl0 = __float_as_uint(Bl[mrow * KA + k0 + qid]);
                uint32_t bl1 = __float_as_uint(Bl[mrow * KA + k0 + qid + 4]);
                mma_tf32(c[nb][0], c[nb][1], c[nb][2], c[nb][3],
                         ah0, ah1, ah2, ah3, bh0, bh1);
                mma_tf32(c[nb][0], c[nb][1], c[nb][2], c[nb][3],
                         ah0, ah1, ah2, ah3, bl0, bl1);
                mma_tf32(c[nb][0], c[nb][1], c[nb][2], c[nb][3],
                         al0, al1, al2, al3, bh0, bh1);
            }
        }

#pragma unroll
        for (int nb = 0; nb < 8; nb++) {
#pragma unroll
            for (int k = 0; k < 4; k++) {
                int cl = ch + nb * 8 + 2 * qid + (k & 1);
                int r = k >> 1;
                float v = Ns[cl] - 2.0f * c[nb][k];
                int mg = m0 + cl;
                TOP4_INSERT(v, mg, S[r][0], I[r][0], S[r][1], I[r][1],
                            S[r][2], I[r][2], S[r][3], I[r][3]);
            }
        }
    }

    __syncthreads();
    float* msc = Ah;
    int* mix = (int*)Al;
    const int slot = (w >> 2) * 4 + qid;
#pragma unroll
    for (int r = 0; r < 2; r++) {
        int row = rt + gid + r * 8;
#pragma unroll
        for (int k = 0; k < 4; k++) {
            msc[(row * 8 + slot) * 4 + k] = S[r][k];
            mix[(row * 8 + slot) * 4 + k] = I[r][k];
        }
    }
    __syncthreads();
    if (tid < 64) {
        float f0 = FLT_MAX, f1 = FLT_MAX, f2 = FLT_MAX, f3 = FLT_MAX;
        int g0 = 0x7fffffff, g1 = 0x7fffffff, g2 = 0x7fffffff, g3 = 0x7fffffff;
        for (int c2 = 0; c2 < 32; c2++) {
            float v = msc[tid * 32 + c2];
            int m = mix[tid * 32 + c2];
            TOP4_INSERT(v, m, f0, g0, f1, g1, f2, g2, f3, g3);
        }
        size_t row = (size_t)h * 1024 + t0 + tid;
        idx_out[row * 4 + 0] = g0;
        idx_out[row * 4 + 1] = g1;
        idx_out[row * 4 + 2] = g2;
        idx_out[row * 4 + 3] = g3;
    }
}

// ---------------- warp-per-token last-row logits ----------------
__global__ void selA_kernel(const float* __restrict__ qkv, float* __restrict__ lg) {
    int h = blockIdx.y;
    int t = blockIdx.x * 8 + (threadIdx.x >> 5);
    int lane = threadIdx.x & 31;
    int d0 = lane * 2;
    const float* q = qkv + (size_t)1023 * 3072 + h * 64;
    const float* k = qkv + (size_t)t * 3072 + 1024 + h * 64;
    float s = q[d0] * k[d0] + q[d0 + 1] * k[d0 + 1];
#pragma unroll
    for (int o = 16; o > 0; o >>= 1) s += __shfl_xor_sync(0xffffffffu, s, o);
    if (lane == 0) lg[h * 1024 + t] = s * 0.125f;
}

// ---------------- per-head softmax of logits row -> sel ----------------
__global__ void selB_kernel(const float* __restrict__ lg, int* __restrict__ sel) {
    int h = blockIdx.x;
    int tid = threadIdx.x;
    int lane = tid & 31, warp = tid >> 5;
    __shared__ float red[8];
    __shared__ float bcast;

    float v[4];
#pragma unroll
    for (int u = 0; u < 4; u++) v[u] = lg[h * 1024 + tid + u * 256];
    float m = fmaxf(fmaxf(v[0], v[1]), fmaxf(v[2], v[3]));
#pragma unroll
    for (int o = 16; o > 0; o >>= 1) m = fmaxf(m, __shfl_xor_sync(0xffffffffu, m, o));
    if (lane == 0) red[warp] = m;
    __syncthreads();
    if (tid == 0) {
        float x = red[0];
#pragma unroll
        for (int w = 1; w < 8; w++) x = fmaxf(x, red[w]);
        bcast = x;
    }
    __syncthreads();
    m = bcast;
    float e[4], s = 0.f;
#pragma unroll
    for (int u = 0; u < 4; u++) { e[u] = __expf(v[u] - m); s += e[u]; }
#pragma unroll
    for (int o = 16; o > 0; o >>= 1) s += __shfl_xor_sync(0xffffffffu, s, o);
    if (lane == 0) red[warp] = s;
    __syncthreads();
    if (tid == 0) {
        float x = 0.f;
#pragma unroll
        for (int w = 0; w < 8; w++) x += red[w];
        bcast = x;
    }
    __syncthreads();
    float inv = 1.f / bcast;
#pragma unroll
    for (int u = 0; u < 4; u++)
        sel[h * 1024 + tid + u * 256] = (e[u] * inv >= (1.0f / 8192.0f)) ? 1 : 0;
}

// ---------------- per-token 5-way memory softmax & blend -> v_new ----------------
__device__ __forceinline__ float warp_sum(float v) {
#pragma unroll
    for (int o = 16; o > 0; o >>= 1) v += __shfl_xor_sync(0xffffffffu, v, o);
    return v;
}

__global__ void vnew_kernel(const float* __restrict__ qkv, const float* __restrict__ kstore,
                            const float* __restrict__ vstore, const int* __restrict__ idx,
                            const int* __restrict__ sel, float* __restrict__ vnew) {
    int gw = (blockIdx.x * blockDim.x + threadIdx.x) >> 5;
    int lane = threadIdx.x & 31;
    if (gw >= 16 * 1024) return;
    int h = gw >> 10, t = gw & 1023;

    const float* base = qkv + (size_t)t * 3072 + h * 64;
    int d0 = lane * 2;
    float q0 = base[d0],        q1 = base[d0 + 1];
    float k0 = base[1024 + d0], k1 = base[1024 + d0 + 1];
    float v0 = base[2048 + d0], v1 = base[2048 + d0 + 1];
    const float scale = 0.125f;

    float attf[5];
    attf[0] = warp_sum(q0 * k0 + q1 * k1) * scale;

    int ids[4];
#pragma unroll
    for (int s2 = 0; s2 < 4; s2++) ids[s2] = idx[(size_t)gw * 4 + s2];

    float fv0[4], fv1[4];
#pragma unroll
    for (int s2 = 0; s2 < 4; s2++) {
        const float* kp = kstore + ((size_t)h * 8192 + ids[s2]) * 64;
        attf[s2 + 1] = warp_sum(q0 * kp[d0] + q1 * kp[d0 + 1]) * scale;
        const float* vp = vstore + ((size_t)h * 8192 + ids[s2]) * 64;
        fv0[s2] = vp[d0]; fv1[s2] = vp[d0 + 1];
    }

    float mx = attf[0];
#pragma unroll
    for (int s2 = 1; s2 < 5; s2++) mx = fmaxf(mx, attf[s2]);
    float e[5], sum = 0.f;
#pragma unroll
    for (int s2 = 0; s2 < 5; s2++) { e[s2] = expf(attf[s2] - mx); sum += e[s2]; }
    float inv = 1.f / sum;

    float o0 = e[0] * v0, o1 = e[0] * v1;
#pragma unroll
    for (int s2 = 0; s2 < 4; s2++) { o0 += e[s2 + 1] * fv0[s2]; o1 += e[s2 + 1] * fv1[s2]; }
    o0 = o0 * inv * 0.5f + v0 * 0.5f;
    o1 = o1 * inv * 0.5f + v1 * 0.5f;

    bool sl = sel[gw] != 0;
    vnew[(size_t)gw * 64 + d0]     = sl ? o0 : v0;
    vnew[(size_t)gw * 64 + d0 + 1] = sl ? o1 : v1;
}

// ------- fused flash attention: y = softmax_causal(q k^T / 8) @ v_new -------
#define FL_QS 132
#define FL_KS 68
#define FL_VS 68
#define FL_PS 68
#define FL_SMEM_FLOATS (64 * FL_QS + 64 * FL_KS + 64 * FL_VS + 128 * FL_PS)

__global__ __launch_bounds__(256) void flash_kernel(
    const float* __restrict__ qkv, const float* __restrict__ vnew,
    float* __restrict__ y) {
    extern __shared__ float sm[];
    float* Qs = sm;
    float* Ks = Qs + 64 * FL_QS;
    float* Vs = Ks + 64 * FL_KS;
    float* Ps = Vs + 64 * FL_VS;

    const int tid = threadIdx.x;
    const int qb = blockIdx.x, h = blockIdx.y;
    const int tx = tid & 15, ty = tid >> 4;
    const int t0 = qb * 128;

    const float* Qbase = qkv + (size_t)t0 * 3072 + h * 64;
    for (int i = tid; i < 128 * 16; i += 256) {
        int r = i & 127, c4 = (i >> 7) << 2;
        float4 v = *(const float4*)(Qbase + (size_t)r * 3072 + c4);
        Qs[(c4 + 0) * FL_QS + r] = v.x * 0.125f;
        Qs[(c4 + 1) * FL_QS + r] = v.y * 0.125f;
        Qs[(c4 + 2) * FL_QS + r] = v.z * 0.125f;
        Qs[(c4 + 3) * FL_QS + r] = v.w * 0.125f;
    }

    float m[8], l[8], O[8][4];
#pragma unroll
    for (int i = 0; i < 8; i++) {
        m[i] = -FLT_MAX; l[i] = 0.f;
#pragma unroll
        for (int j = 0; j < 4; j++) O[i][j] = 0.f;
    }

    const int nj = 2 * qb + 2;
    for (int j = 0; j < nj; j++) {
        const int s0 = j * 64;
        __syncthreads();
        const float* Kbase = qkv + (size_t)s0 * 3072 + 1024 + h * 64;
        for (int i = tid; i < 64 * 16; i += 256) {
            int r = i & 63, c4 = (i >> 6) << 2;
            float4 v = *(const float4*)(Kbase + (size_t)r * 3072 + c4);
            Ks[(c4 + 0) * FL_KS + r] = v.x;
            Ks[(c4 + 1) * FL_KS + r] = v.y;
            Ks[(c4 + 2) * FL_KS + r] = v.z;
            Ks[(c4 + 3) * FL_KS + r] = v.w;
        }
        const float* Vbase = vnew + ((size_t)h * 1024 + s0) * 64;
        for (int i = tid; i < 64 * 16; i += 256) {
            int r = i >> 4, c4 = (i & 15) << 2;
            *(float4*)&Vs[r * FL_VS + c4] = *(const float4*)(Vbase + (size_t)r * 64 + c4);
        }
        __syncthreads();

        float acc[8][4];
#pragma unroll
        for (int i = 0; i < 8; i++)
#pragma unroll
            for (int jj = 0; jj < 4; jj++) acc[i][jj] = 0.f;
#pragma unroll 8
        for (int kk = 0; kk < 64; kk++) {
            float4 a0 = *(const float4*)&Qs[kk * FL_QS + ty * 8];
            float4 a1 = *(const float4*)&Qs[kk * FL_QS + ty * 8 + 4];
            float4 b  = *(const float4*)&Ks[kk * FL_KS + tx * 4];
            float av[8] = {a0.x, a0.y, a0.z, a0.w, a1.x, a1.y, a1.z, a1.w};
            float bv[4] = {b.x, b.y, b.z, b.w};
#pragma unroll
            for (int i = 0; i < 8; i++)
#pragma unroll
                for (int jj = 0; jj < 4; jj++)
                    acc[i][jj] = fmaf(av[i], bv[jj], acc[i][jj]);
        }

        const bool diag = (j >= 2 * qb);
#pragma unroll
        for (int i = 0; i < 8; i++) {
            int tg = t0 + ty * 8 + i;
            float v0 = acc[i][0], v1 = acc[i][1], v2 = acc[i][2], v3 = acc[i][3];
            if (diag) {
                int sg = s0 + tx * 4;
                if (sg + 0 > tg) v0 = -FLT_MAX;
                if (sg + 1 > tg) v1 = -FLT_MAX;
                if (sg + 2 > tg) v2 = -FLT_MAX;
                if (sg + 3 > tg) v3 = -FLT_MAX;
            }
            float rm = fmaxf(fmaxf(v0, v1), fmaxf(v2, v3));
#pragma unroll
            for (int o = 8; o > 0; o >>= 1) rm = fmaxf(rm, __shfl_xor_sync(0xffffffffu, rm, o));
            float mn = fmaxf(m[i], rm);
            float alpha = __expf(m[i] - mn);
            float p0 = __expf(v0 - mn), p1 = __expf(v1 - mn);
            float p2 = __expf(v2 - mn), p3 = __expf(v3 - mn);
            float ps = p0 + p1 + p2 + p3;
#pragma unroll
            for (int o = 8; o > 0; o >>= 1) ps += __shfl_xor_sync(0xffffffffu, ps, o);
            l[i] = l[i] * alpha + ps;
            m[i] = mn;
#pragma unroll
            for (int jj = 0; jj < 4; jj++) O[i][jj] *= alpha;
            float4 pv = {p0, p1, p2, p3};
            *(float4*)&Ps[(ty * 8 + i) * FL_PS + tx * 4] = pv;
        }
        __syncthreads();

#pragma unroll 4
        for (int s4 = 0; s4 < 16; s4++) {
            float4 vv0 = *(const float4*)&Vs[(s4 * 4 + 0) * FL_VS + tx * 4];
            float4 vv1 = *(const float4*)&Vs[(s4 * 4 + 1) * FL_VS + tx * 4];
            float4 vv2 = *(const float4*)&Vs[(s4 * 4 + 2) * FL_VS + tx * 4];
            float4 vv3 = *(const float4*)&Vs[(s4 * 4 + 3) * FL_VS + tx * 4];
#pragma unroll
            for (int i = 0; i < 8; i++) {
                float4 pp = *(const float4*)&Ps[(ty * 8 + i) * FL_PS + s4 * 4];
                O[i][0] = fmaf(pp.x, vv0.x, O[i][0]); O[i][1] = fmaf(pp.x, vv0.y, O[i][1]);
                O[i][2] = fmaf(pp.x, vv0.z, O[i][2]); O[i][3] = fmaf(pp.x, vv0.w, O[i][3]);
                O[i][0] = fmaf(pp.y, vv1.x, O[i][0]); O[i][1] = fmaf(pp.y, vv1.y, O[i][1]);
                O[i][2] = fmaf(pp.y, vv1.z, O[i][2]); O[i][3] = fmaf(pp.y, vv1.w, O[i][3]);
                O[i][0] = fmaf(pp.z, vv2.x, O[i][0]); O[i][1] = fmaf(pp.z, vv2.y, O[i][1]);
                O[i][2] = fmaf(pp.z, vv2.z, O[i][2]); O[i][3] = fmaf(pp.z, vv2.w, O[i][3]);
                O[i][0] = fmaf(pp.w, vv3.x, O[i][0]); O[i][1] = fmaf(pp.w, vv3.y, O[i][1]);
                O[i][2] = fmaf(pp.w, vv3.z, O[i][2]); O[i][3] = fmaf(pp.w, vv3.w, O[i][3]);
            }
        }
    }

#pragma unroll
    for (int i = 0; i < 8; i++) {
        float inv = 1.f / l[i];
        float4 o = {O[i][0] * inv, O[i][1] * inv, O[i][2] * inv, O[i][3] * inv};
        *(float4*)&y[(size_t)(t0 + ty * 8 + i) * 1024 + h * 64 + tx * 4] = o;
    }
}

// ---------------- launch ----------------
extern "C" void kernel_launch(void* const* d_in, const int* in_sizes, int n_in,
                              void* d_out, int out_size) {
    const float* x  = (const float*)d_in[0];
    const float* aw = (const float*)d_in[1];
    const float* ab = (const float*)d_in[2];
    const float* pw = (const float*)d_in[3];
    const float* pb = (const float*)d_in[4];
    const float* ks = (const float*)d_in[5];
    const float* vs = (const float*)d_in[6];
    float* out = (float*)d_out;

    float *qkv, *ksn, *kh, *kl, *mh, *ml, *lg, *vnw, *y;
    float *xh, *xl, *awh, *awl, *pwh, *pwl, *yh, *yl;
    int *idx, *sel;
    cudaGetSymbolAddress((void**)&qkv, g_qkv);
    cudaGetSymbolAddress((void**)&ksn, g_ksnorm);
    cudaGetSymbolAddress((void**)&kh,  g_kh);
    cudaGetSymbolAddress((void**)&kl,  g_kl);
    cudaGetSymbolAddress((void**)&mh,  g_mh);
    cudaGetSymbolAddress((void**)&ml,  g_ml);
    cudaGetSymbolAddress((void**)&xh,  g_xh);
    cudaGetSymbolAddress((void**)&xl,  g_xl);
    cudaGetSymbolAddress((void**)&awh, g_awh);
    cudaGetSymbolAddress((void**)&awl, g_awl);
    cudaGetSymbolAddress((void**)&pwh, g_pwh);
    cudaGetSymbolAddress((void**)&pwl, g_pwl);
    cudaGetSymbolAddress((void**)&yh,  g_yh);
    cudaGetSymbolAddress((void**)&yl,  g_yl);
    cudaGetSymbolAddress((void**)&lg,  g_lg);
    cudaGetSymbolAddress((void**)&idx, g_idx);
    cudaGetSymbolAddress((void**)&sel, g_sel);
    cudaGetSymbolAddress((void**)&vnw, g_vnew);
    cudaGetSymbolAddress((void**)&y,   g_y);

    cudaFuncSetAttribute(knn_mma_kernel,
                         cudaFuncAttributeMaxDynamicSharedMemorySize,
                         KNN_SMEM_FLOATS * (int)sizeof(float));
    cudaFuncSetAttribute(mma_gemm_kernel,
                         cudaFuncAttributeMaxDynamicSharedMemorySize,
                         GM_SMEM_FLOATS * (int)sizeof(float));
    cudaFuncSetAttribute(flash_kernel,
                         cudaFuncAttributeMaxDynamicSharedMemorySize,
                         FL_SMEM_FLOATS * (int)sizeof(float));

    // 0) tf32 splits of inputs
    split_kernel<<<1024, 1024>>>(x,  xh,  xl);    // 1M
    split_kernel<<<3072, 1024>>>(aw, awh, awl);   // 3M
    split_kernel<<<1024, 1024>>>(pw, pwh, pwl);   // 1M
    split_kernel<<<8192, 1024>>>(ks, mh,  ml);    // 8.4M
    // 1) qkv = x @ c_attn_w^T + b   (3xTF32 mma)
    mma_gemm_kernel<<<dim3(24, 16), 256, GM_SMEM_FLOATS * sizeof(float)>>>(
        xh, xl, awh, awl, qkv, 3072, 1024, ab);
    // 2) key_store norms + k split/relayout
    ksnorm_kernel<<<512, 256>>>(ks, ksn);
    split_qk_kernel<<<1024, 1024>>>(qkv, kh, kl);
    // 3) fused kNN scores + top-4 on tensor cores (3xTF32)
    knn_mma_kernel<<<dim3(16, 16), 256, KNN_SMEM_FLOATS * sizeof(float)>>>(
        kh, kl, mh, ml, ksn, idx);
    // 4) sel from last-row softmax
    selA_kernel<<<dim3(128, 16), 256>>>(qkv, lg);
    selB_kernel<<<16, 1024>>>(lg, sel);
    // 5) 5-way softmax blend -> v_new
    vnew_kernel<<<2048, 256>>>(qkv, ks, vs, idx, sel, vnw);
    // 6) fused flash attention -> y (T,C)
    flash_kernel<<<dim3(8, 16), 256, FL_SMEM_FLOATS * sizeof(float)>>>(qkv, vnw, y);
    // 7) out = y @ c_proj_w^T + b   (3xTF32 mma)
    split_kernel<<<1024, 1024>>>(y, yh, yl);
    mma_gemm_kernel<<<dim3(8, 16), 256, GM_SMEM_FLOATS * sizeof(float)>>>(
        yh, yl, pwh, pwl, out, 1024, 1024, pb);
}

// round 8
// speedup vs baseline: 1.7215x; 1.1061x over previous
#include <cuda_runtime.h>
#include <cuda_bf16.h>
#include <cfloat>
#include <cstdint>

// ---------------- scratch (__device__ globals; no allocations) ----------------
__device__ float g_qkv[1024 * 3072];              // 12 MB  (T, 3C)
__device__ float g_ksnorm[16 * 8192];             // (H, M)
__device__ __nv_bfloat16 g_kh[16 * 1024 * 64];    // bf16-hi of k, [h][t][d]
__device__ __nv_bfloat16 g_kl[16 * 1024 * 64];    // bf16-lo of k
__device__ __nv_bfloat16 g_mh[16 * 8192 * 64];    // bf16-hi of key_store
__device__ __nv_bfloat16 g_ml[16 * 8192 * 64];    // bf16-lo of key_store
__device__ float g_xh[1024 * 1024];               // tf32-hi of x
__device__ float g_xl[1024 * 1024];
__device__ float g_awh[3072 * 1024];              // tf32-hi of c_attn_w
__device__ float g_awl[3072 * 1024];
__device__ float g_pwh[1024 * 1024];              // tf32-hi of c_proj_w
__device__ float g_pwl[1024 * 1024];
__device__ float g_yh[1024 * 1024];               // tf32-hi of y
__device__ float g_yl[1024 * 1024];
__device__ float g_lg[16 * 1024];                 // last-row logits
__device__ int   g_idx[16 * 1024 * 4];            // (H, T, 4)
__device__ int   g_sel[16 * 1024];                // (H, T)
__device__ float g_vnew[16 * 1024 * 64];          // (H, T, d)
__device__ float g_y[1024 * 1024];                // (T, C)

// ---------------- helpers ----------------
__device__ __forceinline__ float tf32_rna(float x) {
    uint32_t r;
    asm("cvt.rna.tf32.f32 %0, %1;" : "=r"(r) : "f"(x));
    return __uint_as_float(r);
}

__device__ __forceinline__ void mma_tf32(float& c0, float& c1, float& c2, float& c3,
                                         uint32_t a0, uint32_t a1, uint32_t a2, uint32_t a3,
                                         uint32_t b0, uint32_t b1) {
    asm volatile(
        "mma.sync.aligned.m16n8k8.row.col.f32.tf32.tf32.f32 "
        "{%0,%1,%2,%3}, {%4,%5,%6,%7}, {%8,%9}, {%0,%1,%2,%3};"
        : "+f"(c0), "+f"(c1), "+f"(c2), "+f"(c3)
        : "r"(a0), "r"(a1), "r"(a2), "r"(a3), "r"(b0), "r"(b1));
}

__device__ __forceinline__ void mma_bf16(float& c0, float& c1, float& c2, float& c3,
                                         uint32_t a0, uint32_t a1, uint32_t a2, uint32_t a3,
                                         uint32_t b0, uint32_t b1) {
    asm volatile(
        "mma.sync.aligned.m16n8k16.row.col.f32.bf16.bf16.f32 "
        "{%0,%1,%2,%3}, {%4,%5,%6,%7}, {%8,%9}, {%0,%1,%2,%3};"
        : "+f"(c0), "+f"(c1), "+f"(c2), "+f"(c3)
        : "r"(a0), "r"(a1), "r"(a2), "r"(a3), "r"(b0), "r"(b1));
}

// ---------------- generic contiguous tf32 hi/lo split ----------------
__global__ void split_kernel(const float* __restrict__ src,
                             float* __restrict__ hi, float* __restrict__ lo) {
    size_t i = (size_t)blockIdx.x * 1024 + threadIdx.x;
    float x = src[i];
    float h = tf32_rna(x);
    hi[i] = h;
    lo[i] = tf32_rna(x - h);
}

// ---------------- bf16 hi/lo split of key_store ----------------
__global__ void split_ks_bf16_kernel(const float* __restrict__ ks,
                                     __nv_bfloat16* __restrict__ hi,
                                     __nv_bfloat16* __restrict__ lo) {
    size_t i = (size_t)blockIdx.x * 1024 + threadIdx.x;  // 8.4M
    float x = ks[i];
    __nv_bfloat16 h = __float2bfloat16(x);
    hi[i] = h;
    lo[i] = __float2bfloat16(x - __bfloat162float(h));
}

// -------- bf16 hi/lo split of k (from qkv), relayout to [h][t][d] --------
__global__ void split_qk_bf16_kernel(const float* __restrict__ qkv,
                                     __nv_bfloat16* __restrict__ hi,
                                     __nv_bfloat16* __restrict__ lo) {
    int i = blockIdx.x * 1024 + threadIdx.x;  // 1M
    int d = i & 63, t = (i >> 6) & 1023, h = i >> 16;
    float x = qkv[(size_t)t * 3072 + 1024 + h * 64 + d];
    __nv_bfloat16 hf = __float2bfloat16(x);
    hi[i] = hf;
    lo[i] = __float2bfloat16(x - __bfloat162float(hf));
}

// ---- generic 3xTF32 mma GEMM: C = A * B^T + bias  (round-7 validated) ----
#define KA 68
#define GM_SMEM_FLOATS (64 * KA * 2 + 128 * KA * 2)

__global__ __launch_bounds__(256) void mma_gemm_kernel(
    const float* __restrict__ Ahg, const float* __restrict__ Alg,
    const float* __restrict__ Bhg, const float* __restrict__ Blg,
    float* __restrict__ C, int ldc, int K, const float* __restrict__ bias) {
    extern __shared__ float sm[];
    float* Ah = sm;                   // [64][68]
    float* Al = Ah + 64 * KA;
    float* Bh = Al + 64 * KA;         // [128][68]
    float* Bl = Bh + 128 * KA;

    const int tid = threadIdx.x;
    const int bx = blockIdx.x, by = blockIdx.y;
    const int w = tid >> 5, lane = tid & 31;
    const int gid = lane >> 2, qid = lane & 3;
    const int rt = (w & 3) * 16;
    const int ch = (w >> 2) * 64;

    const float* Ahb = Ahg + (size_t)(by * 64) * K;
    const float* Alb = Alg + (size_t)(by * 64) * K;
    const float* Bhb = Bhg + (size_t)(bx * 128) * K;
    const float* Blb = Blg + (size_t)(bx * 128) * K;

    float c[8][4];
#pragma unroll
    for (int nb = 0; nb < 8; nb++)
#pragma unroll
        for (int k = 0; k < 4; k++) c[nb][k] = 0.f;

    for (int k0 = 0; k0 < K; k0 += 64) {
        __syncthreads();
        for (int i = tid; i < 64 * 16; i += 256) {
            int r = i >> 4, c4 = (i & 15) << 2;
            *(float4*)&Ah[r * KA + c4] = *(const float4*)(Ahb + (size_t)r * K + k0 + c4);
            *(float4*)&Al[r * KA + c4] = *(const float4*)(Alb + (size_t)r * K + k0 + c4);
        }
        for (int i = tid; i < 128 * 16; i += 256) {
            int r = i >> 4, c4 = (i & 15) << 2;
            *(float4*)&Bh[r * KA + c4] = *(const float4*)(Bhb + (size_t)r * K + k0 + c4);
            *(float4*)&Bl[r * KA + c4] = *(const float4*)(Blb + (size_t)r * K + k0 + c4);
        }
        __syncthreads();

#pragma unroll
        for (int ks8 = 0; ks8 < 8; ks8++) {
            const int kk = ks8 * 8;
            uint32_t ah0 = __float_as_uint(Ah[(rt + gid) * KA + kk + qid]);
            uint32_t ah1 = __float_as_uint(Ah[(rt + gid + 8) * KA + kk + qid]);
            uint32_t ah2 = __float_as_uint(Ah[(rt + gid) * KA + kk + qid + 4]);
            uint32_t ah3 = __float_as_uint(Ah[(rt + gid + 8) * KA + kk + qid + 4]);
            uint32_t al0 = __float_as_uint(Al[(rt + gid) * KA + kk + qid]);
            uint32_t al1 = __float_as_uint(Al[(rt + gid + 8) * KA + kk + qid]);
            uint32_t al2 = __float_as_uint(Al[(rt + gid) * KA + kk + qid + 4]);
            uint32_t al3 = __float_as_uint(Al[(rt + gid + 8) * KA + kk + qid + 4]);
#pragma unroll
            for (int nb = 0; nb < 8; nb++) {
                int mrow = ch + nb * 8 + gid;
                uint32_t bh0 = __float_as_uint(Bh[mrow * KA + kk + qid]);
                uint32_t bh1 = __float_as_uint(Bh[mrow * KA + kk + qid + 4]);
                uint32_t bl0 = __float_as_uint(Bl[mrow * KA + kk + qid]);
                uint32_t bl1 = __float_as_uint(Bl[mrow * KA + kk + qid + 4]);
                mma_tf32(c[nb][0], c[nb][1], c[nb][2], c[nb][3],
                         ah0, ah1, ah2, ah3, bh0, bh1);
                mma_tf32(c[nb][0], c[nb][1], c[nb][2], c[nb][3],
                         ah0, ah1, ah2, ah3, bl0, bl1);
                mma_tf32(c[nb][0], c[nb][1], c[nb][2], c[nb][3],
                         al0, al1, al2, al3, bh0, bh1);
            }
        }
    }

#pragma unroll
    for (int nb = 0; nb < 8; nb++) {
#pragma unroll
        for (int k = 0; k < 4; k++) {
            int row = by * 64 + rt + gid + (k >> 1) * 8;
            int col = bx * 128 + ch + nb * 8 + 2 * qid + (k & 1);
            C[(size_t)row * ldc + col] = c[nb][k] + bias[col];
        }
    }
}

// ---------------- ||key_store[h,m]||^2 (exact fp32) ----------------
__global__ void ksnorm_kernel(const float* __restrict__ ks, float* __restrict__ nrm) {
    int r = blockIdx.x * blockDim.x + threadIdx.x;
    if (r >= 16 * 8192) return;
    const float4* p = (const float4*)(ks + (size_t)r * 64);
    float s = 0.f;
#pragma unroll
    for (int i = 0; i < 16; i++) {
        float4 f = p[i];
        s += f.x * f.x + f.y * f.y + f.z * f.z + f.w * f.w;
    }
    nrm[r] = s;
}

// ------------- lexicographic (score, idx) compare: stable top-k --------------
__device__ __forceinline__ bool lex_lt(float sa, int ia, float sb, int ib) {
    return sa < sb || (sa == sb && ia < ib);
}

#define TOP4_INSERT(v, m, s0, x0, s1, x1, s2, x2, s3, x3)              \
    if (lex_lt(v, m, s3, x3)) {                                        \
        if (lex_lt(v, m, s2, x2)) {                                    \
            s3 = s2; x3 = x2;                                          \
            if (lex_lt(v, m, s1, x1)) {                                \
                s2 = s1; x2 = x1;                                      \
                if (lex_lt(v, m, s0, x0)) {                            \
                    s1 = s0; x1 = x0; s0 = v; x0 = m;                  \
                } else { s1 = v; x1 = m; }                             \
            } else { s2 = v; x2 = m; }                                 \
        } else { s3 = v; x3 = m; }                                     \
    }

// ---- fused kNN scores + top-4 via bf16 tensor cores (3xBF16 compensated) ----
// smem halves: Ah[64][72], Al[64][72], Bh[128][72], Bl[128][72], Ns[128]f
#define KAH 72
#define KNN_SMEM_BYTES ((64 * KAH * 2 + 128 * KAH * 2) * 2 + 128 * 4)

__global__ __launch_bounds__(256) void knn_mma_kernel(
    const __nv_bfloat16* __restrict__ kh, const __nv_bfloat16* __restrict__ kl,
    const __nv_bfloat16* __restrict__ mh, const __nv_bfloat16* __restrict__ ml,
    const float* __restrict__ ksn, int* __restrict__ idx_out) {
    extern __shared__ char smc[];
    __nv_bfloat16* Ah = (__nv_bfloat16*)smc;          // [64][72]
    __nv_bfloat16* Al = Ah + 64 * KAH;
    __nv_bfloat16* Bh = Al + 64 * KAH;                // [128][72]
    __nv_bfloat16* Bl = Bh + 128 * KAH;
    float* Ns = (float*)(Bl + 128 * KAH);             // [128]

    const int tid = threadIdx.x;
    const int t0 = blockIdx.x * 64;
    const int h = blockIdx.y;
    const int w = tid >> 5, lane = tid & 31;
    const int gid = lane >> 2, qid = lane & 3;
    const int rt = (w & 3) * 16;        // row tile base (t)
    const int ch = (w >> 2) * 64;       // col half base (m)

    // A tiles (bf16 hi/lo), 64 rows x 64 halves, uint4 = 8 halves
    const __nv_bfloat16* Ahg = kh + ((size_t)h * 1024 + t0) * 64;
    const __nv_bfloat16* Alg = kl + ((size_t)h * 1024 + t0) * 64;
    for (int i = tid; i < 512; i += 256) {
        int r = i >> 3, c8 = (i & 7) * 8;
        *(uint4*)&Ah[r * KAH + c8] = *(const uint4*)(Ahg + (size_t)r * 64 + c8);
        *(uint4*)&Al[r * KAH + c8] = *(const uint4*)(Alg + (size_t)r * 64 + c8);
    }

    float S[2][4];
    int I[2][4];
#pragma unroll
    for (int r = 0; r < 2; r++)
#pragma unroll
        for (int k = 0; k < 4; k++) { S[r][k] = FLT_MAX; I[r][k] = 0x7fffffff; }

    const __nv_bfloat16* Bhg = mh + (size_t)h * 8192 * 64;
    const __nv_bfloat16* Blg = ml + (size_t)h * 8192 * 64;
    const float* Nbase = ksn + h * 8192;

    for (int chunk = 0; chunk < 64; chunk++) {
        const int m0 = chunk << 7;
        __syncthreads();
        if (tid < 128) Ns[tid] = Nbase[m0 + tid];
        for (int i = tid; i < 1024; i += 256) {
            int r = i >> 3, c8 = (i & 7) * 8;
            *(uint4*)&Bh[r * KAH + c8] = *(const uint4*)(Bhg + (size_t)(m0 + r) * 64 + c8);
            *(uint4*)&Bl[r * KAH + c8] = *(const uint4*)(Blg + (size_t)(m0 + r) * 64 + c8);
        }
        __syncthreads();

        float c[8][4];
#pragma unroll
        for (int nb = 0; nb < 8; nb++)
#pragma unroll
            for (int k = 0; k < 4; k++) c[nb][k] = 0.f;

#pragma unroll
        for (int ks16 = 0; ks16 < 4; ks16++) {
            const int k0 = ks16 * 16;
            const int ab = (rt + gid) * KAH + k0 + 2 * qid;
            uint32_t ah0 = *(const uint32_t*)&Ah[ab];
            uint32_t ah1 = *(const uint32_t*)&Ah[ab + 8 * KAH];
            uint32_t ah2 = *(const uint32_t*)&Ah[ab + 8];
            uint32_t ah3 = *(const uint32_t*)&Ah[ab + 8 * KAH + 8];
            uint32_t al0 = *(const uint32_t*)&Al[ab];
            uint32_t al1 = *(const uint32_t*)&Al[ab + 8 * KAH];
            uint32_t al2 = *(const uint32_t*)&Al[ab + 8];
            uint32_t al3 = *(const uint32_t*)&Al[ab + 8 * KAH + 8];
#pragma unroll
            for (int nb = 0; nb < 8; nb++) {
                const int bb = (ch + nb * 8 + gid) * KAH + k0 + 2 * qid;
                uint32_t bh0 = *(const uint32_t*)&Bh[bb];
                uint32_t bh1 = *(const uint32_t*)&Bh[bb + 8];
                uint32_t bl0 = *(const uint32_t*)&Bl[bb];
                uint32_t bl1 = *(const uint32_t*)&Bl[bb + 8];
                mma_bf16(c[nb][0], c[nb][1], c[nb][2], c[nb][3],
                         ah0, ah1, ah2, ah3, bh0, bh1);
                mma_bf16(c[nb][0], c[nb][1], c[nb][2], c[nb][3],
                         ah0, ah1, ah2, ah3, bl0, bl1);
                mma_bf16(c[nb][0], c[nb][1], c[nb][2], c[nb][3],
                         al0, al1, al2, al3, bh0, bh1);
            }
        }

        // fold: c[nb][k]: row = gid + (k>>1)*8 (within tile), col = ch+nb*8+2qid+(k&1)
#pragma unroll
        for (int nb = 0; nb < 8; nb++) {
#pragma unroll
            for (int k = 0; k < 4; k++) {
                int cl = ch + nb * 8 + 2 * qid + (k & 1);
                int r = k >> 1;
                float v = Ns[cl] - 2.0f * c[nb][k];
                int mg = m0 + cl;
                TOP4_INSERT(v, mg, S[r][0], I[r][0], S[r][1], I[r][1],
                            S[r][2], I[r][2], S[r][3], I[r][3]);
            }
        }
    }

    // merge: 8 contributor threads per row (2 warp-halves x 4 qid), 32 cands/row
    __syncthreads();
    float* msc = (float*)smc;                 // [64][32] floats = 8KB
    int* mix = (int*)(smc + 16384);           // [64][32] ints, disjoint
    const int slot = (w >> 2) * 4 + qid;
#pragma unroll
    for (int r = 0; r < 2; r++) {
        int row = rt + gid + r * 8;
#pragma unroll
        for (int k = 0; k < 4; k++) {
            msc[(row * 8 + slot) * 4 + k] = S[r][k];
            mix[(row * 8 + slot) * 4 + k] = I[r][k];
        }
    }
    __syncthreads();
    if (tid < 64) {
        float f0 = FLT_MAX, f1 = FLT_MAX, f2 = FLT_MAX, f3 = FLT_MAX;
        int g0 = 0x7fffffff, g1 = 0x7fffffff, g2 = 0x7fffffff, g3 = 0x7fffffff;
        for (int c2 = 0; c2 < 32; c2++) {
            float v = msc[tid * 32 + c2];
            int m = mix[tid * 32 + c2];
            TOP4_INSERT(v, m, f0, g0, f1, g1, f2, g2, f3, g3);
        }
        size_t row = (size_t)h * 1024 + t0 + tid;
        idx_out[row * 4 + 0] = g0;
        idx_out[row * 4 + 1] = g1;
        idx_out[row * 4 + 2] = g2;
        idx_out[row * 4 + 3] = g3;
    }
}

// ---------------- warp-per-token last-row logits ----------------
__global__ void selA_kernel(const float* __restrict__ qkv, float* __restrict__ lg) {
    int h = blockIdx.y;
    int t = blockIdx.x * 8 + (threadIdx.x >> 5);
    int lane = threadIdx.x & 31;
    int d0 = lane * 2;
    const float* q = qkv + (size_t)1023 * 3072 + h * 64;
    const float* k = qkv + (size_t)t * 3072 + 1024 + h * 64;
    float s = q[d0] * k[d0] + q[d0 + 1] * k[d0 + 1];
#pragma unroll
    for (int o = 16; o > 0; o >>= 1) s += __shfl_xor_sync(0xffffffffu, s, o);
    if (lane == 0) lg[h * 1024 + t] = s * 0.125f;
}

// ---------------- per-head softmax of logits row -> sel ----------------
__global__ void selB_kernel(const float* __restrict__ lg, int* __restrict__ sel) {
    int h = blockIdx.x;
    int tid = threadIdx.x;
    int lane = tid & 31, warp = tid >> 5;
    __shared__ float red[8];
    __shared__ float bcast;

    float v[4];
#pragma unroll
    for (int u = 0; u < 4; u++) v[u] = lg[h * 1024 + tid + u * 256];
    float m = fmaxf(fmaxf(v[0], v[1]), fmaxf(v[2], v[3]));
#pragma unroll
    for (int o = 16; o > 0; o >>= 1) m = fmaxf(m, __shfl_xor_sync(0xffffffffu, m, o));
    if (lane == 0) red[warp] = m;
    __syncthreads();
    if (tid == 0) {
        float x = red[0];
#pragma unroll
        for (int w = 1; w < 8; w++) x = fmaxf(x, red[w]);
        bcast = x;
    }
    __syncthreads();
    m = bcast;
    float e[4], s = 0.f;
#pragma unroll
    for (int u = 0; u < 4; u++) { e[u] = __expf(v[u] - m); s += e[u]; }
#pragma unroll
    for (int o = 16; o > 0; o >>= 1) s += __shfl_xor_sync(0xffffffffu, s, o);
    if (lane == 0) red[warp] = s;
    __syncthreads();
    if (tid == 0) {
        float x = 0.f;
#pragma unroll
        for (int w = 0; w < 8; w++) x += red[w];
        bcast = x;
    }
    __syncthreads();
    float inv = 1.f / bcast;
#pragma unroll
    for (int u = 0; u < 4; u++)
        sel[h * 1024 + tid + u * 256] = (e[u] * inv >= (1.0f / 8192.0f)) ? 1 : 0;
}

// ---------------- per-token 5-way memory softmax & blend -> v_new ----------------
__device__ __forceinline__ float warp_sum(float v) {
#pragma unroll
    for (int o = 16; o > 0; o >>= 1) v += __shfl_xor_sync(0xffffffffu, v, o);
    return v;
}

__global__ void vnew_kernel(const float* __restrict__ qkv, const float* __restrict__ kstore,
                            const float* __restrict__ vstore, const int* __restrict__ idx,
                            const int* __restrict__ sel, float* __restrict__ vnew) {
    int gw = (blockIdx.x * blockDim.x + threadIdx.x) >> 5;
    int lane = threadIdx.x & 31;
    if (gw >= 16 * 1024) return;
    int h = gw >> 10, t = gw & 1023;

    const float* base = qkv + (size_t)t * 3072 + h * 64;
    int d0 = lane * 2;
    float q0 = base[d0],        q1 = base[d0 + 1];
    float k0 = base[1024 + d0], k1 = base[1024 + d0 + 1];
    float v0 = base[2048 + d0], v1 = base[2048 + d0 + 1];
    const float scale = 0.125f;

    float attf[5];
    attf[0] = warp_sum(q0 * k0 + q1 * k1) * scale;

    int ids[4];
#pragma unroll
    for (int s2 = 0; s2 < 4; s2++) ids[s2] = idx[(size_t)gw * 4 + s2];

    float fv0[4], fv1[4];
#pragma unroll
    for (int s2 = 0; s2 < 4; s2++) {
        const float* kp = kstore + ((size_t)h * 8192 + ids[s2]) * 64;
        attf[s2 + 1] = warp_sum(q0 * kp[d0] + q1 * kp[d0 + 1]) * scale;
        const float* vp = vstore + ((size_t)h * 8192 + ids[s2]) * 64;
        fv0[s2] = vp[d0]; fv1[s2] = vp[d0 + 1];
    }

    float mx = attf[0];
#pragma unroll
    for (int s2 = 1; s2 < 5; s2++) mx = fmaxf(mx, attf[s2]);
    float e[5], sum = 0.f;
#pragma unroll
    for (int s2 = 0; s2 < 5; s2++) { e[s2] = expf(attf[s2] - mx); sum += e[s2]; }
    float inv = 1.f / sum;

    float o0 = e[0] * v0, o1 = e[0] * v1;
#pragma unroll
    for (int s2 = 0; s2 < 4; s2++) { o0 += e[s2 + 1] * fv0[s2]; o1 += e[s2 + 1] * fv1[s2]; }
    o0 = o0 * inv * 0.5f + v0 * 0.5f;
    o1 = o1 * inv * 0.5f + v1 * 0.5f;

    bool sl = sel[gw] != 0;
    vnew[(size_t)gw * 64 + d0]     = sl ? o0 : v0;
    vnew[(size_t)gw * 64 + d0 + 1] = sl ? o1 : v1;
}

// ------- fused flash attention: y = softmax_causal(q k^T / 8) @ v_new -------
#define FL_QS 132
#define FL_KS 68
#define FL_VS 68
#define FL_PS 68
#define FL_SMEM_FLOATS (64 * FL_QS + 64 * FL_KS + 64 * FL_VS + 128 * FL_PS)

__global__ __launch_bounds__(256) void flash_kernel(
    const float* __restrict__ qkv, const float* __restrict__ vnew,
    float* __restrict__ y) {
    extern __shared__ float sm[];
    float* Qs = sm;
    float* Ks = Qs + 64 * FL_QS;
    float* Vs = Ks + 64 * FL_KS;
    float* Ps = Vs + 64 * FL_VS;

    const int tid = threadIdx.x;
    const int qb = blockIdx.x, h = blockIdx.y;
    const int tx = tid & 15, ty = tid >> 4;
    const int t0 = qb * 128;

    const float* Qbase = qkv + (size_t)t0 * 3072 + h * 64;
    for (int i = tid; i < 128 * 16; i += 256) {
        int r = i & 127, c4 = (i >> 7) << 2;
        float4 v = *(const float4*)(Qbase + (size_t)r * 3072 + c4);
        Qs[(c4 + 0) * FL_QS + r] = v.x * 0.125f;
        Qs[(c4 + 1) * FL_QS + r] = v.y * 0.125f;
        Qs[(c4 + 2) * FL_QS + r] = v.z * 0.125f;
        Qs[(c4 + 3) * FL_QS + r] = v.w * 0.125f;
    }

    float m[8], l[8], O[8][4];
#pragma unroll
    for (int i = 0; i < 8; i++) {
        m[i] = -FLT_MAX; l[i] = 0.f;
#pragma unroll
        for (int j = 0; j < 4; j++) O[i][j] = 0.f;
    }

    const int nj = 2 * qb + 2;
    for (int j = 0; j < nj; j++) {
        const int s0 = j * 64;
        __syncthreads();
        const float* Kbase = qkv + (size_t)s0 * 3072 + 1024 + h * 64;
        for (int i = tid; i < 64 * 16; i += 256) {
            int r = i & 63, c4 = (i >> 6) << 2;
            float4 v = *(const float4*)(Kbase + (size_t)r * 3072 + c4);
            Ks[(c4 + 0) * FL_KS + r] = v.x;
            Ks[(c4 + 1) * FL_KS + r] = v.y;
            Ks[(c4 + 2) * FL_KS + r] = v.z;
            Ks[(c4 + 3) * FL_KS + r] = v.w;
        }
        const float* Vbase = vnew + ((size_t)h * 1024 + s0) * 64;
        for (int i = tid; i < 64 * 16; i += 256) {
            int r = i >> 4, c4 = (i & 15) << 2;
            *(float4*)&Vs[r * FL_VS + c4] = *(const float4*)(Vbase + (size_t)r * 64 + c4);
        }
        __syncthreads();

        float acc[8][4];
#pragma unroll
        for (int i = 0; i < 8; i++)
#pragma unroll
            for (int jj = 0; jj < 4; jj++) acc[i][jj] = 0.f;
#pragma unroll 8
        for (int kk = 0; kk < 64; kk++) {
            float4 a0 = *(const float4*)&Qs[kk * FL_QS + ty * 8];
            float4 a1 = *(const float4*)&Qs[kk * FL_QS + ty * 8 + 4];
            float4 b  = *(const float4*)&Ks[kk * FL_KS + tx * 4];
            float av[8] = {a0.x, a0.y, a0.z, a0.w, a1.x, a1.y, a1.z, a1.w};
            float bv[4] = {b.x, b.y, b.z, b.w};
#pragma unroll
            for (int i = 0; i < 8; i++)
#pragma unroll
                for (int jj = 0; jj < 4; jj++)
                    acc[i][jj] = fmaf(av[i], bv[jj], acc[i][jj]);
        }

        const bool diag = (j >= 2 * qb);
#pragma unroll
        for (int i = 0; i < 8; i++) {
            int tg = t0 + ty * 8 + i;
            float v0 = acc[i][0], v1 = acc[i][1], v2 = acc[i][2], v3 = acc[i][3];
            if (diag) {
                int sg = s0 + tx * 4;
                if (sg + 0 > tg) v0 = -FLT_MAX;
                if (sg + 1 > tg) v1 = -FLT_MAX;
                if (sg + 2 > tg) v2 = -FLT_MAX;
                if (sg + 3 > tg) v3 = -FLT_MAX;
            }
            float rm = fmaxf(fmaxf(v0, v1), fmaxf(v2, v3));
#pragma unroll
            for (int o = 8; o > 0; o >>= 1) rm = fmaxf(rm, __shfl_xor_sync(0xffffffffu, rm, o));
            float mn = fmaxf(m[i], rm);
            float alpha = __expf(m[i] - mn);
            float p0 = __expf(v0 - mn), p1 = __expf(v1 - mn);
            float p2 = __expf(v2 - mn), p3 = __expf(v3 - mn);
            float ps = p0 + p1 + p2 + p3;
#pragma unroll
            for (int o = 8; o > 0; o >>= 1) ps += __shfl_xor_sync(0xffffffffu, ps, o);
            l[i] = l[i] * alpha + ps;
            m[i] = mn;
#pragma unroll
            for (int jj = 0; jj < 4; jj++) O[i][jj] *= alpha;
            float4 pv = {p0, p1, p2, p3};
            *(float4*)&Ps[(ty * 8 + i) * FL_PS + tx * 4] = pv;
        }
        __syncthreads();

#pragma unroll 4
        for (int s4 = 0; s4 < 16; s4++) {
            float4 vv0 = *(const float4*)&Vs[(s4 * 4 + 0) * FL_VS + tx * 4];
            float4 vv1 = *(const float4*)&Vs[(s4 * 4 + 1) * FL_VS + tx * 4];
            float4 vv2 = *(const float4*)&Vs[(s4 * 4 + 2) * FL_VS + tx * 4];
            float4 vv3 = *(const float4*)&Vs[(s4 * 4 + 3) * FL_VS + tx * 4];
#pragma unroll
            for (int i = 0; i < 8; i++) {
                float4 pp = *(const float4*)&Ps[(ty * 8 + i) * FL_PS + s4 * 4];
                O[i][0] = fmaf(pp.x, vv0.x, O[i][0]); O[i][1] = fmaf(pp.x, vv0.y, O[i][1]);
                O[i][2] = fmaf(pp.x, vv0.z, O[i][2]); O[i][3] = fmaf(pp.x, vv0.w, O[i][3]);
                O[i][0] = fmaf(pp.y, vv1.x, O[i][0]); O[i][1] = fmaf(pp.y, vv1.y, O[i][1]);
                O[i][2] = fmaf(pp.y, vv1.z, O[i][2]); O[i][3] = fmaf(pp.y, vv1.w, O[i][3]);
                O[i][0] = fmaf(pp.z, vv2.x, O[i][0]); O[i][1] = fmaf(pp.z, vv2.y, O[i][1]);
                O[i][2] = fmaf(pp.z, vv2.z, O[i][2]); O[i][3] = fmaf(pp.z, vv2.w, O[i][3]);
                O[i][0] = fmaf(pp.w, vv3.x, O[i][0]); O[i][1] = fmaf(pp.w, vv3.y, O[i][1]);
                O[i][2] = fmaf(pp.w, vv3.z, O[i][2]); O[i][3] = fmaf(pp.w, vv3.w, O[i][3]);
            }
        }
    }

#pragma unroll
    for (int i = 0; i < 8; i++) {
        float inv = 1.f / l[i];
        float4 o = {O[i][0] * inv, O[i][1] * inv, O[i][2] * inv, O[i][3] * inv};
        *(float4*)&y[(size_t)(t0 + ty * 8 + i) * 1024 + h * 64 + tx * 4] = o;
    }
}

// ---------------- launch ----------------
extern "C" void kernel_launch(void* const* d_in, const int* in_sizes, int n_in,
                              void* d_out, int out_size) {
    const float* x  = (const float*)d_in[0];
    const float* aw = (const float*)d_in[1];
    const float* ab = (const float*)d_in[2];
    const float* pw = (const float*)d_in[3];
    const float* pb = (const float*)d_in[4];
    const float* ks = (const float*)d_in[5];
    const float* vs = (const float*)d_in[6];
    float* out = (float*)d_out;

    float *qkv, *ksn, *lg, *vnw, *y;
    float *xh, *xl, *awh, *awl, *pwh, *pwl, *yh, *yl;
    __nv_bfloat16 *kh, *kl, *mh, *ml;
    int *idx, *sel;
    cudaGetSymbolAddress((void**)&qkv, g_qkv);
    cudaGetSymbolAddress((void**)&ksn, g_ksnorm);
    cudaGetSymbolAddress((void**)&kh,  g_kh);
    cudaGetSymbolAddress((void**)&kl,  g_kl);
    cudaGetSymbolAddress((void**)&mh,  g_mh);
    cudaGetSymbolAddress((void**)&ml,  g_ml);
    cudaGetSymbolAddress((void**)&xh,  g_xh);
    cudaGetSymbolAddress((void**)&xl,  g_xl);
    cudaGetSymbolAddress((void**)&awh, g_awh);
    cudaGetSymbolAddress((void**)&awl, g_awl);
    cudaGetSymbolAddress((void**)&pwh, g_pwh);
    cudaGetSymbolAddress((void**)&pwl, g_pwl);
    cudaGetSymbolAddress((void**)&yh,  g_yh);
    cudaGetSymbolAddress((void**)&yl,  g_yl);
    cudaGetSymbolAddress((void**)&lg,  g_lg);
    cudaGetSymbolAddress((void**)&idx, g_idx);
    cudaGetSymbolAddress((void**)&sel, g_sel);
    cudaGetSymbolAddress((void**)&vnw, g_vnew);
    cudaGetSymbolAddress((void**)&y,   g_y);

    cudaFuncSetAttribute(knn_mma_kernel,
                         cudaFuncAttributeMaxDynamicSharedMemorySize,
                         KNN_SMEM_BYTES);
    cudaFuncSetAttribute(mma_gemm_kernel,
                         cudaFuncAttributeMaxDynamicSharedMemorySize,
                         GM_SMEM_FLOATS * (int)sizeof(float));
    cudaFuncSetAttribute(flash_kernel,
                         cudaFuncAttributeMaxDynamicSharedMemorySize,
                         FL_SMEM_FLOATS * (int)sizeof(float));

    // 0) splits: tf32 for dense GEMMs, bf16 for kNN operands
    split_kernel<<<1024, 1024>>>(x,  xh,  xl);
    split_kernel<<<3072, 1024>>>(aw, awh, awl);
    split_kernel<<<1024, 1024>>>(pw, pwh, pwl);
    split_ks_bf16_kernel<<<8192, 1024>>>(ks, mh, ml);
    // 1) qkv = x @ c_attn_w^T + b   (3xTF32 mma)
    mma_gemm_kernel<<<dim3(24, 16), 256, GM_SMEM_FLOATS * sizeof(float)>>>(
        xh, xl, awh, awl, qkv, 3072, 1024, ab);
    // 2) key_store norms + k split/relayout (bf16)
    ksnorm_kernel<<<512, 256>>>(ks, ksn);
    split_qk_bf16_kernel<<<1024, 1024>>>(qkv, kh, kl);
    // 3) fused kNN scores + top-4 on bf16 tensor cores (3xBF16)
    knn_mma_kernel<<<dim3(16, 16), 256, KNN_SMEM_BYTES>>>(
        kh, kl, mh, ml, ksn, idx);
    // 4) sel from last-row softmax
    selA_kernel<<<dim3(128, 16), 256>>>(qkv, lg);
    selB_kernel<<<16, 1024>>>(lg, sel);
    // 5) 5-way softmax blend -> v_new
    vnew_kernel<<<2048, 256>>>(qkv, ks, vs, idx, sel, vnw);
    // 6) fused flash attention -> y (T,C)
    flash_kernel<<<dim3(8, 16), 256, FL_SMEM_FLOATS * sizeof(float)>>>(qkv, vnw, y);
    // 7) out = y @ c_proj_w^T + b   (3xTF32 mma)
    split_kernel<<<1024, 1024>>>(y, yh, yl);
    mma_gemm_kernel<<<dim3(8, 16), 256, GM_SMEM_FLOATS * sizeof(float)>>>(
        yh, yl, pwh, pwl, out, 1024, 1024, pb);
}

// round 9
// speedup vs baseline: 2.1797x; 1.2662x over previous
#include <cuda_runtime.h>
#include <cuda_bf16.h>
#include <cfloat>
#include <cstdint>

// ---------------- scratch (__device__ globals; no allocations) ----------------
__device__ float g_qkv[1024 * 3072];              // 12 MB  (T, 3C)
__device__ float g_ksnorm[16 * 8192];             // (H, M)
__device__ __nv_bfloat16 g_kh[16 * 1024 * 64];    // bf16-hi of k, [h][t][d]
__device__ __nv_bfloat16 g_kl[16 * 1024 * 64];    // bf16-lo of k
__device__ __nv_bfloat16 g_mh[16 * 8192 * 64];    // bf16-hi of key_store
__device__ __nv_bfloat16 g_ml[16 * 8192 * 64];    // bf16-lo of key_store
__device__ __nv_bfloat16 g_xh[1024 * 1024];       // bf16-hi of x
__device__ __nv_bfloat16 g_xl[1024 * 1024];
__device__ __nv_bfloat16 g_awh[3072 * 1024];      // bf16-hi of c_attn_w
__device__ __nv_bfloat16 g_awl[3072 * 1024];
__device__ __nv_bfloat16 g_pwh[1024 * 1024];      // bf16-hi of c_proj_w
__device__ __nv_bfloat16 g_pwl[1024 * 1024];
__device__ __nv_bfloat16 g_yh[1024 * 1024];       // bf16-hi of y
__device__ __nv_bfloat16 g_yl[1024 * 1024];
__device__ float g_lg[16 * 1024];                 // last-row logits
__device__ int   g_idx[16 * 1024 * 4];            // (H, T, 4)
__device__ int   g_sel[16 * 1024];                // (H, T)
__device__ float g_vnew[16 * 1024 * 64];          // (H, T, d)
__device__ float g_y[1024 * 1024];                // (T, C)

// ---------------- helpers ----------------
__device__ __forceinline__ void mma_bf16(float& c0, float& c1, float& c2, float& c3,
                                         uint32_t a0, uint32_t a1, uint32_t a2, uint32_t a3,
                                         uint32_t b0, uint32_t b1) {
    asm volatile(
        "mma.sync.aligned.m16n8k16.row.col.f32.bf16.bf16.f32 "
        "{%0,%1,%2,%3}, {%4,%5,%6,%7}, {%8,%9}, {%0,%1,%2,%3};"
        : "+f"(c0), "+f"(c1), "+f"(c2), "+f"(c3)
        : "r"(a0), "r"(a1), "r"(a2), "r"(a3), "r"(b0), "r"(b1));
}

// ---------- vectorized contiguous bf16 hi/lo split (4 floats / thread) ----------
__global__ void split_bf16_v4(const float4* __restrict__ src,
                              __nv_bfloat162* __restrict__ hi,
                              __nv_bfloat162* __restrict__ lo) {
    size_t i = (size_t)blockIdx.x * 256 + threadIdx.x;
    float4 v = src[i];
    __nv_bfloat16 h0 = __float2bfloat16(v.x), h1 = __float2bfloat16(v.y);
    __nv_bfloat16 h2 = __float2bfloat16(v.z), h3 = __float2bfloat16(v.w);
    __nv_bfloat16 l0 = __float2bfloat16(v.x - __bfloat162float(h0));
    __nv_bfloat16 l1 = __float2bfloat16(v.y - __bfloat162float(h1));
    __nv_bfloat16 l2 = __float2bfloat16(v.z - __bfloat162float(h2));
    __nv_bfloat16 l3 = __float2bfloat16(v.w - __bfloat162float(h3));
    hi[i * 2 + 0] = __nv_bfloat162{h0, h1};
    hi[i * 2 + 1] = __nv_bfloat162{h2, h3};
    lo[i * 2 + 0] = __nv_bfloat162{l0, l1};
    lo[i * 2 + 1] = __nv_bfloat162{l2, l3};
}

// -------- bf16 hi/lo split of k (from qkv), relayout to [h][t][d] --------
__global__ void split_qk_bf16_kernel(const float* __restrict__ qkv,
                                     __nv_bfloat16* __restrict__ hi,
                                     __nv_bfloat16* __restrict__ lo) {
    int i = blockIdx.x * 1024 + threadIdx.x;  // 1M
    int d = i & 63, t = (i >> 6) & 1023, h = i >> 16;
    float x = qkv[(size_t)t * 3072 + 1024 + h * 64 + d];
    __nv_bfloat16 hf = __float2bfloat16(x);
    hi[i] = hf;
    lo[i] = __float2bfloat16(x - __bfloat162float(hf));
}

// ---- generic 3xBF16 mma GEMM: C = A * B^T + bias ----
// A: (M,K) rm bf16 hi/lo, B: (N,K) rm bf16 hi/lo. Block: 64 rows x 128 cols.
// grid = (N/128, M/64). Fragment mapping identical to knn_mma_kernel (validated).
#define KAH 72
#define GM_SMEM_BYTES ((64 * KAH * 2 + 128 * KAH * 2) * 2)

__global__ __launch_bounds__(256) void mma_gemm_bf16_kernel(
    const __nv_bfloat16* __restrict__ Ahg, const __nv_bfloat16* __restrict__ Alg,
    const __nv_bfloat16* __restrict__ Bhg, const __nv_bfloat16* __restrict__ Blg,
    float* __restrict__ C, int ldc, int K, const float* __restrict__ bias) {
    extern __shared__ char smc[];
    __nv_bfloat16* Ah = (__nv_bfloat16*)smc;          // [64][72]
    __nv_bfloat16* Al = Ah + 64 * KAH;
    __nv_bfloat16* Bh = Al + 64 * KAH;                // [128][72]
    __nv_bfloat16* Bl = Bh + 128 * KAH;

    const int tid = threadIdx.x;
    const int bx = blockIdx.x, by = blockIdx.y;
    const int w = tid >> 5, lane = tid & 31;
    const int gid = lane >> 2, qid = lane & 3;
    const int rt = (w & 3) * 16;
    const int ch = (w >> 2) * 64;

    const __nv_bfloat16* Ahb = Ahg + (size_t)(by * 64) * K;
    const __nv_bfloat16* Alb = Alg + (size_t)(by * 64) * K;
    const __nv_bfloat16* Bhb = Bhg + (size_t)(bx * 128) * K;
    const __nv_bfloat16* Blb = Blg + (size_t)(bx * 128) * K;

    float c[8][4];
#pragma unroll
    for (int nb = 0; nb < 8; nb++)
#pragma unroll
        for (int k = 0; k < 4; k++) c[nb][k] = 0.f;

    for (int k0 = 0; k0 < K; k0 += 64) {
        __syncthreads();
        for (int i = tid; i < 512; i += 256) {
            int r = i >> 3, c8 = (i & 7) * 8;
            *(uint4*)&Ah[r * KAH + c8] = *(const uint4*)(Ahb + (size_t)r * K + k0 + c8);
            *(uint4*)&Al[r * KAH + c8] = *(const uint4*)(Alb + (size_t)r * K + k0 + c8);
        }
        for (int i = tid; i < 1024; i += 256) {
            int r = i >> 3, c8 = (i & 7) * 8;
            *(uint4*)&Bh[r * KAH + c8] = *(const uint4*)(Bhb + (size_t)r * K + k0 + c8);
            *(uint4*)&Bl[r * KAH + c8] = *(const uint4*)(Blb + (size_t)r * K + k0 + c8);
        }
        __syncthreads();

#pragma unroll
        for (int ks16 = 0; ks16 < 4; ks16++) {
            const int kk = ks16 * 16;
            const int ab = (rt + gid) * KAH + kk + 2 * qid;
            uint32_t ah0 = *(const uint32_t*)&Ah[ab];
            uint32_t ah1 = *(const uint32_t*)&Ah[ab + 8 * KAH];
            uint32_t ah2 = *(const uint32_t*)&Ah[ab + 8];
            uint32_t ah3 = *(const uint32_t*)&Ah[ab + 8 * KAH + 8];
            uint32_t al0 = *(const uint32_t*)&Al[ab];
            uint32_t al1 = *(const uint32_t*)&Al[ab + 8 * KAH];
            uint32_t al2 = *(const uint32_t*)&Al[ab + 8];
            uint32_t al3 = *(const uint32_t*)&Al[ab + 8 * KAH + 8];
#pragma unroll
            for (int nb = 0; nb < 8; nb++) {
                const int bb = (ch + nb * 8 + gid) * KAH + kk + 2 * qid;
                uint32_t bh0 = *(const uint32_t*)&Bh[bb];
                uint32_t bh1 = *(const uint32_t*)&Bh[bb + 8];
                uint32_t bl0 = *(const uint32_t*)&Bl[bb];
                uint32_t bl1 = *(const uint32_t*)&Bl[bb + 8];
                mma_bf16(c[nb][0], c[nb][1], c[nb][2], c[nb][3],
                         ah0, ah1, ah2, ah3, bh0, bh1);
                mma_bf16(c[nb][0], c[nb][1], c[nb][2], c[nb][3],
                         ah0, ah1, ah2, ah3, bl0, bl1);
                mma_bf16(c[nb][0], c[nb][1], c[nb][2], c[nb][3],
                         al0, al1, al2, al3, bh0, bh1);
            }
        }
    }

#pragma unroll
    for (int nb = 0; nb < 8; nb++) {
#pragma unroll
        for (int k = 0; k < 4; k++) {
            int row = by * 64 + rt + gid + (k >> 1) * 8;
            int col = bx * 128 + ch + nb * 8 + 2 * qid + (k & 1);
            C[(size_t)row * ldc + col] = c[nb][k] + bias[col];
        }
    }
}

// ---------------- ||key_store[h,m]||^2 (exact fp32) ----------------
__global__ void ksnorm_kernel(const float* __restrict__ ks, float* __restrict__ nrm) {
    int r = blockIdx.x * blockDim.x + threadIdx.x;
    if (r >= 16 * 8192) return;
    const float4* p = (const float4*)(ks + (size_t)r * 64);
    float s = 0.f;
#pragma unroll
    for (int i = 0; i < 16; i++) {
        float4 f = p[i];
        s += f.x * f.x + f.y * f.y + f.z * f.z + f.w * f.w;
    }
    nrm[r] = s;
}

// ------------- lexicographic (score, idx) compare: stable top-k --------------
__device__ __forceinline__ bool lex_lt(float sa, int ia, float sb, int ib) {
    return sa < sb || (sa == sb && ia < ib);
}

#define TOP4_INSERT(v, m, s0, x0, s1, x1, s2, x2, s3, x3)              \
    if (lex_lt(v, m, s3, x3)) {                                        \
        if (lex_lt(v, m, s2, x2)) {                                    \
            s3 = s2; x3 = x2;                                          \
            if (lex_lt(v, m, s1, x1)) {                                \
                s2 = s1; x2 = x1;                                      \
                if (lex_lt(v, m, s0, x0)) {                            \
                    s1 = s0; x1 = x0; s0 = v; x0 = m;                  \
                } else { s1 = v; x1 = m; }                             \
            } else { s2 = v; x2 = m; }                                 \
        } else { s3 = v; x3 = m; }                                     \
    }

// ---- fused kNN scores + top-4 via bf16 tensor cores (round-8 validated) ----
#define KNN_SMEM_BYTES ((64 * KAH * 2 + 128 * KAH * 2) * 2 + 128 * 4)

__global__ __launch_bounds__(256) void knn_mma_kernel(
    const __nv_bfloat16* __restrict__ kh, const __nv_bfloat16* __restrict__ kl,
    const __nv_bfloat16* __restrict__ mh, const __nv_bfloat16* __restrict__ ml,
    const float* __restrict__ ksn, int* __restrict__ idx_out) {
    extern __shared__ char smc[];
    __nv_bfloat16* Ah = (__nv_bfloat16*)smc;          // [64][72]
    __nv_bfloat16* Al = Ah + 64 * KAH;
    __nv_bfloat16* Bh = Al + 64 * KAH;                // [128][72]
    __nv_bfloat16* Bl = Bh + 128 * KAH;
    float* Ns = (float*)(Bl + 128 * KAH);             // [128]

    const int tid = threadIdx.x;
    const int t0 = blockIdx.x * 64;
    const int h = blockIdx.y;
    const int w = tid >> 5, lane = tid & 31;
    const int gid = lane >> 2, qid = lane & 3;
    const int rt = (w & 3) * 16;
    const int ch = (w >> 2) * 64;

    const __nv_bfloat16* Ahg = kh + ((size_t)h * 1024 + t0) * 64;
    const __nv_bfloat16* Alg = kl + ((size_t)h * 1024 + t0) * 64;
    for (int i = tid; i < 512; i += 256) {
        int r = i >> 3, c8 = (i & 7) * 8;
        *(uint4*)&Ah[r * KAH + c8] = *(const uint4*)(Ahg + (size_t)r * 64 + c8);
        *(uint4*)&Al[r * KAH + c8] = *(const uint4*)(Alg + (size_t)r * 64 + c8);
    }

    float S[2][4];
    int I[2][4];
#pragma unroll
    for (int r = 0; r < 2; r++)
#pragma unroll
        for (int k = 0; k < 4; k++) { S[r][k] = FLT_MAX; I[r][k] = 0x7fffffff; }

    const __nv_bfloat16* Bhg = mh + (size_t)h * 8192 * 64;
    const __nv_bfloat16* Blg = ml + (size_t)h * 8192 * 64;
    const float* Nbase = ksn + h * 8192;

    for (int chunk = 0; chunk < 64; chunk++) {
        const int m0 = chunk << 7;
        __syncthreads();
        if (tid < 128) Ns[tid] = Nbase[m0 + tid];
        for (int i = tid; i < 1024; i += 256) {
            int r = i >> 3, c8 = (i & 7) * 8;
            *(uint4*)&Bh[r * KAH + c8] = *(const uint4*)(Bhg + (size_t)(m0 + r) * 64 + c8);
            *(uint4*)&Bl[r * KAH + c8] = *(const uint4*)(Blg + (size_t)(m0 + r) * 64 + c8);
        }
        __syncthreads();

        float c[8][4];
#pragma unroll
        for (int nb = 0; nb < 8; nb++)
#pragma unroll
            for (int k = 0; k < 4; k++) c[nb][k] = 0.f;

#pragma unroll
        for (int ks16 = 0; ks16 < 4; ks16++) {
            const int k0 = ks16 * 16;
            const int ab = (rt + gid) * KAH + k0 + 2 * qid;
            uint32_t ah0 = *(const uint32_t*)&Ah[ab];
            uint32_t ah1 = *(const uint32_t*)&Ah[ab + 8 * KAH];
            uint32_t ah2 = *(const uint32_t*)&Ah[ab + 8];
            uint32_t ah3 = *(const uint32_t*)&Ah[ab + 8 * KAH + 8];
            uint32_t al0 = *(const uint32_t*)&Al[ab];
            uint32_t al1 = *(const uint32_t*)&Al[ab + 8 * KAH];
            uint32_t al2 = *(const uint32_t*)&Al[ab + 8];
            uint32_t al3 = *(const uint32_t*)&Al[ab + 8 * KAH + 8];
#pragma unroll
            for (int nb = 0; nb < 8; nb++) {
                const int bb = (ch + nb * 8 + gid) * KAH + k0 + 2 * qid;
                uint32_t bh0 = *(const uint32_t*)&Bh[bb];
                uint32_t bh1 = *(const uint32_t*)&Bh[bb + 8];
                uint32_t bl0 = *(const uint32_t*)&Bl[bb];
                uint32_t bl1 = *(const uint32_t*)&Bl[bb + 8];
                mma_bf16(c[nb][0], c[nb][1], c[nb][2], c[nb][3],
                         ah0, ah1, ah2, ah3, bh0, bh1);
                mma_bf16(c[nb][0], c[nb][1], c[nb][2], c[nb][3],
                         ah0, ah1, ah2, ah3, bl0, bl1);
                mma_bf16(c[nb][0], c[nb][1], c[nb][2], c[nb][3],
                         al0, al1, al2, al3, bh0, bh1);
            }
        }

#pragma unroll
        for (int nb = 0; nb < 8; nb++) {
#pragma unroll
            for (int k = 0; k < 4; k++) {
                int cl = ch + nb * 8 + 2 * qid + (k & 1);
                int r = k >> 1;
                float v = Ns[cl] - 2.0f * c[nb][k];
                int mg = m0 + cl;
                TOP4_INSERT(v, mg, S[r][0], I[r][0], S[r][1], I[r][1],
                            S[r][2], I[r][2], S[r][3], I[r][3]);
            }
        }
    }

    __syncthreads();
    float* msc = (float*)smc;                 // [64][32]
    int* mix = (int*)(smc + 16384);
    const int slot = (w >> 2) * 4 + qid;
#pragma unroll
    for (int r = 0; r < 2; r++) {
        int row = rt + gid + r * 8;
#pragma unroll
        for (int k = 0; k < 4; k++) {
            msc[(row * 8 + slot) * 4 + k] = S[r][k];
            mix[(row * 8 + slot) * 4 + k] = I[r][k];
        }
    }
    __syncthreads();
    if (tid < 64) {
        float f0 = FLT_MAX, f1 = FLT_MAX, f2 = FLT_MAX, f3 = FLT_MAX;
        int g0 = 0x7fffffff, g1 = 0x7fffffff, g2 = 0x7fffffff, g3 = 0x7fffffff;
        for (int c2 = 0; c2 < 32; c2++) {
            float v = msc[tid * 32 + c2];
            int m = mix[tid * 32 + c2];
            TOP4_INSERT(v, m, f0, g0, f1, g1, f2, g2, f3, g3);
        }
        size_t row = (size_t)h * 1024 + t0 + tid;
        idx_out[row * 4 + 0] = g0;
        idx_out[row * 4 + 1] = g1;
        idx_out[row * 4 + 2] = g2;
        idx_out[row * 4 + 3] = g3;
    }
}

// ---------------- warp-per-token last-row logits ----------------
__global__ void selA_kernel(const float* __restrict__ qkv, float* __restrict__ lg) {
    int h = blockIdx.y;
    int t = blockIdx.x * 8 + (threadIdx.x >> 5);
    int lane = threadIdx.x & 31;
    int d0 = lane * 2;
    const float* q = qkv + (size_t)1023 * 3072 + h * 64;
    const float* k = qkv + (size_t)t * 3072 + 1024 + h * 64;
    float s = q[d0] * k[d0] + q[d0 + 1] * k[d0 + 1];
#pragma unroll
    for (int o = 16; o > 0; o >>= 1) s += __shfl_xor_sync(0xffffffffu, s, o);
    if (lane == 0) lg[h * 1024 + t] = s * 0.125f;
}

// ---------------- per-head softmax of logits row -> sel ----------------
__global__ void selB_kernel(const float* __restrict__ lg, int* __restrict__ sel) {
    int h = blockIdx.x;
    int tid = threadIdx.x;
    int lane = tid & 31, warp = tid >> 5;
    __shared__ float red[8];
    __shared__ float bcast;

    float v[4];
#pragma unroll
    for (int u = 0; u < 4; u++) v[u] = lg[h * 1024 + tid + u * 256];
    float m = fmaxf(fmaxf(v[0], v[1]), fmaxf(v[2], v[3]));
#pragma unroll
    for (int o = 16; o > 0; o >>= 1) m = fmaxf(m, __shfl_xor_sync(0xffffffffu, m, o));
    if (lane == 0) red[warp] = m;
    __syncthreads();
    if (tid == 0) {
        float x = red[0];
#pragma unroll
        for (int w = 1; w < 8; w++) x = fmaxf(x, red[w]);
        bcast = x;
    }
    __syncthreads();
    m = bcast;
    float e[4], s = 0.f;
#pragma unroll
    for (int u = 0; u < 4; u++) { e[u] = __expf(v[u] - m); s += e[u]; }
#pragma unroll
    for (int o = 16; o > 0; o >>= 1) s += __shfl_xor_sync(0xffffffffu, s, o);
    if (lane == 0) red[warp] = s;
    __syncthreads();
    if (tid == 0) {
        float x = 0.f;
#pragma unroll
        for (int w = 0; w < 8; w++) x += red[w];
        bcast = x;
    }
    __syncthreads();
    float inv = 1.f / bcast;
#pragma unroll
    for (int u = 0; u < 4; u++)
        sel[h * 1024 + tid + u * 256] = (e[u] * inv >= (1.0f / 8192.0f)) ? 1 : 0;
}

// ---------------- per-token 5-way memory softmax & blend -> v_new ----------------
__device__ __forceinline__ float warp_sum(float v) {
#pragma unroll
    for (int o = 16; o > 0; o >>= 1) v += __shfl_xor_sync(0xffffffffu, v, o);
    return v;
}

__global__ void vnew_kernel(const float* __restrict__ qkv, const float* __restrict__ kstore,
                            const float* __restrict__ vstore, const int* __restrict__ idx,
                            const int* __restrict__ sel, float* __restrict__ vnew) {
    int gw = (blockIdx.x * blockDim.x + threadIdx.x) >> 5;
    int lane = threadIdx.x & 31;
    if (gw >= 16 * 1024) return;
    int h = gw >> 10, t = gw & 1023;

    const float* base = qkv + (size_t)t * 3072 + h * 64;
    int d0 = lane * 2;
    float q0 = base[d0],        q1 = base[d0 + 1];
    float k0 = base[1024 + d0], k1 = base[1024 + d0 + 1];
    float v0 = base[2048 + d0], v1 = base[2048 + d0 + 1];
    const float scale = 0.125f;

    float attf[5];
    attf[0] = warp_sum(q0 * k0 + q1 * k1) * scale;

    int ids[4];
#pragma unroll
    for (int s2 = 0; s2 < 4; s2++) ids[s2] = idx[(size_t)gw * 4 + s2];

    float fv0[4], fv1[4];
#pragma unroll
    for (int s2 = 0; s2 < 4; s2++) {
        const float* kp = kstore + ((size_t)h * 8192 + ids[s2]) * 64;
        attf[s2 + 1] = warp_sum(q0 * kp[d0] + q1 * kp[d0 + 1]) * scale;
        const float* vp = vstore + ((size_t)h * 8192 + ids[s2]) * 64;
        fv0[s2] = vp[d0]; fv1[s2] = vp[d0 + 1];
    }

    float mx = attf[0];
#pragma unroll
    for (int s2 = 1; s2 < 5; s2++) mx = fmaxf(mx, attf[s2]);
    float e[5], sum = 0.f;
#pragma unroll
    for (int s2 = 0; s2 < 5; s2++) { e[s2] = expf(attf[s2] - mx); sum += e[s2]; }
    float inv = 1.f / sum;

    float o0 = e[0] * v0, o1 = e[0] * v1;
#pragma unroll
    for (int s2 = 0; s2 < 4; s2++) { o0 += e[s2 + 1] * fv0[s2]; o1 += e[s2 + 1] * fv1[s2]; }
    o0 = o0 * inv * 0.5f + v0 * 0.5f;
    o1 = o1 * inv * 0.5f + v1 * 0.5f;

    bool sl = sel[gw] != 0;
    vnew[(size_t)gw * 64 + d0]     = sl ? o0 : v0;
    vnew[(size_t)gw * 64 + d0 + 1] = sl ? o1 : v1;
}

// ------- fused flash attention: y = softmax_causal(q k^T / 8) @ v_new -------
#define FL_QS 132
#define FL_KS 68
#define FL_VS 68
#define FL_PS 68
#define FL_SMEM_FLOATS (64 * FL_QS + 64 * FL_KS + 64 * FL_VS + 128 * FL_PS)

__global__ __launch_bounds__(256) void flash_kernel(
    const float* __restrict__ qkv, const float* __restrict__ vnew,
    float* __restrict__ y) {
    extern __shared__ float sm[];
    float* Qs = sm;
    float* Ks = Qs + 64 * FL_QS;
    float* Vs = Ks + 64 * FL_KS;
    float* Ps = Vs + 64 * FL_VS;

    const int tid = threadIdx.x;
    const int qb = blockIdx.x, h = blockIdx.y;
    const int tx = tid & 15, ty = tid >> 4;
    const int t0 = qb * 128;

    const float* Qbase = qkv + (size_t)t0 * 3072 + h * 64;
    for (int i = tid; i < 128 * 16; i += 256) {
        int r = i & 127, c4 = (i >> 7) << 2;
        float4 v = *(const float4*)(Qbase + (size_t)r * 3072 + c4);
        Qs[(c4 + 0) * FL_QS + r] = v.x * 0.125f;
        Qs[(c4 + 1) * FL_QS + r] = v.y * 0.125f;
        Qs[(c4 + 2) * FL_QS + r] = v.z * 0.125f;
        Qs[(c4 + 3) * FL_QS + r] = v.w * 0.125f;
    }

    float m[8], l[8], O[8][4];
#pragma unroll
    for (int i = 0; i < 8; i++) {
        m[i] = -FLT_MAX; l[i] = 0.f;
#pragma unroll
        for (int j = 0; j < 4; j++) O[i][j] = 0.f;
    }

    const int nj = 2 * qb + 2;
    for (int j = 0; j < nj; j++) {
        const int s0 = j * 64;
        __syncthreads();
        const float* Kbase = qkv + (size_t)s0 * 3072 + 1024 + h * 64;
        for (int i = tid; i < 64 * 16; i += 256) {
            int r = i & 63, c4 = (i >> 6) << 2;
            float4 v = *(const float4*)(Kbase + (size_t)r * 3072 + c4);
            Ks[(c4 + 0) * FL_KS + r] = v.x;
            Ks[(c4 + 1) * FL_KS + r] = v.y;
            Ks[(c4 + 2) * FL_KS + r] = v.z;
            Ks[(c4 + 3) * FL_KS + r] = v.w;
        }
        const float* Vbase = vnew + ((size_t)h * 1024 + s0) * 64;
        for (int i = tid; i < 64 * 16; i += 256) {
            int r = i >> 4, c4 = (i & 15) << 2;
            *(float4*)&Vs[r * FL_VS + c4] = *(const float4*)(Vbase + (size_t)r * 64 + c4);
        }
        __syncthreads();

        float acc[8][4];
#pragma unroll
        for (int i = 0; i < 8; i++)
#pragma unroll
            for (int jj = 0; jj < 4; jj++) acc[i][jj] = 0.f;
#pragma unroll 8
        for (int kk = 0; kk < 64; kk++) {
            float4 a0 = *(const float4*)&Qs[kk * FL_QS + ty * 8];
            float4 a1 = *(const float4*)&Qs[kk * FL_QS + ty * 8 + 4];
            float4 b  = *(const float4*)&Ks[kk * FL_KS + tx * 4];
            float av[8] = {a0.x, a0.y, a0.z, a0.w, a1.x, a1.y, a1.z, a1.w};
            float bv[4] = {b.x, b.y, b.z, b.w};
#pragma unroll
            for (int i = 0; i < 8; i++)
#pragma unroll
                for (int jj = 0; jj < 4; jj++)
                    acc[i][jj] = fmaf(av[i], bv[jj], acc[i][jj]);
        }

        const bool diag = (j >= 2 * qb);
#pragma unroll
        for (int i = 0; i < 8; i++) {
            int tg = t0 + ty * 8 + i;
            float v0 = acc[i][0], v1 = acc[i][1], v2 = acc[i][2], v3 = acc[i][3];
            if (diag) {
                int sg = s0 + tx * 4;
                if (sg + 0 > tg) v0 = -FLT_MAX;
                if (sg + 1 > tg) v1 = -FLT_MAX;
                if (sg + 2 > tg) v2 = -FLT_MAX;
                if (sg + 3 > tg) v3 = -FLT_MAX;
            }
            float rm = fmaxf(fmaxf(v0, v1), fmaxf(v2, v3));
#pragma unroll
            for (int o = 8; o > 0; o >>= 1) rm = fmaxf(rm, __shfl_xor_sync(0xffffffffu, rm, o));
            float mn = fmaxf(m[i], rm);
            float alpha = __expf(m[i] - mn);
            float p0 = __expf(v0 - mn), p1 = __expf(v1 - mn);
            float p2 = __expf(v2 - mn), p3 = __expf(v3 - mn);
            float ps = p0 + p1 + p2 + p3;
#pragma unroll
            for (int o = 8; o > 0; o >>= 1) ps += __shfl_xor_sync(0xffffffffu, ps, o);
            l[i] = l[i] * alpha + ps;
            m[i] = mn;
#pragma unroll
            for (int jj = 0; jj < 4; jj++) O[i][jj] *= alpha;
            float4 pv = {p0, p1, p2, p3};
            *(float4*)&Ps[(ty * 8 + i) * FL_PS + tx * 4] = pv;
        }
        __syncthreads();

#pragma unroll 4
        for (int s4 = 0; s4 < 16; s4++) {
            float4 vv0 = *(const float4*)&Vs[(s4 * 4 + 0) * FL_VS + tx * 4];
            float4 vv1 = *(const float4*)&Vs[(s4 * 4 + 1) * FL_VS + tx * 4];
            float4 vv2 = *(const float4*)&Vs[(s4 * 4 + 2) * FL_VS + tx * 4];
            float4 vv3 = *(const float4*)&Vs[(s4 * 4 + 3) * FL_VS + tx * 4];
#pragma unroll
            for (int i = 0; i < 8; i++) {
                float4 pp = *(const float4*)&Ps[(ty * 8 + i) * FL_PS + s4 * 4];
                O[i][0] = fmaf(pp.x, vv0.x, O[i][0]); O[i][1] = fmaf(pp.x, vv0.y, O[i][1]);
                O[i][2] = fmaf(pp.x, vv0.z, O[i][2]); O[i][3] = fmaf(pp.x, vv0.w, O[i][3]);
                O[i][0] = fmaf(pp.y, vv1.x, O[i][0]); O[i][1] = fmaf(pp.y, vv1.y, O[i][1]);
                O[i][2] = fmaf(pp.y, vv1.z, O[i][2]); O[i][3] = fmaf(pp.y, vv1.w, O[i][3]);
                O[i][0] = fmaf(pp.z, vv2.x, O[i][0]); O[i][1] = fmaf(pp.z, vv2.y, O[i][1]);
                O[i][2] = fmaf(pp.z, vv2.z, O[i][2]); O[i][3] = fmaf(pp.z, vv2.w, O[i][3]);
                O[i][0] = fmaf(pp.w, vv3.x, O[i][0]); O[i][1] = fmaf(pp.w, vv3.y, O[i][1]);
                O[i][2] = fmaf(pp.w, vv3.z, O[i][2]); O[i][3] = fmaf(pp.w, vv3.w, O[i][3]);
            }
        }
    }

#pragma unroll
    for (int i = 0; i < 8; i++) {
        float inv = 1.f / l[i];
        float4 o = {O[i][0] * inv, O[i][1] * inv, O[i][2] * inv, O[i][3] * inv};
        *(float4*)&y[(size_t)(t0 + ty * 8 + i) * 1024 + h * 64 + tx * 4] = o;
    }
}

// ---------------- launch ----------------
extern "C" void kernel_launch(void* const* d_in, const int* in_sizes, int n_in,
                              void* d_out, int out_size) {
    const float* x  = (const float*)d_in[0];
    const float* aw = (const float*)d_in[1];
    const float* ab = (const float*)d_in[2];
    const float* pw = (const float*)d_in[3];
    const float* pb = (const float*)d_in[4];
    const float* ks = (const float*)d_in[5];
    const float* vs = (const float*)d_in[6];
    float* out = (float*)d_out;

    float *qkv, *ksn, *lg, *vnw, *y;
    __nv_bfloat16 *kh, *kl, *mh, *ml, *xh, *xl, *awh, *awl, *pwh, *pwl, *yh, *yl;
    int *idx, *sel;
    cudaGetSymbolAddress((void**)&qkv, g_qkv);
    cudaGetSymbolAddress((void**)&ksn, g_ksnorm);
    cudaGetSymbolAddress((void**)&kh,  g_kh);
    cudaGetSymbolAddress((void**)&kl,  g_kl);
    cudaGetSymbolAddress((void**)&mh,  g_mh);
    cudaGetSymbolAddress((void**)&ml,  g_ml);
    cudaGetSymbolAddress((void**)&xh,  g_xh);
    cudaGetSymbolAddress((void**)&xl,  g_xl);
    cudaGetSymbolAddress((void**)&awh, g_awh);
    cudaGetSymbolAddress((void**)&awl, g_awl);
    cudaGetSymbolAddress((void**)&pwh, g_pwh);
    cudaGetSymbolAddress((void**)&pwl, g_pwl);
    cudaGetSymbolAddress((void**)&yh,  g_yh);
    cudaGetSymbolAddress((void**)&yl,  g_yl);
    cudaGetSymbolAddress((void**)&lg,  g_lg);
    cudaGetSymbolAddress((void**)&idx, g_idx);
    cudaGetSymbolAddress((void**)&sel, g_sel);
    cudaGetSymbolAddress((void**)&vnw, g_vnew);
    cudaGetSymbolAddress((void**)&y,   g_y);

    cudaFuncSetAttribute(knn_mma_kernel,
                         cudaFuncAttributeMaxDynamicSharedMemorySize, KNN_SMEM_BYTES);
    cudaFuncSetAttribute(mma_gemm_bf16_kernel,
                         cudaFuncAttributeMaxDynamicSharedMemorySize, GM_SMEM_BYTES);
    cudaFuncSetAttribute(flash_kernel,
                         cudaFuncAttributeMaxDynamicSharedMemorySize,
                         FL_SMEM_FLOATS * (int)sizeof(float));

    // 0) bf16 hi/lo splits (vectorized, 4 floats/thread)
    split_bf16_v4<<<1024, 256>>>((const float4*)x,
                                 (__nv_bfloat162*)xh, (__nv_bfloat162*)xl);
    split_bf16_v4<<<3072, 256>>>((const float4*)aw,
                                 (__nv_bfloat162*)awh, (__nv_bfloat162*)awl);
    split_bf16_v4<<<1024, 256>>>((const float4*)pw,
                                 (__nv_bfloat162*)pwh, (__nv_bfloat162*)pwl);
    split_bf16_v4<<<8192, 256>>>((const float4*)ks,
                                 (__nv_bfloat162*)mh, (__nv_bfloat162*)ml);
    // 1) qkv = x @ c_attn_w^T + b   (3xBF16 mma)
    mma_gemm_bf16_kernel<<<dim3(24, 16), 256, GM_SMEM_BYTES>>>(
        xh, xl, awh, awl, qkv, 3072, 1024, ab);
    // 2) key_store norms + k split/relayout (bf16)
    ksnorm_kernel<<<512, 256>>>(ks, ksn);
    split_qk_bf16_kernel<<<1024, 1024>>>(qkv, kh, kl);
    // 3) fused kNN scores + top-4 on bf16 tensor cores (3xBF16)
    knn_mma_kernel<<<dim3(16, 16), 256, KNN_SMEM_BYTES>>>(
        kh, kl, mh, ml, ksn, idx);
    // 4) sel from last-row softmax
    selA_kernel<<<dim3(128, 16), 256>>>(qkv, lg);
    selB_kernel<<<16, 1024>>>(lg, sel);
    // 5) 5-way softmax blend -> v_new
    vnew_kernel<<<2048, 256>>>(qkv, ks, vs, idx, sel, vnw);
    // 6) fused flash attention -> y (T,C)
    flash_kernel<<<dim3(8, 16), 256, FL_SMEM_FLOATS * sizeof(float)>>>(qkv, vnw, y);
    // 7) out = y @ c_proj_w^T + b   (3xBF16 mma)
    split_bf16_v4<<<1024, 256>>>((const float4*)y,
                                 (__nv_bfloat162*)yh, (__nv_bfloat162*)yl);
    mma_gemm_bf16_kernel<<<dim3(8, 16), 256, GM_SMEM_BYTES>>>(
        yh, yl, pwh, pwl, out, 1024, 1024, pb);
}

// round 10
// speedup vs baseline: 2.3843x; 1.0939x over previous
#include <cuda_runtime.h>
#include <cuda_bf16.h>
#include <cfloat>
#include <cstdint>

// ---------------- scratch (__device__ globals; no allocations) ----------------
__device__ float g_qkv[1024 * 3072];              // 12 MB  (T, 3C)
__device__ float g_ksnorm[16 * 8192];             // (H, M)
__device__ __nv_bfloat16 g_kh[16 * 1024 * 64];    // bf16-hi of k, [h][t][d]
__device__ __nv_bfloat16 g_kl[16 * 1024 * 64];    // bf16-lo of k
__device__ __nv_bfloat16 g_qh[16 * 1024 * 64];    // bf16-hi of q*0.125, [h][t][d]
__device__ __nv_bfloat16 g_ql[16 * 1024 * 64];    // bf16-lo
__device__ __nv_bfloat16 g_mh[16 * 8192 * 64];    // bf16-hi of key_store
__device__ __nv_bfloat16 g_ml[16 * 8192 * 64];    // bf16-lo of key_store
__device__ __nv_bfloat16 g_xh[1024 * 1024];       // bf16-hi of x
__device__ __nv_bfloat16 g_xl[1024 * 1024];
__device__ __nv_bfloat16 g_awh[3072 * 1024];      // bf16-hi of c_attn_w
__device__ __nv_bfloat16 g_awl[3072 * 1024];
__device__ __nv_bfloat16 g_pwh[1024 * 1024];      // bf16-hi of c_proj_w
__device__ __nv_bfloat16 g_pwl[1024 * 1024];
__device__ __nv_bfloat16 g_yh[1024 * 1024];       // bf16-hi of y
__device__ __nv_bfloat16 g_yl[1024 * 1024];
__device__ float g_lg[16 * 1024];                 // last-row logits
__device__ int   g_idx[16 * 1024 * 4];            // (H, T, 4)
__device__ int   g_sel[16 * 1024];                // (H, T)
__device__ float g_vnew[16 * 1024 * 64];          // (H, T, d)
__device__ float g_y[1024 * 1024];                // (T, C)

// ---------------- helpers ----------------
__device__ __forceinline__ void mma_bf16(float& c0, float& c1, float& c2, float& c3,
                                         uint32_t a0, uint32_t a1, uint32_t a2, uint32_t a3,
                                         uint32_t b0, uint32_t b1) {
    asm volatile(
        "mma.sync.aligned.m16n8k16.row.col.f32.bf16.bf16.f32 "
        "{%0,%1,%2,%3}, {%4,%5,%6,%7}, {%8,%9}, {%0,%1,%2,%3};"
        : "+f"(c0), "+f"(c1), "+f"(c2), "+f"(c3)
        : "r"(a0), "r"(a1), "r"(a2), "r"(a3), "r"(b0), "r"(b1));
}

__device__ __forceinline__ uint32_t pack_bf16(__nv_bfloat16 lo, __nv_bfloat16 hi) {
    __nv_bfloat162 t;
    t.x = lo; t.y = hi;
    return *(uint32_t*)&t;
}

// ---------- vectorized contiguous bf16 hi/lo split (4 floats / thread) ----------
__global__ void split_bf16_v4(const float4* __restrict__ src,
                              __nv_bfloat162* __restrict__ hi,
                              __nv_bfloat162* __restrict__ lo) {
    size_t i = (size_t)blockIdx.x * 256 + threadIdx.x;
    float4 v = src[i];
    __nv_bfloat16 h0 = __float2bfloat16(v.x), h1 = __float2bfloat16(v.y);
    __nv_bfloat16 h2 = __float2bfloat16(v.z), h3 = __float2bfloat16(v.w);
    __nv_bfloat16 l0 = __float2bfloat16(v.x - __bfloat162float(h0));
    __nv_bfloat16 l1 = __float2bfloat16(v.y - __bfloat162float(h1));
    __nv_bfloat16 l2 = __float2bfloat16(v.z - __bfloat162float(h2));
    __nv_bfloat16 l3 = __float2bfloat16(v.w - __bfloat162float(h3));
    hi[i * 2 + 0] = __nv_bfloat162{h0, h1};
    hi[i * 2 + 1] = __nv_bfloat162{h2, h3};
    lo[i * 2 + 0] = __nv_bfloat162{l0, l1};
    lo[i * 2 + 1] = __nv_bfloat162{l2, l3};
}

// -- bf16 hi/lo split of k AND q (scaled 0.125) from qkv, relayout to [h][t][d] --
__global__ void split_qk_bf16_kernel(const float* __restrict__ qkv,
                                     __nv_bfloat16* __restrict__ khi,
                                     __nv_bfloat16* __restrict__ klo,
                                     __nv_bfloat16* __restrict__ qhi,
                                     __nv_bfloat16* __restrict__ qlo) {
    int i = blockIdx.x * 1024 + threadIdx.x;  // 2M
    int which = i >> 20;                      // 0: k, 1: q
    int r = i & 0xFFFFF;
    int d = r & 63, t = (r >> 6) & 1023, h = r >> 16;
    float x = qkv[(size_t)t * 3072 + (which ? 0 : 1024) + h * 64 + d];
    if (which) x *= 0.125f;
    __nv_bfloat16 hf = __float2bfloat16(x);
    __nv_bfloat16 lf = __float2bfloat16(x - __bfloat162float(hf));
    if (which) { qhi[r] = hf; qlo[r] = lf; }
    else       { khi[r] = hf; klo[r] = lf; }
}

// ---- generic 3xBF16 mma GEMM: C = A * B^T + bias  (round-9 validated) ----
#define KAH 72
#define GM_SMEM_BYTES ((64 * KAH * 2 + 128 * KAH * 2) * 2)

__global__ __launch_bounds__(256) void mma_gemm_bf16_kernel(
    const __nv_bfloat16* __restrict__ Ahg, const __nv_bfloat16* __restrict__ Alg,
    const __nv_bfloat16* __restrict__ Bhg, const __nv_bfloat16* __restrict__ Blg,
    float* __restrict__ C, int ldc, int K, const float* __restrict__ bias) {
    extern __shared__ char smc[];
    __nv_bfloat16* Ah = (__nv_bfloat16*)smc;          // [64][72]
    __nv_bfloat16* Al = Ah + 64 * KAH;
    __nv_bfloat16* Bh = Al + 64 * KAH;                // [128][72]
    __nv_bfloat16* Bl = Bh + 128 * KAH;

    const int tid = threadIdx.x;
    const int bx = blockIdx.x, by = blockIdx.y;
    const int w = tid >> 5, lane = tid & 31;
    const int gid = lane >> 2, qid = lane & 3;
    const int rt = (w & 3) * 16;
    const int ch = (w >> 2) * 64;

    const __nv_bfloat16* Ahb = Ahg + (size_t)(by * 64) * K;
    const __nv_bfloat16* Alb = Alg + (size_t)(by * 64) * K;
    const __nv_bfloat16* Bhb = Bhg + (size_t)(bx * 128) * K;
    const __nv_bfloat16* Blb = Blg + (size_t)(bx * 128) * K;

    float c[8][4];
#pragma unroll
    for (int nb = 0; nb < 8; nb++)
#pragma unroll
        for (int k = 0; k < 4; k++) c[nb][k] = 0.f;

    for (int k0 = 0; k0 < K; k0 += 64) {
        __syncthreads();
        for (int i = tid; i < 512; i += 256) {
            int r = i >> 3, c8 = (i & 7) * 8;
            *(uint4*)&Ah[r * KAH + c8] = *(const uint4*)(Ahb + (size_t)r * K + k0 + c8);
            *(uint4*)&Al[r * KAH + c8] = *(const uint4*)(Alb + (size_t)r * K + k0 + c8);
        }
        for (int i = tid; i < 1024; i += 256) {
            int r = i >> 3, c8 = (i & 7) * 8;
            *(uint4*)&Bh[r * KAH + c8] = *(const uint4*)(Bhb + (size_t)r * K + k0 + c8);
            *(uint4*)&Bl[r * KAH + c8] = *(const uint4*)(Blb + (size_t)r * K + k0 + c8);
        }
        __syncthreads();

#pragma unroll
        for (int ks16 = 0; ks16 < 4; ks16++) {
            const int kk = ks16 * 16;
            const int ab = (rt + gid) * KAH + kk + 2 * qid;
            uint32_t ah0 = *(const uint32_t*)&Ah[ab];
            uint32_t ah1 = *(const uint32_t*)&Ah[ab + 8 * KAH];
            uint32_t ah2 = *(const uint32_t*)&Ah[ab + 8];
            uint32_t ah3 = *(const uint32_t*)&Ah[ab + 8 * KAH + 8];
            uint32_t al0 = *(const uint32_t*)&Al[ab];
            uint32_t al1 = *(const uint32_t*)&Al[ab + 8 * KAH];
            uint32_t al2 = *(const uint32_t*)&Al[ab + 8];
            uint32_t al3 = *(const uint32_t*)&Al[ab + 8 * KAH + 8];
#pragma unroll
            for (int nb = 0; nb < 8; nb++) {
                const int bb = (ch + nb * 8 + gid) * KAH + kk + 2 * qid;
                uint32_t bh0 = *(const uint32_t*)&Bh[bb];
                uint32_t bh1 = *(const uint32_t*)&Bh[bb + 8];
                uint32_t bl0 = *(const uint32_t*)&Bl[bb];
                uint32_t bl1 = *(const uint32_t*)&Bl[bb + 8];
                mma_bf16(c[nb][0], c[nb][1], c[nb][2], c[nb][3],
                         ah0, ah1, ah2, ah3, bh0, bh1);
                mma_bf16(c[nb][0], c[nb][1], c[nb][2], c[nb][3],
                         ah0, ah1, ah2, ah3, bl0, bl1);
                mma_bf16(c[nb][0], c[nb][1], c[nb][2], c[nb][3],
                         al0, al1, al2, al3, bh0, bh1);
            }
        }
    }

#pragma unroll
    for (int nb = 0; nb < 8; nb++) {
#pragma unroll
        for (int k = 0; k < 4; k++) {
            int row = by * 64 + rt + gid + (k >> 1) * 8;
            int col = bx * 128 + ch + nb * 8 + 2 * qid + (k & 1);
            C[(size_t)row * ldc + col] = c[nb][k] + bias[col];
        }
    }
}

// ---------------- ||key_store[h,m]||^2 (exact fp32) ----------------
__global__ void ksnorm_kernel(const float* __restrict__ ks, float* __restrict__ nrm) {
    int r = blockIdx.x * blockDim.x + threadIdx.x;
    if (r >= 16 * 8192) return;
    const float4* p = (const float4*)(ks + (size_t)r * 64);
    float s = 0.f;
#pragma unroll
    for (int i = 0; i < 16; i++) {
        float4 f = p[i];
        s += f.x * f.x + f.y * f.y + f.z * f.z + f.w * f.w;
    }
    nrm[r] = s;
}

// ------------- lexicographic (score, idx) compare: stable top-k --------------
__device__ __forceinline__ bool lex_lt(float sa, int ia, float sb, int ib) {
    return sa < sb || (sa == sb && ia < ib);
}

#define TOP4_INSERT(v, m, s0, x0, s1, x1, s2, x2, s3, x3)              \
    if (lex_lt(v, m, s3, x3)) {                                        \
        if (lex_lt(v, m, s2, x2)) {                                    \
            s3 = s2; x3 = x2;                                          \
            if (lex_lt(v, m, s1, x1)) {                                \
                s2 = s1; x2 = x1;                                      \
                if (lex_lt(v, m, s0, x0)) {                            \
                    s1 = s0; x1 = x0; s0 = v; x0 = m;                  \
                } else { s1 = v; x1 = m; }                             \
            } else { s2 = v; x2 = m; }                                 \
        } else { s3 = v; x3 = m; }                                     \
    }

// ---- fused kNN scores + top-4 via bf16 tensor cores (round-8 validated) ----
#define KNN_SMEM_BYTES ((64 * KAH * 2 + 128 * KAH * 2) * 2 + 128 * 4)

__global__ __launch_bounds__(256) void knn_mma_kernel(
    const __nv_bfloat16* __restrict__ kh, const __nv_bfloat16* __restrict__ kl,
    const __nv_bfloat16* __restrict__ mh, const __nv_bfloat16* __restrict__ ml,
    const float* __restrict__ ksn, int* __restrict__ idx_out) {
    extern __shared__ char smc[];
    __nv_bfloat16* Ah = (__nv_bfloat16*)smc;          // [64][72]
    __nv_bfloat16* Al = Ah + 64 * KAH;
    __nv_bfloat16* Bh = Al + 64 * KAH;                // [128][72]
    __nv_bfloat16* Bl = Bh + 128 * KAH;
    float* Ns = (float*)(Bl + 128 * KAH);             // [128]

    const int tid = threadIdx.x;
    const int t0 = blockIdx.x * 64;
    const int h = blockIdx.y;
    const int w = tid >> 5, lane = tid & 31;
    const int gid = lane >> 2, qid = lane & 3;
    const int rt = (w & 3) * 16;
    const int ch = (w >> 2) * 64;

    const __nv_bfloat16* Ahg = kh + ((size_t)h * 1024 + t0) * 64;
    const __nv_bfloat16* Alg = kl + ((size_t)h * 1024 + t0) * 64;
    for (int i = tid; i < 512; i += 256) {
        int r = i >> 3, c8 = (i & 7) * 8;
        *(uint4*)&Ah[r * KAH + c8] = *(const uint4*)(Ahg + (size_t)r * 64 + c8);
        *(uint4*)&Al[r * KAH + c8] = *(const uint4*)(Alg + (size_t)r * 64 + c8);
    }

    float S[2][4];
    int I[2][4];
#pragma unroll
    for (int r = 0; r < 2; r++)
#pragma unroll
        for (int k = 0; k < 4; k++) { S[r][k] = FLT_MAX; I[r][k] = 0x7fffffff; }

    const __nv_bfloat16* Bhg = mh + (size_t)h * 8192 * 64;
    const __nv_bfloat16* Blg = ml + (size_t)h * 8192 * 64;
    const float* Nbase = ksn + h * 8192;

    for (int chunk = 0; chunk < 64; chunk++) {
        const int m0 = chunk << 7;
        __syncthreads();
        if (tid < 128) Ns[tid] = Nbase[m0 + tid];
        for (int i = tid; i < 1024; i += 256) {
            int r = i >> 3, c8 = (i & 7) * 8;
            *(uint4*)&Bh[r * KAH + c8] = *(const uint4*)(Bhg + (size_t)(m0 + r) * 64 + c8);
            *(uint4*)&Bl[r * KAH + c8] = *(const uint4*)(Blg + (size_t)(m0 + r) * 64 + c8);
        }
        __syncthreads();

        float c[8][4];
#pragma unroll
        for (int nb = 0; nb < 8; nb++)
#pragma unroll
            for (int k = 0; k < 4; k++) c[nb][k] = 0.f;

#pragma unroll
        for (int ks16 = 0; ks16 < 4; ks16++) {
            const int k0 = ks16 * 16;
            const int ab = (rt + gid) * KAH + k0 + 2 * qid;
            uint32_t ah0 = *(const uint32_t*)&Ah[ab];
            uint32_t ah1 = *(const uint32_t*)&Ah[ab + 8 * KAH];
            uint32_t ah2 = *(const uint32_t*)&Ah[ab + 8];
            uint32_t ah3 = *(const uint32_t*)&Ah[ab + 8 * KAH + 8];
            uint32_t al0 = *(const uint32_t*)&Al[ab];
            uint32_t al1 = *(const uint32_t*)&Al[ab + 8 * KAH];
            uint32_t al2 = *(const uint32_t*)&Al[ab + 8];
            uint32_t al3 = *(const uint32_t*)&Al[ab + 8 * KAH + 8];
#pragma unroll
            for (int nb = 0; nb < 8; nb++) {
                const int bb = (ch + nb * 8 + gid) * KAH + k0 + 2 * qid;
                uint32_t bh0 = *(const uint32_t*)&Bh[bb];
                uint32_t bh1 = *(const uint32_t*)&Bh[bb + 8];
                uint32_t bl0 = *(const uint32_t*)&Bl[bb];
                uint32_t bl1 = *(const uint32_t*)&Bl[bb + 8];
                mma_bf16(c[nb][0], c[nb][1], c[nb][2], c[nb][3],
                         ah0, ah1, ah2, ah3, bh0, bh1);
                mma_bf16(c[nb][0], c[nb][1], c[nb][2], c[nb][3],
                         ah0, ah1, ah2, ah3, bl0, bl1);
                mma_bf16(c[nb][0], c[nb][1], c[nb][2], c[nb][3],
                         al0, al1, al2, al3, bh0, bh1);
            }
        }

#pragma unroll
        for (int nb = 0; nb < 8; nb++) {
#pragma unroll
            for (int k = 0; k < 4; k++) {
                int cl = ch + nb * 8 + 2 * qid + (k & 1);
                int r = k >> 1;
                float v = Ns[cl] - 2.0f * c[nb][k];
                int mg = m0 + cl;
                TOP4_INSERT(v, mg, S[r][0], I[r][0], S[r][1], I[r][1],
                            S[r][2], I[r][2], S[r][3], I[r][3]);
            }
        }
    }

    __syncthreads();
    float* msc = (float*)smc;                 // [64][32]
    int* mix = (int*)(smc + 16384);
    const int slot = (w >> 2) * 4 + qid;
#pragma unroll
    for (int r = 0; r < 2; r++) {
        int row = rt + gid + r * 8;
#pragma unroll
        for (int k = 0; k < 4; k++) {
            msc[(row * 8 + slot) * 4 + k] = S[r][k];
            mix[(row * 8 + slot) * 4 + k] = I[r][k];
        }
    }
    __syncthreads();
    if (tid < 64) {
        float f0 = FLT_MAX, f1 = FLT_MAX, f2 = FLT_MAX, f3 = FLT_MAX;
        int g0 = 0x7fffffff, g1 = 0x7fffffff, g2 = 0x7fffffff, g3 = 0x7fffffff;
        for (int c2 = 0; c2 < 32; c2++) {
            float v = msc[tid * 32 + c2];
            int m = mix[tid * 32 + c2];
            TOP4_INSERT(v, m, f0, g0, f1, g1, f2, g2, f3, g3);
        }
        size_t row = (size_t)h * 1024 + t0 + tid;
        idx_out[row * 4 + 0] = g0;
        idx_out[row * 4 + 1] = g1;
        idx_out[row * 4 + 2] = g2;
        idx_out[row * 4 + 3] = g3;
    }
}

// ---------------- warp-per-token last-row logits ----------------
__global__ void selA_kernel(const float* __restrict__ qkv, float* __restrict__ lg) {
    int h = blockIdx.y;
    int t = blockIdx.x * 8 + (threadIdx.x >> 5);
    int lane = threadIdx.x & 31;
    int d0 = lane * 2;
    const float* q = qkv + (size_t)1023 * 3072 + h * 64;
    const float* k = qkv + (size_t)t * 3072 + 1024 + h * 64;
    float s = q[d0] * k[d0] + q[d0 + 1] * k[d0 + 1];
#pragma unroll
    for (int o = 16; o > 0; o >>= 1) s += __shfl_xor_sync(0xffffffffu, s, o);
    if (lane == 0) lg[h * 1024 + t] = s * 0.125f;
}

// ---------------- per-head softmax of logits row -> sel ----------------
__global__ void selB_kernel(const float* __restrict__ lg, int* __restrict__ sel) {
    int h = blockIdx.x;
    int tid = threadIdx.x;
    int lane = tid & 31, warp = tid >> 5;
    __shared__ float red[8];
    __shared__ float bcast;

    float v[4];
#pragma unroll
    for (int u = 0; u < 4; u++) v[u] = lg[h * 1024 + tid + u * 256];
    float m = fmaxf(fmaxf(v[0], v[1]), fmaxf(v[2], v[3]));
#pragma unroll
    for (int o = 16; o > 0; o >>= 1) m = fmaxf(m, __shfl_xor_sync(0xffffffffu, m, o));
    if (lane == 0) red[warp] = m;
    __syncthreads();
    if (tid == 0) {
        float x = red[0];
#pragma unroll
        for (int w = 1; w < 8; w++) x = fmaxf(x, red[w]);
        bcast = x;
    }
    __syncthreads();
    m = bcast;
    float e[4], s = 0.f;
#pragma unroll
    for (int u = 0; u < 4; u++) { e[u] = __expf(v[u] - m); s += e[u]; }
#pragma unroll
    for (int o = 16; o > 0; o >>= 1) s += __shfl_xor_sync(0xffffffffu, s, o);
    if (lane == 0) red[warp] = s;
    __syncthreads();
    if (tid == 0) {
        float x = 0.f;
#pragma unroll
        for (int w = 0; w < 8; w++) x += red[w];
        bcast = x;
    }
    __syncthreads();
    float inv = 1.f / bcast;
#pragma unroll
    for (int u = 0; u < 4; u++)
        sel[h * 1024 + tid + u * 256] = (e[u] * inv >= (1.0f / 8192.0f)) ? 1 : 0;
}

// ---------------- per-token 5-way memory softmax & blend -> v_new ----------------
__device__ __forceinline__ float warp_sum(float v) {
#pragma unroll
    for (int o = 16; o > 0; o >>= 1) v += __shfl_xor_sync(0xffffffffu, v, o);
    return v;
}

__global__ void vnew_kernel(const float* __restrict__ qkv, const float* __restrict__ kstore,
                            const float* __restrict__ vstore, const int* __restrict__ idx,
                            const int* __restrict__ sel, float* __restrict__ vnew) {
    int gw = (blockIdx.x * blockDim.x + threadIdx.x) >> 5;
    int lane = threadIdx.x & 31;
    if (gw >= 16 * 1024) return;
    int h = gw >> 10, t = gw & 1023;

    const float* base = qkv + (size_t)t * 3072 + h * 64;
    int d0 = lane * 2;
    float q0 = base[d0],        q1 = base[d0 + 1];
    float k0 = base[1024 + d0], k1 = base[1024 + d0 + 1];
    float v0 = base[2048 + d0], v1 = base[2048 + d0 + 1];
    const float scale = 0.125f;

    float attf[5];
    attf[0] = warp_sum(q0 * k0 + q1 * k1) * scale;

    int ids[4];
#pragma unroll
    for (int s2 = 0; s2 < 4; s2++) ids[s2] = idx[(size_t)gw * 4 + s2];

    float fv0[4], fv1[4];
#pragma unroll
    for (int s2 = 0; s2 < 4; s2++) {
        const float* kp = kstore + ((size_t)h * 8192 + ids[s2]) * 64;
        attf[s2 + 1] = warp_sum(q0 * kp[d0] + q1 * kp[d0 + 1]) * scale;
        const float* vp = vstore + ((size_t)h * 8192 + ids[s2]) * 64;
        fv0[s2] = vp[d0]; fv1[s2] = vp[d0 + 1];
    }

    float mx = attf[0];
#pragma unroll
    for (int s2 = 1; s2 < 5; s2++) mx = fmaxf(mx, attf[s2]);
    float e[5], sum = 0.f;
#pragma unroll
    for (int s2 = 0; s2 < 5; s2++) { e[s2] = expf(attf[s2] - mx); sum += e[s2]; }
    float inv = 1.f / sum;

    float o0 = e[0] * v0, o1 = e[0] * v1;
#pragma unroll
    for (int s2 = 0; s2 < 4; s2++) { o0 += e[s2 + 1] * fv0[s2]; o1 += e[s2 + 1] * fv1[s2]; }
    o0 = o0 * inv * 0.5f + v0 * 0.5f;
    o1 = o1 * inv * 0.5f + v1 * 0.5f;

    bool sl = sel[gw] != 0;
    vnew[(size_t)gw * 64 + d0]     = sl ? o0 : v0;
    vnew[(size_t)gw * 64 + d0 + 1] = sl ? o1 : v1;
}

// ------- fused flash attention on bf16 mma: y = softmax_causal(qk^T/8) @ v_new -------
// Block: 256 thr (8 warps), 128 q-rows x one head. Warp w: rows w*16..w*16+15, all 64 cols.
// smem: Qh/Ql [128][72], Kh/Kl [64][72] (s-major), Vh/Vl [64][72] (d-major = V^T)
#define FLM_SMEM_BYTES ((128 * KAH * 2 + 64 * KAH * 2 + 64 * KAH * 2) * 2)

__global__ __launch_bounds__(256) void flash_mma_kernel(
    const __nv_bfloat16* __restrict__ qhg, const __nv_bfloat16* __restrict__ qlg,
    const __nv_bfloat16* __restrict__ khg, const __nv_bfloat16* __restrict__ klg,
    const float* __restrict__ vnw, float* __restrict__ y) {
    extern __shared__ char smc[];
    __nv_bfloat16* Qh = (__nv_bfloat16*)smc;          // [128][72]
    __nv_bfloat16* Ql = Qh + 128 * KAH;
    __nv_bfloat16* Kh = Ql + 128 * KAH;               // [64][72]
    __nv_bfloat16* Kl = Kh + 64 * KAH;
    __nv_bfloat16* Vh = Kl + 64 * KAH;                // [64][72]  (row = d, col = s)
    __nv_bfloat16* Vl = Vh + 64 * KAH;

    const int tid = threadIdx.x;
    const int qb = blockIdx.x, h = blockIdx.y;
    const int w = tid >> 5, lane = tid & 31;
    const int gid = lane >> 2, qid = lane & 3;
    const int rt = w * 16;
    const int t0 = qb * 128;

    // Q tiles (pre-scaled by 0.125 at split time)
    const __nv_bfloat16* Qhg = qhg + ((size_t)h * 1024 + t0) * 64;
    const __nv_bfloat16* Qlg = qlg + ((size_t)h * 1024 + t0) * 64;
    for (int i = tid; i < 1024; i += 256) {
        int r = i >> 3, c8 = (i & 7) * 8;
        *(uint4*)&Qh[r * KAH + c8] = *(const uint4*)(Qhg + (size_t)r * 64 + c8);
        *(uint4*)&Ql[r * KAH + c8] = *(const uint4*)(Qlg + (size_t)r * 64 + c8);
    }

    float m0 = -FLT_MAX, m1 = -FLT_MAX, l0 = 0.f, l1 = 0.f;
    float O[8][4];
#pragma unroll
    for (int nb = 0; nb < 8; nb++)
#pragma unroll
        for (int k = 0; k < 4; k++) O[nb][k] = 0.f;

    const int row0 = t0 + rt + gid, row1 = row0 + 8;
    const int nj = 2 * qb + 2;

    for (int j = 0; j < nj; j++) {
        const int s0 = j * 64;
        __syncthreads();  // prior PV reads done (and Q loads on first iter)
        const __nv_bfloat16* Khg = khg + ((size_t)h * 1024 + s0) * 64;
        const __nv_bfloat16* Klg = klg + ((size_t)h * 1024 + s0) * 64;
        for (int i = tid; i < 512; i += 256) {
            int r = i >> 3, c8 = (i & 7) * 8;
            *(uint4*)&Kh[r * KAH + c8] = *(const uint4*)(Khg + (size_t)r * 64 + c8);
            *(uint4*)&Kl[r * KAH + c8] = *(const uint4*)(Klg + (size_t)r * 64 + c8);
        }
        // V tile: load fp32 [s][d], split + transpose to [d][s]
        const float* Vg = vnw + ((size_t)h * 1024 + s0) * 64;
        for (int i = tid; i < 1024; i += 256) {
            int s = i >> 4, c4 = (i & 15) * 4;
            float4 v = *(const float4*)(Vg + (size_t)s * 64 + c4);
            float vv[4] = {v.x, v.y, v.z, v.w};
#pragma unroll
            for (int jj = 0; jj < 4; jj++) {
                __nv_bfloat16 hh = __float2bfloat16(vv[jj]);
                Vh[(c4 + jj) * KAH + s] = hh;
                Vl[(c4 + jj) * KAH + s] = __float2bfloat16(vv[jj] - __bfloat162float(hh));
            }
        }
        __syncthreads();

        // S = Q K^T (3xBF16): warp rows rt..rt+15, cols 0..63
        float c[8][4];
#pragma unroll
        for (int nb = 0; nb < 8; nb++)
#pragma unroll
            for (int k = 0; k < 4; k++) c[nb][k] = 0.f;

#pragma unroll
        for (int ks16 = 0; ks16 < 4; ks16++) {
            const int kk = ks16 * 16;
            const int ab = (rt + gid) * KAH + kk + 2 * qid;
            uint32_t ah0 = *(const uint32_t*)&Qh[ab];
            uint32_t ah1 = *(const uint32_t*)&Qh[ab + 8 * KAH];
            uint32_t ah2 = *(const uint32_t*)&Qh[ab + 8];
            uint32_t ah3 = *(const uint32_t*)&Qh[ab + 8 * KAH + 8];
            uint32_t al0 = *(const uint32_t*)&Ql[ab];
            uint32_t al1 = *(const uint32_t*)&Ql[ab + 8 * KAH];
            uint32_t al2 = *(const uint32_t*)&Ql[ab + 8];
            uint32_t al3 = *(const uint32_t*)&Ql[ab + 8 * KAH + 8];
#pragma unroll
            for (int nb = 0; nb < 8; nb++) {
                const int bb = (nb * 8 + gid) * KAH + kk + 2 * qid;
                uint32_t bh0 = *(const uint32_t*)&Kh[bb];
                uint32_t bh1 = *(const uint32_t*)&Kh[bb + 8];
                uint32_t bl0 = *(const uint32_t*)&Kl[bb];
                uint32_t bl1 = *(const uint32_t*)&Kl[bb + 8];
                mma_bf16(c[nb][0], c[nb][1], c[nb][2], c[nb][3],
                         ah0, ah1, ah2, ah3, bh0, bh1);
                mma_bf16(c[nb][0], c[nb][1], c[nb][2], c[nb][3],
                         ah0, ah1, ah2, ah3, bl0, bl1);
                mma_bf16(c[nb][0], c[nb][1], c[nb][2], c[nb][3],
                         al0, al1, al2, al3, bh0, bh1);
            }
        }

        // causal mask (only last blocks can cross the diagonal for this warp)
        if (s0 + 63 > t0 + rt) {
#pragma unroll
            for (int nb = 0; nb < 8; nb++) {
                int cb = s0 + nb * 8 + 2 * qid;
                if (cb > row0)     c[nb][0] = -FLT_MAX;
                if (cb + 1 > row0) c[nb][1] = -FLT_MAX;
                if (cb > row1)     c[nb][2] = -FLT_MAX;
                if (cb + 1 > row1) c[nb][3] = -FLT_MAX;
            }
        }

        // online softmax: row stats across this thread's 16 cols + 4 qid lanes
        float rm0 = -FLT_MAX, rm1 = -FLT_MAX;
#pragma unroll
        for (int nb = 0; nb < 8; nb++) {
            rm0 = fmaxf(rm0, fmaxf(c[nb][0], c[nb][1]));
            rm1 = fmaxf(rm1, fmaxf(c[nb][2], c[nb][3]));
        }
        rm0 = fmaxf(rm0, __shfl_xor_sync(0xffffffffu, rm0, 1));
        rm0 = fmaxf(rm0, __shfl_xor_sync(0xffffffffu, rm0, 2));
        rm1 = fmaxf(rm1, __shfl_xor_sync(0xffffffffu, rm1, 1));
        rm1 = fmaxf(rm1, __shfl_xor_sync(0xffffffffu, rm1, 2));

        float mn0 = fmaxf(m0, rm0), mn1 = fmaxf(m1, rm1);
        float alpha0 = __expf(m0 - mn0), alpha1 = __expf(m1 - mn1);
        float ps0 = 0.f, ps1 = 0.f;
#pragma unroll
        for (int nb = 0; nb < 8; nb++) {
            c[nb][0] = __expf(c[nb][0] - mn0); ps0 += c[nb][0];
            c[nb][1] = __expf(c[nb][1] - mn0); ps0 += c[nb][1];
            c[nb][2] = __expf(c[nb][2] - mn1); ps1 += c[nb][2];
            c[nb][3] = __expf(c[nb][3] - mn1); ps1 += c[nb][3];
        }
        ps0 += __shfl_xor_sync(0xffffffffu, ps0, 1);
        ps0 += __shfl_xor_sync(0xffffffffu, ps0, 2);
        ps1 += __shfl_xor_sync(0xffffffffu, ps1, 1);
        ps1 += __shfl_xor_sync(0xffffffffu, ps1, 2);
        l0 = l0 * alpha0 + ps0; m0 = mn0;
        l1 = l1 * alpha1 + ps1; m1 = mn1;
#pragma unroll
        for (int nb = 0; nb < 8; nb++) {
            O[nb][0] *= alpha0; O[nb][1] *= alpha0;
            O[nb][2] *= alpha1; O[nb][3] *= alpha1;
        }

        // P@V: P (C-frag) is bitwise the A-frag layout — register-only conversion
#pragma unroll
        for (int kb = 0; kb < 4; kb++) {
            float p00 = c[2 * kb][0],     p01 = c[2 * kb][1];
            float p02 = c[2 * kb][2],     p03 = c[2 * kb][3];
            float p10 = c[2 * kb + 1][0], p11 = c[2 * kb + 1][1];
            float p12 = c[2 * kb + 1][2], p13 = c[2 * kb + 1][3];
            __nv_bfloat16 h00 = __float2bfloat16(p00), h01 = __float2bfloat16(p01);
            __nv_bfloat16 h02 = __float2bfloat16(p02), h03 = __float2bfloat16(p03);
            __nv_bfloat16 h10 = __float2bfloat16(p10), h11 = __float2bfloat16(p11);
            __nv_bfloat16 h12 = __float2bfloat16(p12), h13 = __float2bfloat16(p13);
            uint32_t Ah0 = pack_bf16(h00, h01);
            uint32_t Ah1 = pack_bf16(h02, h03);
            uint32_t Ah2 = pack_bf16(h10, h11);
            uint32_t Ah3 = pack_bf16(h12, h13);
            uint32_t Al0 = pack_bf16(__float2bfloat16(p00 - __bfloat162float(h00)),
                                     __float2bfloat16(p01 - __bfloat162float(h01)));
            uint32_t Al1 = pack_bf16(__float2bfloat16(p02 - __bfloat162float(h02)),
                                     __float2bfloat16(p03 - __bfloat162float(h03)));
            uint32_t Al2 = pack_bf16(__float2bfloat16(p10 - __bfloat162float(h10)),
                                     __float2bfloat16(p11 - __bfloat162float(h11)));
            uint32_t Al3 = pack_bf16(__float2bfloat16(p12 - __bfloat162float(h12)),
                                     __float2bfloat16(p13 - __bfloat162float(h13)));
#pragma unroll
            for (int nb = 0; nb < 8; nb++) {
                const int bb = (nb * 8 + gid) * KAH + kb * 16 + 2 * qid;
                uint32_t bh0 = *(const uint32_t*)&Vh[bb];
                uint32_t bh1 = *(const uint32_t*)&Vh[bb + 8];
                uint32_t bl0 = *(const uint32_t*)&Vl[bb];
                uint32_t bl1 = *(const uint32_t*)&Vl[bb + 8];
                mma_bf16(O[nb][0], O[nb][1], O[nb][2], O[nb][3],
                         Ah0, Ah1, Ah2, Ah3, bh0, bh1);
                mma_bf16(O[nb][0], O[nb][1], O[nb][2], O[nb][3],
                         Ah0, Ah1, Ah2, Ah3, bl0, bl1);
                mma_bf16(O[nb][0], O[nb][1], O[nb][2], O[nb][3],
                         Al0, Al1, Al2, Al3, bh0, bh1);
            }
        }
    }

    // epilogue: y[t][h*64 + d] = O / l
    float inv0 = 1.f / l0, inv1 = 1.f / l1;
#pragma unroll
    for (int nb = 0; nb < 8; nb++) {
        int colb = h * 64 + nb * 8 + 2 * qid;
        y[(size_t)row0 * 1024 + colb]     = O[nb][0] * inv0;
        y[(size_t)row0 * 1024 + colb + 1] = O[nb][1] * inv0;
        y[(size_t)row1 * 1024 + colb]     = O[nb][2] * inv1;
        y[(size_t)row1 * 1024 + colb + 1] = O[nb][3] * inv1;
    }
}

// ---------------- launch ----------------
extern "C" void kernel_launch(void* const* d_in, const int* in_sizes, int n_in,
                              void* d_out, int out_size) {
    const float* x  = (const float*)d_in[0];
    const float* aw = (const float*)d_in[1];
    const float* ab = (const float*)d_in[2];
    const float* pw = (const float*)d_in[3];
    const float* pb = (const float*)d_in[4];
    const float* ks = (const float*)d_in[5];
    const float* vs = (const float*)d_in[6];
    float* out = (float*)d_out;

    float *qkv, *ksn, *lg, *vnw, *y;
    __nv_bfloat16 *kh, *kl, *qh, *ql, *mh, *ml, *xh, *xl, *awh, *awl, *pwh, *pwl, *yh, *yl;
    int *idx, *sel;
    cudaGetSymbolAddress((void**)&qkv, g_qkv);
    cudaGetSymbolAddress((void**)&ksn, g_ksnorm);
    cudaGetSymbolAddress((void**)&kh,  g_kh);
    cudaGetSymbolAddress((void**)&kl,  g_kl);
    cudaGetSymbolAddress((void**)&qh,  g_qh);
    cudaGetSymbolAddress((void**)&ql,  g_ql);
    cudaGetSymbolAddress((void**)&mh,  g_mh);
    cudaGetSymbolAddress((void**)&ml,  g_ml);
    cudaGetSymbolAddress((void**)&xh,  g_xh);
    cudaGetSymbolAddress((void**)&xl,  g_xl);
    cudaGetSymbolAddress((void**)&awh, g_awh);
    cudaGetSymbolAddress((void**)&awl, g_awl);
    cudaGetSymbolAddress((void**)&pwh, g_pwh);
    cudaGetSymbolAddress((void**)&pwl, g_pwl);
    cudaGetSymbolAddress((void**)&yh,  g_yh);
    cudaGetSymbolAddress((void**)&yl,  g_yl);
    cudaGetSymbolAddress((void**)&lg,  g_lg);
    cudaGetSymbolAddress((void**)&idx, g_idx);
    cudaGetSymbolAddress((void**)&sel, g_sel);
    cudaGetSymbolAddress((void**)&vnw, g_vnew);
    cudaGetSymbolAddress((void**)&y,   g_y);

    cudaFuncSetAttribute(knn_mma_kernel,
                         cudaFuncAttributeMaxDynamicSharedMemorySize, KNN_SMEM_BYTES);
    cudaFuncSetAttribute(mma_gemm_bf16_kernel,
                         cudaFuncAttributeMaxDynamicSharedMemorySize, GM_SMEM_BYTES);
    cudaFuncSetAttribute(flash_mma_kernel,
                         cudaFuncAttributeMaxDynamicSharedMemorySize, FLM_SMEM_BYTES);

    // 0) bf16 hi/lo splits (vectorized, 4 floats/thread)
    split_bf16_v4<<<1024, 256>>>((const float4*)x,
                                 (__nv_bfloat162*)xh, (__nv_bfloat162*)xl);
    split_bf16_v4<<<3072, 256>>>((const float4*)aw,
                                 (__nv_bfloat162*)awh, (__nv_bfloat162*)awl);
    split_bf16_v4<<<1024, 256>>>((const float4*)pw,
                                 (__nv_bfloat162*)pwh, (__nv_bfloat162*)pwl);
    split_bf16_v4<<<8192, 256>>>((const float4*)ks,
                                 (__nv_bfloat162*)mh, (__nv_bfloat162*)ml);
    // 1) qkv = x @ c_attn_w^T + b   (3xBF16 mma)
    mma_gemm_bf16_kernel<<<dim3(24, 16), 256, GM_SMEM_BYTES>>>(
        xh, xl, awh, awl, qkv, 3072, 1024, ab);
    // 2) key_store norms + k/q split/relayout (bf16, q pre-scaled)
    ksnorm_kernel<<<512, 256>>>(ks, ksn);
    split_qk_bf16_kernel<<<2048, 1024>>>(qkv, kh, kl, qh, ql);
    // 3) fused kNN scores + top-4 on bf16 tensor cores (3xBF16)
    knn_mma_kernel<<<dim3(16, 16), 256, KNN_SMEM_BYTES>>>(
        kh, kl, mh, ml, ksn, idx);
    // 4) sel from last-row softmax
    selA_kernel<<<dim3(128, 16), 256>>>(qkv, lg);
    selB_kernel<<<16, 1024>>>(lg, sel);
    // 5) 5-way softmax blend -> v_new
    vnew_kernel<<<2048, 256>>>(qkv, ks, vs, idx, sel, vnw);
    // 6) fused flash attention on bf16 mma -> y (T,C)
    flash_mma_kernel<<<dim3(8, 16), 256, FLM_SMEM_BYTES>>>(qh, ql, kh, kl, vnw, y);
    // 7) out = y @ c_proj_w^T + b   (3xBF16 mma)
    split_bf16_v4<<<1024, 256>>>((const float4*)y,
                                 (__nv_bfloat162*)yh, (__nv_bfloat162*)yl);
    mma_gemm_bf16_kernel<<<dim3(8, 16), 256, GM_SMEM_BYTES>>>(
        yh, yl, pwh, pwl, out, 1024, 1024, pb);
}